// round 8
// baseline (speedup 1.0000x reference)
#include <cuda_runtime.h>
#include <cuda_fp16.h>
#include <math.h>
#include <stdint.h>

// ---------------- problem dims ----------------
#define Bsz 16
#define Tn  1024
#define Dn  1024
#define Hn  4096
#define BT  (Bsz*Tn)              // 16384
#define BTD (Bsz*Tn*Dn)           // 16777216
#define BTH (Bsz*Tn*Hn)           // 67108864
#define CONVK 4

// ---------------- GEMM tile config ----------------
#define STAGES 4
#define S_A_BYTES 20480           // 256 rows x 80B
#define S_STAGE   30720
#define S_SMEM    (STAGES*S_STAGE)    // 122880
#define D_STAGE   30720               // dual: A,Bg,Bu 128x32 each
#define D_SMEM    (STAGES*D_STAGE)    // 122880

// ---------------- scratch (device globals) ----------------
__device__ __align__(128) float g_b1[BTD];
__device__ __align__(128) float g_conv[BTD];
__device__ __align__(128) float g_a[BTD];
__device__ __align__(128) float g_u[BTD];
__device__ __align__(128) float g_scan[BTD];
__device__ __align__(128) float g_x1[BTD];
__device__ __align__(128) float g_ls8[Dn];          // 8*log_sigmoid(lambda)

__device__ __align__(128) __half g_norm_h[BTD];
__device__ __align__(128) __half g_conv_h[BTD];
__device__ __align__(128) __half g_prod_h[BTD];
__device__ __align__(128) __half g_n2_h[BTD];
__device__ __align__(128) __half g_act_h[BTH];

__device__ __align__(128) __half g_w1_h[Dn*Dn];
__device__ __align__(128) __half g_wa_h[Dn*Dn];
__device__ __align__(128) __half g_wx_h[Dn*Dn];
__device__ __align__(128) __half g_w2_h[Dn*Dn];
__device__ __align__(128) __half g_wo_h[Dn*Dn];              // Wout
__device__ __align__(128) __half g_wg_h[(long)Hn*Dn];
__device__ __align__(128) __half g_wu_h[(long)Hn*Dn];
__device__ __align__(128) __half g_wout2_h[(long)Dn*Hn];     // Wo

// ---------------- helpers ----------------
__device__ __forceinline__ uint32_t smem_u32(const void* p) {
    uint32_t a;
    asm("{ .reg .u64 t; cvta.to.shared.u64 t, %1; cvt.u32.u64 %0, t; }"
        : "=r"(a) : "l"(p));
    return a;
}
__device__ __forceinline__ float gelu_f(float x) {
    return 0.5f * x * (1.0f + erff(x * 0.70710678118654752440f));
}
__device__ __forceinline__ float sigm_f(float x) {
    return 1.0f / (1.0f + expf(-x));
}
__device__ __forceinline__ uint32_t pack2h(float a, float b) {
    __half2 t = __floats2half2_rn(a, b);
    return *reinterpret_cast<uint32_t*>(&t);
}
__device__ __forceinline__ void ldsm4(uint32_t addr, uint32_t r[4]) {
    asm volatile("ldmatrix.sync.aligned.m8n8.x4.shared.b16 {%0,%1,%2,%3}, [%4];"
                 : "=r"(r[0]), "=r"(r[1]), "=r"(r[2]), "=r"(r[3]) : "r"(addr));
}
__device__ __forceinline__ void mma16816(float c[4], const uint32_t a[4], const uint32_t b[2]) {
    asm volatile("mma.sync.aligned.m16n8k16.row.col.f32.f16.f16.f32 "
                 "{%0,%1,%2,%3}, {%4,%5,%6,%7}, {%8,%9}, {%0,%1,%2,%3};"
                 : "+f"(c[0]), "+f"(c[1]), "+f"(c[2]), "+f"(c[3])
                 : "r"(a[0]), "r"(a[1]), "r"(a[2]), "r"(a[3]), "r"(b[0]), "r"(b[1]));
}
__device__ __forceinline__ void cp16(uint32_t dst, const void* src) {
    asm volatile("cp.async.cg.shared.global [%0], [%1], 16;" :: "r"(dst), "l"(src));
}
#define CP_COMMIT() asm volatile("cp.async.commit_group;" ::: "memory")
#define CP_WAIT2()  asm volatile("cp.async.wait_group 2;" ::: "memory")

// ================= GEMM 256x128: C[M,N] = A[M,K] @ B[N,K]^T =================
// EPI: 0=none 3=v+aux 5=gelu(v)*aux ; HOUT: 1 -> fp16 out
template<int EPI, int HOUT>
__global__ void __launch_bounds__(256, 1)
gemm_mma(const __half* __restrict__ A, const __half* __restrict__ B,
         float* __restrict__ C, __half* __restrict__ Ch,
         const float* __restrict__ aux, int N, int K)
{
    extern __shared__ __align__(128) char smem[];
    const uint32_t sb = smem_u32(smem);
    const int tid = threadIdx.x;
    const int lane = tid & 31, wid = tid >> 5;
    const int wm = wid & 3;            // 4 warps along M (64 rows each)
    const int wn = wid >> 2;           // 2 warps along N (64 cols each)
    const long rowA = (long)blockIdx.y * 256;
    const long rowB = (long)blockIdx.x * 128;
    const int nk = K >> 5;             // BK = 32

    float acc[4][8][4];
    #pragma unroll
    for (int i = 0; i < 4; i++)
        #pragma unroll
        for (int n = 0; n < 8; n++)
            #pragma unroll
            for (int q = 0; q < 4; q++) acc[i][n][q] = 0.f;

    auto load_stage = [&](int s, int kt) {
        const uint32_t base = sb + s * S_STAGE;
        const int k0 = kt << 5;
        #pragma unroll
        for (int t = 0; t < 4; t++) {
            const int idx = tid + t * 256;
            const int r = idx >> 2, c = idx & 3;
            cp16(base + r * 80 + c * 16, A + (rowA + r) * (long)K + k0 + c * 8);
        }
        #pragma unroll
        for (int t = 0; t < 2; t++) {
            const int idx = tid + t * 256;
            const int r = idx >> 2, c = idx & 3;
            cp16(base + S_A_BYTES + r * 80 + c * 16, B + (rowB + r) * (long)K + k0 + c * 8);
        }
    };

    load_stage(0, 0); CP_COMMIT();
    load_stage(1, 1); CP_COMMIT();
    load_stage(2, 2); CP_COMMIT();

    for (int kt = 0; kt < nk; kt++) {
        CP_WAIT2();
        __syncthreads();
        if (kt + 3 < nk) load_stage((kt + 3) & 3, kt + 3);
        CP_COMMIT();

        const uint32_t base = sb + (kt & 3) * S_STAGE;
        #pragma unroll
        for (int kk = 0; kk < 2; kk++) {
            const uint32_t koff = (kk * 16 + (lane >> 4) * 8) * 2;
            uint32_t ah[4][4];
            #pragma unroll
            for (int i = 0; i < 4; i++) {
                const uint32_t off = (uint32_t)(wm * 64 + i * 16 + (lane & 15)) * 80 + koff;
                ldsm4(base + off, ah[i]);
            }
            uint32_t bh[8][2];
            #pragma unroll
            for (int j = 0; j < 4; j++) {
                const uint32_t off = (uint32_t)(wn * 64 + j * 16 + (lane & 15)) * 80 + koff;
                uint32_t t[4];
                ldsm4(base + S_A_BYTES + off, t);
                bh[2*j][0] = t[0]; bh[2*j][1] = t[2];
                bh[2*j+1][0] = t[1]; bh[2*j+1][1] = t[3];
            }
            #pragma unroll
            for (int i = 0; i < 4; i++)
                #pragma unroll
                for (int n = 0; n < 8; n++)
                    mma16816(acc[i][n], ah[i], bh[n]);
        }
    }

    const long r0 = rowA + wm * 64 + (lane >> 2);
    const long c0 = rowB + wn * 64 + (lane & 3) * 2;
    #pragma unroll
    for (int i = 0; i < 4; i++) {
        #pragma unroll
        for (int n = 0; n < 8; n++) {
            #pragma unroll
            for (int h = 0; h < 2; h++) {
                const long row = r0 + i * 16 + h * 8;
                const long col = c0 + n * 8;
                float v0 = acc[i][n][2*h + 0];
                float v1 = acc[i][n][2*h + 1];
                if (EPI == 3) {
                    const float2 a2 = *(const float2*)(aux + row * (long)N + col);
                    v0 += a2.x; v1 += a2.y;
                } else if (EPI == 5) {
                    const float2 a2 = *(const float2*)(aux + row * (long)N + col);
                    v0 = gelu_f(v0) * a2.x; v1 = gelu_f(v1) * a2.y;
                }
                if (HOUT) {
                    *(uint32_t*)(Ch + row * (long)N + col) = pack2h(v0, v1);
                } else {
                    float2 o; o.x = v0; o.y = v1;
                    *(float2*)(C + row * (long)N + col) = o;
                }
            }
        }
    }
}

// ================= Dual GEMM 128x128 core (shared by gate + mlp) ============
// MODE 0 (mlp): Ch = gelu(A@Bg^T) * (A@Bu^T)            [fp16 out]
// MODE 1 (gate): r=sigm(g+b1[col]); i=sigm(u+b2[col]);
//                a=exp(r*ls8[col]); gate=sqrt(max((1-a)(1+a),1e-6));
//                Aout=a; Uout=gate*i*aux                 [fp32 out x2]
template<int MODE>
__global__ void __launch_bounds__(256, 1)
gemm_dual(const __half* __restrict__ A, const __half* __restrict__ Bg,
          const __half* __restrict__ Bu, __half* __restrict__ Ch,
          float* __restrict__ Aout, float* __restrict__ Uout,
          const float* __restrict__ aux, const float* __restrict__ bias1,
          const float* __restrict__ bias2, const float* __restrict__ ls8,
          int N, int K)
{
    extern __shared__ __align__(128) char smem[];
    const uint32_t sb = smem_u32(smem);
    const int tid = threadIdx.x;
    const int lane = tid & 31, wid = tid >> 5;
    const int wm = wid & 1;
    const int wn = wid >> 1;
    const long rowA = (long)blockIdx.y * 128;
    const long rowB = (long)blockIdx.x * 128;
    const int nk = K >> 5;

    float accg[4][4][4], accu[4][4][4];
    #pragma unroll
    for (int i = 0; i < 4; i++)
        #pragma unroll
        for (int n = 0; n < 4; n++)
            #pragma unroll
            for (int q = 0; q < 4; q++) { accg[i][n][q] = 0.f; accu[i][n][q] = 0.f; }

    auto load_stage = [&](int s, int kt) {
        const uint32_t base = sb + s * D_STAGE;
        const int k0 = kt << 5;
        #pragma unroll
        for (int t = 0; t < 2; t++) {
            const int idx = tid + t * 256;
            const int r = idx >> 2, c = idx & 3;
            cp16(base + r * 80 + c * 16, A + (rowA + r) * (long)K + k0 + c * 8);
            cp16(base + 10240 + r * 80 + c * 16, Bg + (rowB + r) * (long)K + k0 + c * 8);
            cp16(base + 20480 + r * 80 + c * 16, Bu + (rowB + r) * (long)K + k0 + c * 8);
        }
    };

    load_stage(0, 0); CP_COMMIT();
    load_stage(1, 1); CP_COMMIT();
    load_stage(2, 2); CP_COMMIT();

    for (int kt = 0; kt < nk; kt++) {
        CP_WAIT2();
        __syncthreads();
        if (kt + 3 < nk) load_stage((kt + 3) & 3, kt + 3);
        CP_COMMIT();

        const uint32_t base = sb + (kt & 3) * D_STAGE;
        #pragma unroll
        for (int kk = 0; kk < 2; kk++) {
            const uint32_t koff = (kk * 16 + (lane >> 4) * 8) * 2;
            uint32_t ah[4][4];
            #pragma unroll
            for (int i = 0; i < 4; i++) {
                const uint32_t off = (uint32_t)(wm * 64 + i * 16 + (lane & 15)) * 80 + koff;
                ldsm4(base + off, ah[i]);
            }
            uint32_t bg[4][2], bu[4][2];
            #pragma unroll
            for (int j = 0; j < 2; j++) {
                const uint32_t off = (uint32_t)(wn * 32 + j * 16 + (lane & 15)) * 80 + koff;
                uint32_t t[4], u[4];
                ldsm4(base + 10240 + off, t);
                ldsm4(base + 20480 + off, u);
                bg[2*j][0] = t[0]; bg[2*j][1] = t[2];
                bg[2*j+1][0] = t[1]; bg[2*j+1][1] = t[3];
                bu[2*j][0] = u[0]; bu[2*j][1] = u[2];
                bu[2*j+1][0] = u[1]; bu[2*j+1][1] = u[3];
            }
            #pragma unroll
            for (int i = 0; i < 4; i++)
                #pragma unroll
                for (int n = 0; n < 4; n++) {
                    mma16816(accg[i][n], ah[i], bg[n]);
                    mma16816(accu[i][n], ah[i], bu[n]);
                }
        }
    }

    const long r0 = rowA + wm * 64 + (lane >> 2);
    const long c0 = rowB + wn * 32 + (lane & 3) * 2;
    #pragma unroll
    for (int i = 0; i < 4; i++) {
        #pragma unroll
        for (int n = 0; n < 4; n++) {
            #pragma unroll
            for (int h = 0; h < 2; h++) {
                const long row = r0 + i * 16 + h * 8;
                const long col = c0 + n * 8;
                const float vg0 = accg[i][n][2*h + 0], vg1 = accg[i][n][2*h + 1];
                const float vu0 = accu[i][n][2*h + 0], vu1 = accu[i][n][2*h + 1];
                if (MODE == 0) {
                    *(uint32_t*)(Ch + row * (long)N + col) =
                        pack2h(gelu_f(vg0) * vu0, gelu_f(vg1) * vu1);
                } else {
                    const float r_0 = sigm_f(vg0 + bias1[col]);
                    const float r_1 = sigm_f(vg1 + bias1[col + 1]);
                    const float i_0 = sigm_f(vu0 + bias2[col]);
                    const float i_1 = sigm_f(vu1 + bias2[col + 1]);
                    const float a0 = expf(r_0 * ls8[col]);
                    const float a1 = expf(r_1 * ls8[col + 1]);
                    const float g0 = sqrtf(fmaxf((1.f - a0) * (1.f + a0), 1e-6f));
                    const float g1 = sqrtf(fmaxf((1.f - a1) * (1.f + a1), 1e-6f));
                    const float2 cv = *(const float2*)(aux + row * (long)N + col);
                    float2 av; av.x = a0; av.y = a1;
                    float2 uv; uv.x = g0 * i_0 * cv.x; uv.y = g1 * i_1 * cv.y;
                    *(float2*)(Aout + row * (long)N + col) = av;
                    *(float2*)(Uout + row * (long)N + col) = uv;
                }
            }
        }
    }
}

// ================= elementwise kernels =================
// one kernel converts ALL weights to fp16 + builds ls8 table
#define W1M (Dn*Dn/4)
#define WHM ((long)Hn*Dn/4)
__global__ void wconv_all_k(const float* __restrict__ W1, const float* __restrict__ Wa,
                            const float* __restrict__ Wx, const float* __restrict__ W2,
                            const float* __restrict__ Wout, const float* __restrict__ Wg,
                            const float* __restrict__ Wu, const float* __restrict__ Wo,
                            const float* __restrict__ ll,
                            __half* __restrict__ o1, __half* __restrict__ oa,
                            __half* __restrict__ ox, __half* __restrict__ o2,
                            __half* __restrict__ oo, __half* __restrict__ og,
                            __half* __restrict__ ou, __half* __restrict__ owo,
                            float* __restrict__ ls8)
{
    const long i = (long)blockIdx.x * 256 + threadIdx.x;
    const long T5 = 5L * W1M, T6 = T5 + WHM, T7 = T6 + WHM, T8 = T7 + WHM;
    const float* src; __half* dst; long off;
    if (i < T5) {
        const long s = i / W1M; off = i - s * W1M;
        const float* srcs[5] = {W1, Wa, Wx, W2, Wout};
        __half* dsts[5] = {o1, oa, ox, o2, oo};
        src = srcs[s]; dst = dsts[s];
    } else if (i < T6) { src = Wg;  dst = og;  off = i - T5; }
    else if (i < T7)   { src = Wu;  dst = ou;  off = i - T6; }
    else if (i < T8)   { src = Wo;  dst = owo; off = i - T7; }
    else {
        const long d = (i - T8) * 4;
        if (d < Dn) {
            #pragma unroll
            for (int j = 0; j < 4; j++)
                ls8[d + j] = -8.0f * log1pf(expf(-ll[d + j]));
        }
        return;
    }
    float4 v = *(const float4*)(src + off * 4);
    uint2 hv; hv.x = pack2h(v.x, v.y); hv.y = pack2h(v.z, v.w);
    *(uint2*)(dst + off * 4) = hv;
}

__global__ void rmsnorm_half_k(const float* __restrict__ x, const float* __restrict__ w,
                               __half* __restrict__ out) {
    const long row = blockIdx.x;
    const float* xr = x + row * (long)Dn;
    const int t4 = threadIdx.x * 4;
    float4 v = *(const float4*)(xr + t4);
    float ss = v.x*v.x + v.y*v.y + v.z*v.z + v.w*v.w;
    #pragma unroll
    for (int o = 16; o > 0; o >>= 1) ss += __shfl_xor_sync(0xffffffffu, ss, o);
    __shared__ float warps[8];
    if ((threadIdx.x & 31) == 0) warps[threadIdx.x >> 5] = ss;
    __syncthreads();
    float tot = 0.f;
    #pragma unroll
    for (int i = 0; i < 8; i++) tot += warps[i];
    const float inv = rsqrtf(tot * (1.0f / Dn) + 1.1920929e-07f);
    float4 wv = *(const float4*)(w + t4);
    uint2 hv;
    hv.x = pack2h(v.x*inv*wv.x, v.y*inv*wv.y);
    hv.y = pack2h(v.z*inv*wv.z, v.w*inv*wv.w);
    *(uint2*)(out + row * (long)Dn + t4) = hv;
}

__global__ void conv_kernel(const float* __restrict__ b1, const float* __restrict__ cbuf,
                            const float* __restrict__ cw, const float* __restrict__ cb,
                            float* __restrict__ out, __half* __restrict__ oh) {
    const long idx = (long)blockIdx.x * 256 + threadIdx.x;
    if (idx >= BTD) return;
    const int d = (int)(idx % Dn);
    const long td = idx / Dn;
    const int t = (int)(td % Tn);
    const int b = (int)(td / Tn);
    float acc = cb[d];
    #pragma unroll
    for (int k = 0; k < CONVK; k++) {
        const int tt = t + k - (CONVK - 1);
        float v = (tt >= 0) ? b1[((long)b * Tn + tt) * Dn + d]
                            : cbuf[((long)b * (CONVK - 1) + (t + k)) * Dn + d];
        acc = fmaf(v, cw[d * CONVK + k], acc);
    }
    out[idx] = acc;
    oh[idx] = __float2half_rn(acc);
}

// pure scan: h = a*h + u, software pipelined
__global__ void scan_pure_k(const float* __restrict__ a, const float* __restrict__ u,
                            const float* __restrict__ h0, float* __restrict__ out,
                            float* __restrict__ newh) {
    const int idx = blockIdx.x * 128 + threadIdx.x;
    const int b = idx / Dn, d = idx % Dn;
    const long base = (long)b * Tn * Dn + d;
    float h = h0[idx];
    float ca[4], cu[4];
    #pragma unroll
    for (int j = 0; j < 4; j++) {
        const long o = base + (long)j * Dn;
        ca[j] = a[o]; cu[j] = u[o];
    }
    for (int t0 = 0; t0 < Tn; t0 += 4) {
        float na[4], nu[4];
        if (t0 + 4 < Tn) {
            #pragma unroll
            for (int j = 0; j < 4; j++) {
                const long o = base + (long)(t0 + 4 + j) * Dn;
                na[j] = a[o]; nu[j] = u[o];
            }
        }
        #pragma unroll
        for (int j = 0; j < 4; j++) {
            h = fmaf(ca[j], h, cu[j]);
            out[base + (long)(t0 + j) * Dn] = h;
        }
        #pragma unroll
        for (int j = 0; j < 4; j++) { ca[j] = na[j]; cu[j] = nu[j]; }
    }
    newh[idx] = h;
}

__global__ void cbuf_k(const float* __restrict__ b1, float* __restrict__ out) {
    const int idx = blockIdx.x * 256 + threadIdx.x;
    if (idx >= Bsz * (CONVK - 1) * Dn) return;
    const int d = idx % Dn;
    const int j = (idx / Dn) % (CONVK - 1);
    const int b = idx / (Dn * (CONVK - 1));
    out[idx] = b1[((long)b * Tn + (Tn - (CONVK - 1) + j)) * Dn + d];
}

// ================= host side =================
extern "C" void kernel_launch(void* const* d_in, const int* in_sizes, int n_in,
                              void* d_out, int out_size) {
    const float* x_seq   = (const float*)d_in[0];
    const float* h0      = (const float*)d_in[1];
    const float* convbuf = (const float*)d_in[2];
    const float* norm1_w = (const float*)d_in[3];
    const float* W1      = (const float*)d_in[4];
    const float* conv_w  = (const float*)d_in[5];
    const float* conv_b  = (const float*)d_in[6];
    const float* Wa      = (const float*)d_in[7];
    const float* ba      = (const float*)d_in[8];
    const float* Wx      = (const float*)d_in[9];
    const float* bx      = (const float*)d_in[10];
    const float* log_lam = (const float*)d_in[11];
    const float* W2      = (const float*)d_in[12];
    const float* Wout    = (const float*)d_in[13];
    const float* norm2_w = (const float*)d_in[14];
    const float* Wg      = (const float*)d_in[15];
    const float* Wu      = (const float*)d_in[16];
    const float* Wo      = (const float*)d_in[17];

    float* out_x2 = (float*)d_out;
    float* out_h  = out_x2 + (long)BTD;
    float* out_cb = out_h + (long)Bsz * Dn;

    float *p_b1, *p_conv, *p_a, *p_u, *p_scan, *p_x1, *p_ls8;
    cudaGetSymbolAddress((void**)&p_b1, g_b1);
    cudaGetSymbolAddress((void**)&p_conv, g_conv);
    cudaGetSymbolAddress((void**)&p_a, g_a);
    cudaGetSymbolAddress((void**)&p_u, g_u);
    cudaGetSymbolAddress((void**)&p_scan, g_scan);
    cudaGetSymbolAddress((void**)&p_x1, g_x1);
    cudaGetSymbolAddress((void**)&p_ls8, g_ls8);

    __half *nh, *ch, *ph, *n2h, *acth;
    cudaGetSymbolAddress((void**)&nh, g_norm_h);
    cudaGetSymbolAddress((void**)&ch, g_conv_h);
    cudaGetSymbolAddress((void**)&ph, g_prod_h);
    cudaGetSymbolAddress((void**)&n2h, g_n2_h);
    cudaGetSymbolAddress((void**)&acth, g_act_h);

    __half *w1h, *wah, *wxh, *w2h, *woh, *wgh, *wuh, *wo2h;
    cudaGetSymbolAddress((void**)&w1h, g_w1_h);
    cudaGetSymbolAddress((void**)&wah, g_wa_h);
    cudaGetSymbolAddress((void**)&wxh, g_wx_h);
    cudaGetSymbolAddress((void**)&w2h, g_w2_h);
    cudaGetSymbolAddress((void**)&woh, g_wo_h);
    cudaGetSymbolAddress((void**)&wgh, g_wg_h);
    cudaGetSymbolAddress((void**)&wuh, g_wu_h);
    cudaGetSymbolAddress((void**)&wo2h, g_wout2_h);

    cudaFuncSetAttribute(gemm_mma<0,0>, cudaFuncAttributeMaxDynamicSharedMemorySize, S_SMEM);
    cudaFuncSetAttribute(gemm_mma<3,0>, cudaFuncAttributeMaxDynamicSharedMemorySize, S_SMEM);
    cudaFuncSetAttribute(gemm_mma<5,1>, cudaFuncAttributeMaxDynamicSharedMemorySize, S_SMEM);
    cudaFuncSetAttribute(gemm_dual<0>,  cudaFuncAttributeMaxDynamicSharedMemorySize, D_SMEM);
    cudaFuncSetAttribute(gemm_dual<1>,  cudaFuncAttributeMaxDynamicSharedMemorySize, D_SMEM);

    const dim3 gD(Dn / 128, BT / 256);     // (8, 64)   single 256x128
    const dim3 gDd(Dn / 128, BT / 128);    // (8, 128)  dual 128x128
    const dim3 gH(Hn / 128, BT / 128);     // (32, 128) dual mlp
    const int EW = (BTD + 255) / 256;

    const long WTOT = 5L*W1M + 3L*WHM + (Dn/4);
    // 1. all weight conversions + ls8 table (ONE launch)
    wconv_all_k<<<(int)((WTOT + 255) / 256), 256>>>(
        W1, Wa, Wx, W2, Wout, Wg, Wu, Wo, log_lam,
        w1h, wah, wxh, w2h, woh, wgh, wuh, wo2h, p_ls8);
    // 2. rmsnorm1 -> fp16
    rmsnorm_half_k<<<BT, 256>>>(x_seq, norm1_w, nh);
    // 3. b1 = normed @ W1^T
    gemm_mma<0,0><<<gD, 256, S_SMEM>>>(nh, w1h, p_b1, nullptr, nullptr, Dn, Dn);
    // 4. conv (+fp16)
    conv_kernel<<<EW, 256>>>(p_b1, convbuf, conv_w, conv_b, p_conv, ch);
    // 5. new_conv_buf
    cbuf_k<<<(Bsz * (CONVK - 1) * Dn + 255) / 256, 256>>>(p_b1, out_cb);
    // 6. dual gate GEMM -> a, u   (ncu capture slot)
    gemm_dual<1><<<gDd, 256, D_SMEM>>>(ch, wah, wxh, nullptr, p_a, p_u,
                                       p_conv, ba, bx, p_ls8, Dn, Dn);
    // 7. pure scan
    scan_pure_k<<<(Bsz * Dn) / 128, 128>>>(p_a, p_u, h0, p_scan, out_h);
    // 8. prod = gelu(normed @ W2^T) * scan -> fp16
    gemm_mma<5,1><<<gD, 256, S_SMEM>>>(nh, w2h, nullptr, ph, p_scan, Dn, Dn);
    // 9. x1 = x_seq + prod @ Wout^T
    gemm_mma<3,0><<<gD, 256, S_SMEM>>>(ph, woh, p_x1, nullptr, x_seq, Dn, Dn);
    // 10. n2 = rmsnorm(x1) -> fp16
    rmsnorm_half_k<<<BT, 256>>>(p_x1, norm2_w, n2h);
    // 11. act = gelu(n2@Wg^T) * (n2@Wu^T) -> fp16
    gemm_dual<0><<<gH, 256, D_SMEM>>>(n2h, wgh, wuh, acth, nullptr, nullptr,
                                      nullptr, nullptr, nullptr, nullptr, Hn, Dn);
    // 12. x2 = x1 + act @ Wo^T
    gemm_mma<3,0><<<gD, 256, S_SMEM>>>(acth, wo2h, out_x2, nullptr, p_x1, Dn, Hn);
}

// round 11
// speedup vs baseline: 1.0244x; 1.0244x over previous
#include <cuda_runtime.h>
#include <cuda_fp16.h>
#include <math.h>
#include <stdint.h>

// ---------------- problem dims ----------------
#define Bsz 16
#define Tn  1024
#define Dn  1024
#define Hn  4096
#define BT  (Bsz*Tn)              // 16384
#define BTD (Bsz*Tn*Dn)           // 16777216
#define BTH (Bsz*Tn*Hn)           // 67108864
#define CONVK 4

// ---------------- GEMM tile config ----------------
#define STAGES 4
#define S_A_BYTES 20480           // 256 rows x 80B
#define S_STAGE   30720
#define S_SMEM    (STAGES*S_STAGE)    // 122880
#define D_STAGE   30720               // dual: A,Bg,Bu 128x32 each
#define D_SMEM    (STAGES*D_STAGE)    // 122880

// ---------------- scratch (device globals) ----------------
__device__ __align__(128) float g_r[BTD];
__device__ __align__(128) float g_i[BTD];
__device__ __align__(128) float g_x1[BTD];
__device__ __align__(128) float g_ls8[Dn];          // 8*log_sigmoid(lambda)

__device__ __align__(128) __half g_b1_h[BTD];
__device__ __align__(128) __half g_norm_h[BTD];
__device__ __align__(128) __half g_conv_h[BTD];
__device__ __align__(128) __half g_scan_h[BTD];
__device__ __align__(128) __half g_prod_h[BTD];
__device__ __align__(128) __half g_n2_h[BTD];
__device__ __align__(128) __half g_act_h[BTH];

__device__ __align__(128) __half g_w1_h[Dn*Dn];
__device__ __align__(128) __half g_wa_h[Dn*Dn];
__device__ __align__(128) __half g_wx_h[Dn*Dn];
__device__ __align__(128) __half g_w2_h[Dn*Dn];
__device__ __align__(128) __half g_wo_h[Dn*Dn];              // Wout
__device__ __align__(128) __half g_wg_h[(long)Hn*Dn];
__device__ __align__(128) __half g_wu_h[(long)Hn*Dn];
__device__ __align__(128) __half g_wout2_h[(long)Dn*Hn];     // Wo

// ---------------- helpers ----------------
__device__ __forceinline__ uint32_t smem_u32(const void* p) {
    uint32_t a;
    asm("{ .reg .u64 t; cvta.to.shared.u64 t, %1; cvt.u32.u64 %0, t; }"
        : "=r"(a) : "l"(p));
    return a;
}
__device__ __forceinline__ float gelu_f(float x) {
    return 0.5f * x * (1.0f + erff(x * 0.70710678118654752440f));
}
__device__ __forceinline__ float sigm_f(float x) {
    return 1.0f / (1.0f + expf(-x));
}
__device__ __forceinline__ uint32_t pack2h(float a, float b) {
    __half2 t = __floats2half2_rn(a, b);
    return *reinterpret_cast<uint32_t*>(&t);
}
__device__ __forceinline__ void ldsm4(uint32_t addr, uint32_t r[4]) {
    asm volatile("ldmatrix.sync.aligned.m8n8.x4.shared.b16 {%0,%1,%2,%3}, [%4];"
                 : "=r"(r[0]), "=r"(r[1]), "=r"(r[2]), "=r"(r[3]) : "r"(addr));
}
__device__ __forceinline__ void mma16816(float c[4], const uint32_t a[4], const uint32_t b[2]) {
    asm volatile("mma.sync.aligned.m16n8k16.row.col.f32.f16.f16.f32 "
                 "{%0,%1,%2,%3}, {%4,%5,%6,%7}, {%8,%9}, {%0,%1,%2,%3};"
                 : "+f"(c[0]), "+f"(c[1]), "+f"(c[2]), "+f"(c[3])
                 : "r"(a[0]), "r"(a[1]), "r"(a[2]), "r"(a[3]), "r"(b[0]), "r"(b[1]));
}
__device__ __forceinline__ void cp16(uint32_t dst, const void* src) {
    asm volatile("cp.async.cg.shared.global [%0], [%1], 16;" :: "r"(dst), "l"(src));
}
#define CP_COMMIT() asm volatile("cp.async.commit_group;" ::: "memory")
#define CP_WAIT2()  asm volatile("cp.async.wait_group 2;" ::: "memory")

// ================= GEMM 256x128: C[M,N] = A[M,K] @ B[N,K]^T =================
// EPI: 0=none 1=sigmoid(v+bias[col]) 3=v+auxf 6=gelu(v)*auxh
// HOUT: 1 -> fp16 out
template<int EPI, int HOUT>
__global__ void __launch_bounds__(256, 1)
gemm_mma(const __half* __restrict__ A, const __half* __restrict__ B,
         float* __restrict__ C, __half* __restrict__ Ch,
         const float* __restrict__ auxf, const __half* __restrict__ auxh,
         const float* __restrict__ bias, int N, int K)
{
    extern __shared__ __align__(128) char smem[];
    const uint32_t sb = smem_u32(smem);
    const int tid = threadIdx.x;
    const int lane = tid & 31, wid = tid >> 5;
    const int wm = wid & 3;            // 4 warps along M (64 rows each)
    const int wn = wid >> 2;           // 2 warps along N (64 cols each)
    const long rowA = (long)blockIdx.y * 256;
    const long rowB = (long)blockIdx.x * 128;
    const int nk = K >> 5;             // BK = 32

    float acc[4][8][4];
    #pragma unroll
    for (int i = 0; i < 4; i++)
        #pragma unroll
        for (int n = 0; n < 8; n++)
            #pragma unroll
            for (int q = 0; q < 4; q++) acc[i][n][q] = 0.f;

    auto load_stage = [&](int s, int kt) {
        const uint32_t base = sb + s * S_STAGE;
        const int k0 = kt << 5;
        #pragma unroll
        for (int t = 0; t < 4; t++) {
            const int idx = tid + t * 256;
            const int r = idx >> 2, c = idx & 3;
            cp16(base + r * 80 + c * 16, A + (rowA + r) * (long)K + k0 + c * 8);
        }
        #pragma unroll
        for (int t = 0; t < 2; t++) {
            const int idx = tid + t * 256;
            const int r = idx >> 2, c = idx & 3;
            cp16(base + S_A_BYTES + r * 80 + c * 16, B + (rowB + r) * (long)K + k0 + c * 8);
        }
    };

    load_stage(0, 0); CP_COMMIT();
    load_stage(1, 1); CP_COMMIT();
    load_stage(2, 2); CP_COMMIT();

    for (int kt = 0; kt < nk; kt++) {
        CP_WAIT2();
        __syncthreads();
        if (kt + 3 < nk) load_stage((kt + 3) & 3, kt + 3);
        CP_COMMIT();

        const uint32_t base = sb + (kt & 3) * S_STAGE;
        #pragma unroll
        for (int kk = 0; kk < 2; kk++) {
            const uint32_t koff = (kk * 16 + (lane >> 4) * 8) * 2;
            uint32_t ah[4][4];
            #pragma unroll
            for (int i = 0; i < 4; i++) {
                const uint32_t off = (uint32_t)(wm * 64 + i * 16 + (lane & 15)) * 80 + koff;
                ldsm4(base + off, ah[i]);
            }
            uint32_t bh[8][2];
            #pragma unroll
            for (int j = 0; j < 4; j++) {
                const uint32_t off = (uint32_t)(wn * 64 + j * 16 + (lane & 15)) * 80 + koff;
                uint32_t t[4];
                ldsm4(base + S_A_BYTES + off, t);
                bh[2*j][0] = t[0]; bh[2*j][1] = t[2];
                bh[2*j+1][0] = t[1]; bh[2*j+1][1] = t[3];
            }
            #pragma unroll
            for (int i = 0; i < 4; i++)
                #pragma unroll
                for (int n = 0; n < 8; n++)
                    mma16816(acc[i][n], ah[i], bh[n]);
        }
    }

    const long r0 = rowA + wm * 64 + (lane >> 2);
    const long c0 = rowB + wn * 64 + (lane & 3) * 2;
    #pragma unroll
    for (int i = 0; i < 4; i++) {
        #pragma unroll
        for (int n = 0; n < 8; n++) {
            #pragma unroll
            for (int h = 0; h < 2; h++) {
                const long row = r0 + i * 16 + h * 8;
                const long col = c0 + n * 8;
                float v0 = acc[i][n][2*h + 0];
                float v1 = acc[i][n][2*h + 1];
                if (EPI == 1) {
                    v0 = sigm_f(v0 + bias[col]);
                    v1 = sigm_f(v1 + bias[col + 1]);
                } else if (EPI == 3) {
                    const float2 a2 = *(const float2*)(auxf + row * (long)N + col);
                    v0 += a2.x; v1 += a2.y;
                } else if (EPI == 6) {
                    const __half2 h2 = *(const __half2*)(auxh + row * (long)N + col);
                    v0 = gelu_f(v0) * __half2float(h2.x);
                    v1 = gelu_f(v1) * __half2float(h2.y);
                }
                if (HOUT) {
                    *(uint32_t*)(Ch + row * (long)N + col) = pack2h(v0, v1);
                } else {
                    float2 o; o.x = v0; o.y = v1;
                    *(float2*)(C + row * (long)N + col) = o;
                }
            }
        }
    }
}

// ================= Dual MLP GEMM 128x128: Ch = gelu(A@Bg^T)*(A@Bu^T) ========
__global__ void __launch_bounds__(256, 1)
gemm_dual(const __half* __restrict__ A, const __half* __restrict__ Bg,
          const __half* __restrict__ Bu, __half* __restrict__ Ch,
          int N, int K)
{
    extern __shared__ __align__(128) char smem[];
    const uint32_t sb = smem_u32(smem);
    const int tid = threadIdx.x;
    const int lane = tid & 31, wid = tid >> 5;
    const int wm = wid & 1;
    const int wn = wid >> 1;
    const long rowA = (long)blockIdx.y * 128;
    const long rowB = (long)blockIdx.x * 128;
    const int nk = K >> 5;

    float accg[4][4][4], accu[4][4][4];
    #pragma unroll
    for (int i = 0; i < 4; i++)
        #pragma unroll
        for (int n = 0; n < 4; n++)
            #pragma unroll
            for (int q = 0; q < 4; q++) { accg[i][n][q] = 0.f; accu[i][n][q] = 0.f; }

    auto load_stage = [&](int s, int kt) {
        const uint32_t base = sb + s * D_STAGE;
        const int k0 = kt << 5;
        #pragma unroll
        for (int t = 0; t < 2; t++) {
            const int idx = tid + t * 256;
            const int r = idx >> 2, c = idx & 3;
            cp16(base + r * 80 + c * 16, A + (rowA + r) * (long)K + k0 + c * 8);
            cp16(base + 10240 + r * 80 + c * 16, Bg + (rowB + r) * (long)K + k0 + c * 8);
            cp16(base + 20480 + r * 80 + c * 16, Bu + (rowB + r) * (long)K + k0 + c * 8);
        }
    };

    load_stage(0, 0); CP_COMMIT();
    load_stage(1, 1); CP_COMMIT();
    load_stage(2, 2); CP_COMMIT();

    for (int kt = 0; kt < nk; kt++) {
        CP_WAIT2();
        __syncthreads();
        if (kt + 3 < nk) load_stage((kt + 3) & 3, kt + 3);
        CP_COMMIT();

        const uint32_t base = sb + (kt & 3) * D_STAGE;
        #pragma unroll
        for (int kk = 0; kk < 2; kk++) {
            const uint32_t koff = (kk * 16 + (lane >> 4) * 8) * 2;
            uint32_t ah[4][4];
            #pragma unroll
            for (int i = 0; i < 4; i++) {
                const uint32_t off = (uint32_t)(wm * 64 + i * 16 + (lane & 15)) * 80 + koff;
                ldsm4(base + off, ah[i]);
            }
            uint32_t bg[4][2], bu[4][2];
            #pragma unroll
            for (int j = 0; j < 2; j++) {
                const uint32_t off = (uint32_t)(wn * 32 + j * 16 + (lane & 15)) * 80 + koff;
                uint32_t t[4], u[4];
                ldsm4(base + 10240 + off, t);
                ldsm4(base + 20480 + off, u);
                bg[2*j][0] = t[0]; bg[2*j][1] = t[2];
                bg[2*j+1][0] = t[1]; bg[2*j+1][1] = t[3];
                bu[2*j][0] = u[0]; bu[2*j][1] = u[2];
                bu[2*j+1][0] = u[1]; bu[2*j+1][1] = u[3];
            }
            #pragma unroll
            for (int i = 0; i < 4; i++)
                #pragma unroll
                for (int n = 0; n < 4; n++) {
                    mma16816(accg[i][n], ah[i], bg[n]);
                    mma16816(accu[i][n], ah[i], bu[n]);
                }
        }
    }

    const long r0 = rowA + wm * 64 + (lane >> 2);
    const long c0 = rowB + wn * 32 + (lane & 3) * 2;
    #pragma unroll
    for (int i = 0; i < 4; i++) {
        #pragma unroll
        for (int n = 0; n < 4; n++) {
            #pragma unroll
            for (int h = 0; h < 2; h++) {
                const long row = r0 + i * 16 + h * 8;
                const long col = c0 + n * 8;
                const float v0 = gelu_f(accg[i][n][2*h + 0]) * accu[i][n][2*h + 0];
                const float v1 = gelu_f(accg[i][n][2*h + 1]) * accu[i][n][2*h + 1];
                *(uint32_t*)(Ch + row * (long)N + col) = pack2h(v0, v1);
            }
        }
    }
}

// ================= elementwise kernels =================
#define W1M (Dn*Dn/4)
#define WHM ((long)Hn*Dn/4)
__global__ void wconv_all_k(const float* __restrict__ W1, const float* __restrict__ Wa,
                            const float* __restrict__ Wx, const float* __restrict__ W2,
                            const float* __restrict__ Wout, const float* __restrict__ Wg,
                            const float* __restrict__ Wu, const float* __restrict__ Wo,
                            const float* __restrict__ ll,
                            __half* __restrict__ o1, __half* __restrict__ oa,
                            __half* __restrict__ ox, __half* __restrict__ o2,
                            __half* __restrict__ oo, __half* __restrict__ og,
                            __half* __restrict__ ou, __half* __restrict__ owo,
                            float* __restrict__ ls8)
{
    const long i = (long)blockIdx.x * 256 + threadIdx.x;
    const long T5 = 5L * W1M, T6 = T5 + WHM, T7 = T6 + WHM, T8 = T7 + WHM;
    const float* src; __half* dst; long off;
    if (i < T5) {
        const long s = i / W1M; off = i - s * W1M;
        const float* srcs[5] = {W1, Wa, Wx, W2, Wout};
        __half* dsts[5] = {o1, oa, ox, o2, oo};
        src = srcs[s]; dst = dsts[s];
    } else if (i < T6) { src = Wg;  dst = og;  off = i - T5; }
    else if (i < T7)   { src = Wu;  dst = ou;  off = i - T6; }
    else if (i < T8)   { src = Wo;  dst = owo; off = i - T7; }
    else {
        const long d = (i - T8) * 4;
        if (d < Dn) {
            #pragma unroll
            for (int j = 0; j < 4; j++)
                ls8[d + j] = -8.0f * log1pf(expf(-ll[d + j]));
        }
        return;
    }
    float4 v = *(const float4*)(src + off * 4);
    uint2 hv; hv.x = pack2h(v.x, v.y); hv.y = pack2h(v.z, v.w);
    *(uint2*)(dst + off * 4) = hv;
}

__global__ void rmsnorm_half_k(const float* __restrict__ x, const float* __restrict__ w,
                               __half* __restrict__ out) {
    const long row = blockIdx.x;
    const float* xr = x + row * (long)Dn;
    const int t4 = threadIdx.x * 4;
    float4 v = *(const float4*)(xr + t4);
    float ss = v.x*v.x + v.y*v.y + v.z*v.z + v.w*v.w;
    #pragma unroll
    for (int o = 16; o > 0; o >>= 1) ss += __shfl_xor_sync(0xffffffffu, ss, o);
    __shared__ float warps[8];
    if ((threadIdx.x & 31) == 0) warps[threadIdx.x >> 5] = ss;
    __syncthreads();
    float tot = 0.f;
    #pragma unroll
    for (int i = 0; i < 8; i++) tot += warps[i];
    const float inv = rsqrtf(tot * (1.0f / Dn) + 1.1920929e-07f);
    float4 wv = *(const float4*)(w + t4);
    uint2 hv;
    hv.x = pack2h(v.x*inv*wv.x, v.y*inv*wv.y);
    hv.y = pack2h(v.z*inv*wv.z, v.w*inv*wv.w);
    *(uint2*)(out + row * (long)Dn + t4) = hv;
}

// row-per-block conv: block = one (b,t) row; thread = 4 channels (float4)
__global__ void __launch_bounds__(256)
conv_row_k(const __half* __restrict__ b1h, const float* __restrict__ cbuf,
           const float* __restrict__ cw, const float* __restrict__ cb,
           __half* __restrict__ oh) {
    const int row = blockIdx.x;              // 0..BT-1
    const int t = row & (Tn - 1);
    const int b = row >> 10;                 // Tn = 1024
    const int d4 = threadIdx.x * 4;
    // taps for 4 channels: cw is [D][4] floats
    const float4 w0 = *(const float4*)(cw + (d4 + 0) * CONVK);
    const float4 w1 = *(const float4*)(cw + (d4 + 1) * CONVK);
    const float4 w2 = *(const float4*)(cw + (d4 + 2) * CONVK);
    const float4 w3 = *(const float4*)(cw + (d4 + 3) * CONVK);
    const float4 bias = *(const float4*)(cb + d4);
    float acc0 = bias.x, acc1 = bias.y, acc2 = bias.z, acc3 = bias.w;
    #pragma unroll
    for (int k = 0; k < CONVK; k++) {
        const int tt = t + k - (CONVK - 1);
        float s0, s1, s2, s3;
        if (tt >= 0) {
            const uint2 hv = *(const uint2*)(b1h + ((long)b * Tn + tt) * Dn + d4);
            const __half2 h0 = *(const __half2*)&hv.x;
            const __half2 h1 = *(const __half2*)&hv.y;
            s0 = __half2float(h0.x); s1 = __half2float(h0.y);
            s2 = __half2float(h1.x); s3 = __half2float(h1.y);
        } else {
            const float4 f = *(const float4*)(cbuf + ((long)b * (CONVK - 1) + (t + k)) * Dn + d4);
            s0 = f.x; s1 = f.y; s2 = f.z; s3 = f.w;
        }
        const float wk0 = (&w0.x)[k], wk1 = (&w1.x)[k], wk2 = (&w2.x)[k], wk3 = (&w3.x)[k];
        acc0 = fmaf(s0, wk0, acc0);
        acc1 = fmaf(s1, wk1, acc1);
        acc2 = fmaf(s2, wk2, acc2);
        acc3 = fmaf(s3, wk3, acc3);
    }
    uint2 hv; hv.x = pack2h(acc0, acc1); hv.y = pack2h(acc2, acc3);
    *(uint2*)(oh + (long)row * Dn + d4) = hv;
}

// fused gate + scan: reads r,i (fp32), conv (fp16); writes scan fp16 + final h
__global__ void scan_fused_k(const float* __restrict__ r, const float* __restrict__ ig,
                             const __half* __restrict__ convh, const float* __restrict__ ls8,
                             const float* __restrict__ h0, __half* __restrict__ outh,
                             float* __restrict__ newh) {
    const int idx = blockIdx.x * 128 + threadIdx.x;
    const int b = idx / Dn, d = idx % Dn;
    const float l8 = ls8[d];
    const long base = (long)b * Tn * Dn + d;
    float h = h0[idx];
    float cr[4], ci[4], cc[4];
    #pragma unroll
    for (int j = 0; j < 4; j++) {
        const long o = base + (long)j * Dn;
        cr[j] = r[o]; ci[j] = ig[o]; cc[j] = __half2float(convh[o]);
    }
    for (int t0 = 0; t0 < Tn; t0 += 4) {
        float nr[4], ni[4], nc[4];
        if (t0 + 4 < Tn) {
            #pragma unroll
            for (int j = 0; j < 4; j++) {
                const long o = base + (long)(t0 + 4 + j) * Dn;
                nr[j] = r[o]; ni[j] = ig[o]; nc[j] = __half2float(convh[o]);
            }
        }
        #pragma unroll
        for (int j = 0; j < 4; j++) {
            const float a = expf(cr[j] * l8);
            const float gate = sqrtf(fmaxf((1.f - a) * (1.f + a), 1e-6f));
            h = fmaf(a, h, gate * ci[j] * cc[j]);
            outh[base + (long)(t0 + j) * Dn] = __float2half_rn(h);
        }
        #pragma unroll
        for (int j = 0; j < 4; j++) { cr[j] = nr[j]; ci[j] = ni[j]; cc[j] = nc[j]; }
    }
    newh[idx] = h;
}

__global__ void cbuf_k(const __half* __restrict__ b1h, float* __restrict__ out) {
    const int idx = blockIdx.x * 256 + threadIdx.x;
    if (idx >= Bsz * (CONVK - 1) * Dn) return;
    const int d = idx % Dn;
    const int j = (idx / Dn) % (CONVK - 1);
    const int b = idx / (Dn * (CONVK - 1));
    out[idx] = __half2float(b1h[((long)b * Tn + (Tn - (CONVK - 1) + j)) * Dn + d]);
}

// ================= host side =================
extern "C" void kernel_launch(void* const* d_in, const int* in_sizes, int n_in,
                              void* d_out, int out_size) {
    const float* x_seq   = (const float*)d_in[0];
    const float* h0      = (const float*)d_in[1];
    const float* convbuf = (const float*)d_in[2];
    const float* norm1_w = (const float*)d_in[3];
    const float* W1      = (const float*)d_in[4];
    const float* conv_w  = (const float*)d_in[5];
    const float* conv_b  = (const float*)d_in[6];
    const float* Wa      = (const float*)d_in[7];
    const float* ba      = (const float*)d_in[8];
    const float* Wx      = (const float*)d_in[9];
    const float* bx      = (const float*)d_in[10];
    const float* log_lam = (const float*)d_in[11];
    const float* W2      = (const float*)d_in[12];
    const float* Wout    = (const float*)d_in[13];
    const float* norm2_w = (const float*)d_in[14];
    const float* Wg      = (const float*)d_in[15];
    const float* Wu      = (const float*)d_in[16];
    const float* Wo      = (const float*)d_in[17];

    float* out_x2 = (float*)d_out;
    float* out_h  = out_x2 + (long)BTD;
    float* out_cb = out_h + (long)Bsz * Dn;

    float *p_r, *p_i, *p_x1, *p_ls8;
    cudaGetSymbolAddress((void**)&p_r, g_r);
    cudaGetSymbolAddress((void**)&p_i, g_i);
    cudaGetSymbolAddress((void**)&p_x1, g_x1);
    cudaGetSymbolAddress((void**)&p_ls8, g_ls8);

    __half *b1h, *nh, *ch, *sch, *ph, *n2h, *acth;
    cudaGetSymbolAddress((void**)&b1h, g_b1_h);
    cudaGetSymbolAddress((void**)&nh, g_norm_h);
    cudaGetSymbolAddress((void**)&ch, g_conv_h);
    cudaGetSymbolAddress((void**)&sch, g_scan_h);
    cudaGetSymbolAddress((void**)&ph, g_prod_h);
    cudaGetSymbolAddress((void**)&n2h, g_n2_h);
    cudaGetSymbolAddress((void**)&acth, g_act_h);

    __half *w1h, *wah, *wxh, *w2h, *woh, *wgh, *wuh, *wo2h;
    cudaGetSymbolAddress((void**)&w1h, g_w1_h);
    cudaGetSymbolAddress((void**)&wah, g_wa_h);
    cudaGetSymbolAddress((void**)&wxh, g_wx_h);
    cudaGetSymbolAddress((void**)&w2h, g_w2_h);
    cudaGetSymbolAddress((void**)&woh, g_wo_h);
    cudaGetSymbolAddress((void**)&wgh, g_wg_h);
    cudaGetSymbolAddress((void**)&wuh, g_wu_h);
    cudaGetSymbolAddress((void**)&wo2h, g_wout2_h);

    cudaFuncSetAttribute(gemm_mma<0,1>, cudaFuncAttributeMaxDynamicSharedMemorySize, S_SMEM);
    cudaFuncSetAttribute(gemm_mma<1,0>, cudaFuncAttributeMaxDynamicSharedMemorySize, S_SMEM);
    cudaFuncSetAttribute(gemm_mma<3,0>, cudaFuncAttributeMaxDynamicSharedMemorySize, S_SMEM);
    cudaFuncSetAttribute(gemm_mma<6,1>, cudaFuncAttributeMaxDynamicSharedMemorySize, S_SMEM);
    cudaFuncSetAttribute(gemm_dual,     cudaFuncAttributeMaxDynamicSharedMemorySize, D_SMEM);

    const dim3 gD(Dn / 128, BT / 256);     // (8, 64)   single 256x128
    const dim3 gH(Hn / 128, BT / 128);     // (32, 128) dual mlp

    const long WTOT = 5L*W1M + 3L*WHM + (Dn/4);
    // 1. all weight conversions + ls8 table (ONE launch)
    wconv_all_k<<<(int)((WTOT + 255) / 256), 256>>>(
        W1, Wa, Wx, W2, Wout, Wg, Wu, Wo, log_lam,
        w1h, wah, wxh, w2h, woh, wgh, wuh, wo2h, p_ls8);
    // 2. rmsnorm1 -> fp16
    rmsnorm_half_k<<<BT, 256>>>(x_seq, norm1_w, nh);
    // 3. b1 = normed @ W1^T -> fp16
    gemm_mma<0,1><<<gD, 256, S_SMEM>>>(nh, w1h, nullptr, b1h, nullptr, nullptr, nullptr, Dn, Dn);
    // 4. conv -> fp16 (row-per-block)
    conv_row_k<<<BT, 256>>>(b1h, convbuf, conv_w, conv_b, ch);
    // 5. new_conv_buf (fp32 from fp16 b1)
    cbuf_k<<<(Bsz * (CONVK - 1) * Dn + 255) / 256, 256>>>(b1h, out_cb);
    // 6/7. r, i = sigmoid(conv @ {Wa,Wx}^T + bias)
    gemm_mma<1,0><<<gD, 256, S_SMEM>>>(ch, wah, p_r, nullptr, nullptr, nullptr, ba, Dn, Dn);
    gemm_mma<1,0><<<gD, 256, S_SMEM>>>(ch, wxh, p_i, nullptr, nullptr, nullptr, bx, Dn, Dn);
    // 8. fused gate + scan -> fp16 scan
    scan_fused_k<<<(Bsz * Dn) / 128, 128>>>(p_r, p_i, ch, p_ls8, h0, sch, out_h);
    // 9. prod = gelu(normed @ W2^T) * scan -> fp16
    gemm_mma<6,1><<<gD, 256, S_SMEM>>>(nh, w2h, nullptr, ph, nullptr, sch, nullptr, Dn, Dn);
    // 10. x1 = x_seq + prod @ Wout^T
    gemm_mma<3,0><<<gD, 256, S_SMEM>>>(ph, woh, p_x1, nullptr, x_seq, nullptr, nullptr, Dn, Dn);
    // 11. n2 = rmsnorm(x1) -> fp16
    rmsnorm_half_k<<<BT, 256>>>(p_x1, norm2_w, n2h);
    // 12. act = gelu(n2@Wg^T) * (n2@Wu^T) -> fp16
    gemm_dual<<<gH, 256, D_SMEM>>>(n2h, wgh, wuh, acth, Hn, Dn);
    // 13. x2 = x1 + act @ Wo^T
    gemm_mma<3,0><<<gD, 256, S_SMEM>>>(acth, wo2h, out_x2, nullptr, p_x1, nullptr, nullptr, Dn, Hn);
}

// round 12
// speedup vs baseline: 1.0817x; 1.0559x over previous
#include <cuda_runtime.h>
#include <cuda_fp16.h>
#include <math.h>
#include <stdint.h>

// ---------------- problem dims ----------------
#define Bsz 16
#define Tn  1024
#define Dn  1024
#define Hn  4096
#define BT  (Bsz*Tn)              // 16384
#define BTD (Bsz*Tn*Dn)           // 16777216
#define BTH (Bsz*Tn*Hn)           // 67108864
#define CONVK 4
#define NCH 4                     // scan chunks
#define CHL (Tn/NCH)              // 256

// ---------------- GEMM tile config ----------------
#define STAGES 4
#define S_A_BYTES 20480           // 256 rows x 80B
#define S_STAGE   30720
#define S_SMEM    (STAGES*S_STAGE)    // 122880
#define D_STAGE   30720               // dual: A,Bg,Bu 128x32 each
#define D_SMEM    (STAGES*D_STAGE)    // 122880

// ---------------- scratch (device globals) ----------------
__device__ __align__(128) float g_r[BTD];
__device__ __align__(128) float g_x1[BTD];
__device__ __align__(128) float g_ls8[Dn];          // 8*log_sigmoid(lambda)
__device__ __align__(128) float g_sE[Bsz*NCH*Dn];   // chunk-end local h
__device__ __align__(128) float g_sP[Bsz*NCH*Dn];   // chunk a-product
__device__ __align__(128) float g_hs[Bsz*NCH*Dn];   // chunk start h

__device__ __align__(128) __half g_b1_h[BTD];
__device__ __align__(128) __half g_i_h[BTD];
__device__ __align__(128) __half g_norm_h[BTD];
__device__ __align__(128) __half g_conv_h[BTD];
__device__ __align__(128) __half g_scan_h[BTD];     // chunk-local scan
__device__ __align__(128) __half g_pa_h[BTD];       // per-element a-product
__device__ __align__(128) __half g_prod_h[BTD];
__device__ __align__(128) __half g_n2_h[BTD];
__device__ __align__(128) __half g_act_h[BTH];

__device__ __align__(128) __half g_w1_h[Dn*Dn];
__device__ __align__(128) __half g_wa_h[Dn*Dn];
__device__ __align__(128) __half g_wx_h[Dn*Dn];
__device__ __align__(128) __half g_w2_h[Dn*Dn];
__device__ __align__(128) __half g_wo_h[Dn*Dn];              // Wout
__device__ __align__(128) __half g_wg_h[(long)Hn*Dn];
__device__ __align__(128) __half g_wu_h[(long)Hn*Dn];
__device__ __align__(128) __half g_wout2_h[(long)Dn*Hn];     // Wo

// ---------------- helpers ----------------
__device__ __forceinline__ uint32_t smem_u32(const void* p) {
    uint32_t a;
    asm("{ .reg .u64 t; cvta.to.shared.u64 t, %1; cvt.u32.u64 %0, t; }"
        : "=r"(a) : "l"(p));
    return a;
}
__device__ __forceinline__ float gelu_f(float x) {
    return 0.5f * x * (1.0f + erff(x * 0.70710678118654752440f));
}
__device__ __forceinline__ float sigm_f(float x) {
    return 1.0f / (1.0f + expf(-x));
}
__device__ __forceinline__ uint32_t pack2h(float a, float b) {
    __half2 t = __floats2half2_rn(a, b);
    return *reinterpret_cast<uint32_t*>(&t);
}
__device__ __forceinline__ void ldsm4(uint32_t addr, uint32_t r[4]) {
    asm volatile("ldmatrix.sync.aligned.m8n8.x4.shared.b16 {%0,%1,%2,%3}, [%4];"
                 : "=r"(r[0]), "=r"(r[1]), "=r"(r[2]), "=r"(r[3]) : "r"(addr));
}
__device__ __forceinline__ void mma16816(float c[4], const uint32_t a[4], const uint32_t b[2]) {
    asm volatile("mma.sync.aligned.m16n8k16.row.col.f32.f16.f16.f32 "
                 "{%0,%1,%2,%3}, {%4,%5,%6,%7}, {%8,%9}, {%0,%1,%2,%3};"
                 : "+f"(c[0]), "+f"(c[1]), "+f"(c[2]), "+f"(c[3])
                 : "r"(a[0]), "r"(a[1]), "r"(a[2]), "r"(a[3]), "r"(b[0]), "r"(b[1]));
}
__device__ __forceinline__ void cp16(uint32_t dst, const void* src) {
    asm volatile("cp.async.cg.shared.global [%0], [%1], 16;" :: "r"(dst), "l"(src));
}
#define CP_COMMIT() asm volatile("cp.async.commit_group;" ::: "memory")
#define CP_WAIT2()  asm volatile("cp.async.wait_group 2;" ::: "memory")

// ================= GEMM 256x128: C[M,N] = A[M,K] @ B[N,K]^T =================
// EPI: 0=none 1=sigmoid(v+bias[col]) 3=v+auxf
//      6=gelu(v)*(scan_local + pa*hs)   (scan fixup fused)
// HOUT: 1 -> fp16 out
template<int EPI, int HOUT>
__global__ void __launch_bounds__(256, 1)
gemm_mma(const __half* __restrict__ A, const __half* __restrict__ B,
         float* __restrict__ C, __half* __restrict__ Ch,
         const float* __restrict__ auxf, const __half* __restrict__ auxh,
         const __half* __restrict__ pa, const float* __restrict__ hs,
         const float* __restrict__ bias, int N, int K)
{
    extern __shared__ __align__(128) char smem[];
    const uint32_t sb = smem_u32(smem);
    const int tid = threadIdx.x;
    const int lane = tid & 31, wid = tid >> 5;
    const int wm = wid & 3;            // 4 warps along M (64 rows each)
    const int wn = wid >> 2;           // 2 warps along N (64 cols each)
    const long rowA = (long)blockIdx.y * 256;
    const long rowB = (long)blockIdx.x * 128;
    const int nk = K >> 5;             // BK = 32

    float acc[4][8][4];
    #pragma unroll
    for (int i = 0; i < 4; i++)
        #pragma unroll
        for (int n = 0; n < 8; n++)
            #pragma unroll
            for (int q = 0; q < 4; q++) acc[i][n][q] = 0.f;

    auto load_stage = [&](int s, int kt) {
        const uint32_t base = sb + s * S_STAGE;
        const int k0 = kt << 5;
        #pragma unroll
        for (int t = 0; t < 4; t++) {
            const int idx = tid + t * 256;
            const int r = idx >> 2, c = idx & 3;
            cp16(base + r * 80 + c * 16, A + (rowA + r) * (long)K + k0 + c * 8);
        }
        #pragma unroll
        for (int t = 0; t < 2; t++) {
            const int idx = tid + t * 256;
            const int r = idx >> 2, c = idx & 3;
            cp16(base + S_A_BYTES + r * 80 + c * 16, B + (rowB + r) * (long)K + k0 + c * 8);
        }
    };

    load_stage(0, 0); CP_COMMIT();
    load_stage(1, 1); CP_COMMIT();
    load_stage(2, 2); CP_COMMIT();

    for (int kt = 0; kt < nk; kt++) {
        CP_WAIT2();
        __syncthreads();
        if (kt + 3 < nk) load_stage((kt + 3) & 3, kt + 3);
        CP_COMMIT();

        const uint32_t base = sb + (kt & 3) * S_STAGE;
        #pragma unroll
        for (int kk = 0; kk < 2; kk++) {
            const uint32_t koff = (kk * 16 + (lane >> 4) * 8) * 2;
            uint32_t ah[4][4];
            #pragma unroll
            for (int i = 0; i < 4; i++) {
                const uint32_t off = (uint32_t)(wm * 64 + i * 16 + (lane & 15)) * 80 + koff;
                ldsm4(base + off, ah[i]);
            }
            uint32_t bh[8][2];
            #pragma unroll
            for (int j = 0; j < 4; j++) {
                const uint32_t off = (uint32_t)(wn * 64 + j * 16 + (lane & 15)) * 80 + koff;
                uint32_t t[4];
                ldsm4(base + S_A_BYTES + off, t);
                bh[2*j][0] = t[0]; bh[2*j][1] = t[2];
                bh[2*j+1][0] = t[1]; bh[2*j+1][1] = t[3];
            }
            #pragma unroll
            for (int i = 0; i < 4; i++)
                #pragma unroll
                for (int n = 0; n < 8; n++)
                    mma16816(acc[i][n], ah[i], bh[n]);
        }
    }

    const long r0 = rowA + wm * 64 + (lane >> 2);
    const long c0 = rowB + wn * 64 + (lane & 3) * 2;
    #pragma unroll
    for (int i = 0; i < 4; i++) {
        #pragma unroll
        for (int n = 0; n < 8; n++) {
            #pragma unroll
            for (int h = 0; h < 2; h++) {
                const long row = r0 + i * 16 + h * 8;
                const long col = c0 + n * 8;
                float v0 = acc[i][n][2*h + 0];
                float v1 = acc[i][n][2*h + 1];
                if (EPI == 1) {
                    v0 = sigm_f(v0 + bias[col]);
                    v1 = sigm_f(v1 + bias[col + 1]);
                } else if (EPI == 3) {
                    const float2 a2 = *(const float2*)(auxf + row * (long)N + col);
                    v0 += a2.x; v1 += a2.y;
                } else if (EPI == 6) {
                    const __half2 hl2 = *(const __half2*)(auxh + row * (long)N + col);
                    const __half2 pa2 = *(const __half2*)(pa + row * (long)N + col);
                    const int b = (int)(row >> 10);
                    const int t = (int)(row & (Tn - 1));
                    const int cch = t >> 8;              // t / CHL
                    const float2 hs2 = *(const float2*)(hs + ((long)(b * NCH + cch)) * Dn + col);
                    const float s0 = __half2float(hl2.x) + __half2float(pa2.x) * hs2.x;
                    const float s1 = __half2float(hl2.y) + __half2float(pa2.y) * hs2.y;
                    v0 = gelu_f(v0) * s0;
                    v1 = gelu_f(v1) * s1;
                }
                if (HOUT) {
                    *(uint32_t*)(Ch + row * (long)N + col) = pack2h(v0, v1);
                } else {
                    float2 o; o.x = v0; o.y = v1;
                    *(float2*)(C + row * (long)N + col) = o;
                }
            }
        }
    }
}

// ================= Dual MLP GEMM 128x128: Ch = gelu(A@Bg^T)*(A@Bu^T) ========
__global__ void __launch_bounds__(256, 1)
gemm_dual(const __half* __restrict__ A, const __half* __restrict__ Bg,
          const __half* __restrict__ Bu, __half* __restrict__ Ch,
          int N, int K)
{
    extern __shared__ __align__(128) char smem[];
    const uint32_t sb = smem_u32(smem);
    const int tid = threadIdx.x;
    const int lane = tid & 31, wid = tid >> 5;
    const int wm = wid & 1;
    const int wn = wid >> 1;
    const long rowA = (long)blockIdx.y * 128;
    const long rowB = (long)blockIdx.x * 128;
    const int nk = K >> 5;

    float accg[4][4][4], accu[4][4][4];
    #pragma unroll
    for (int i = 0; i < 4; i++)
        #pragma unroll
        for (int n = 0; n < 4; n++)
            #pragma unroll
            for (int q = 0; q < 4; q++) { accg[i][n][q] = 0.f; accu[i][n][q] = 0.f; }

    auto load_stage = [&](int s, int kt) {
        const uint32_t base = sb + s * D_STAGE;
        const int k0 = kt << 5;
        #pragma unroll
        for (int t = 0; t < 2; t++) {
            const int idx = tid + t * 256;
            const int r = idx >> 2, c = idx & 3;
            cp16(base + r * 80 + c * 16, A + (rowA + r) * (long)K + k0 + c * 8);
            cp16(base + 10240 + r * 80 + c * 16, Bg + (rowB + r) * (long)K + k0 + c * 8);
            cp16(base + 20480 + r * 80 + c * 16, Bu + (rowB + r) * (long)K + k0 + c * 8);
        }
    };

    load_stage(0, 0); CP_COMMIT();
    load_stage(1, 1); CP_COMMIT();
    load_stage(2, 2); CP_COMMIT();

    for (int kt = 0; kt < nk; kt++) {
        CP_WAIT2();
        __syncthreads();
        if (kt + 3 < nk) load_stage((kt + 3) & 3, kt + 3);
        CP_COMMIT();

        const uint32_t base = sb + (kt & 3) * D_STAGE;
        #pragma unroll
        for (int kk = 0; kk < 2; kk++) {
            const uint32_t koff = (kk * 16 + (lane >> 4) * 8) * 2;
            uint32_t ah[4][4];
            #pragma unroll
            for (int i = 0; i < 4; i++) {
                const uint32_t off = (uint32_t)(wm * 64 + i * 16 + (lane & 15)) * 80 + koff;
                ldsm4(base + off, ah[i]);
            }
            uint32_t bg[4][2], bu[4][2];
            #pragma unroll
            for (int j = 0; j < 2; j++) {
                const uint32_t off = (uint32_t)(wn * 32 + j * 16 + (lane & 15)) * 80 + koff;
                uint32_t t[4], u[4];
                ldsm4(base + 10240 + off, t);
                ldsm4(base + 20480 + off, u);
                bg[2*j][0] = t[0]; bg[2*j][1] = t[2];
                bg[2*j+1][0] = t[1]; bg[2*j+1][1] = t[3];
                bu[2*j][0] = u[0]; bu[2*j][1] = u[2];
                bu[2*j+1][0] = u[1]; bu[2*j+1][1] = u[3];
            }
            #pragma unroll
            for (int i = 0; i < 4; i++)
                #pragma unroll
                for (int n = 0; n < 4; n++) {
                    mma16816(accg[i][n], ah[i], bg[n]);
                    mma16816(accu[i][n], ah[i], bu[n]);
                }
        }
    }

    const long r0 = rowA + wm * 64 + (lane >> 2);
    const long c0 = rowB + wn * 32 + (lane & 3) * 2;
    #pragma unroll
    for (int i = 0; i < 4; i++) {
        #pragma unroll
        for (int n = 0; n < 4; n++) {
            #pragma unroll
            for (int h = 0; h < 2; h++) {
                const long row = r0 + i * 16 + h * 8;
                const long col = c0 + n * 8;
                const float v0 = gelu_f(accg[i][n][2*h + 0]) * accu[i][n][2*h + 0];
                const float v1 = gelu_f(accg[i][n][2*h + 1]) * accu[i][n][2*h + 1];
                *(uint32_t*)(Ch + row * (long)N + col) = pack2h(v0, v1);
            }
        }
    }
}

// ================= elementwise kernels =================
#define W1M (Dn*Dn/4)
#define WHM ((long)Hn*Dn/4)

// convert W1 + ls8 table (small, fast — lets gemm_b1 land at launch #4)
__global__ void wconv_w1_k(const float* __restrict__ W1, const float* __restrict__ ll,
                           __half* __restrict__ o1, float* __restrict__ ls8) {
    const long i = (long)blockIdx.x * 256 + threadIdx.x;
    if (i < W1M) {
        float4 v = *(const float4*)(W1 + i * 4);
        uint2 hv; hv.x = pack2h(v.x, v.y); hv.y = pack2h(v.z, v.w);
        *(uint2*)(o1 + i * 4) = hv;
    } else if (i < W1M + Dn / 4) {
        const long d = (i - W1M) * 4;
        #pragma unroll
        for (int j = 0; j < 4; j++)
            ls8[d + j] = -8.0f * log1pf(expf(-ll[d + j]));
    }
}

// convert remaining 7 weight matrices
__global__ void wconv_rest_k(const float* __restrict__ Wa, const float* __restrict__ Wx,
                             const float* __restrict__ W2, const float* __restrict__ Wout,
                             const float* __restrict__ Wg, const float* __restrict__ Wu,
                             const float* __restrict__ Wo,
                             __half* __restrict__ oa, __half* __restrict__ ox,
                             __half* __restrict__ o2, __half* __restrict__ oo,
                             __half* __restrict__ og, __half* __restrict__ ou,
                             __half* __restrict__ owo)
{
    const long i = (long)blockIdx.x * 256 + threadIdx.x;
    const long T4 = 4L * W1M, T5 = T4 + WHM, T6 = T5 + WHM, T7 = T6 + WHM;
    const float* src; __half* dst; long off;
    if (i < T4) {
        const long s = i / W1M; off = i - s * W1M;
        const float* srcs[4] = {Wa, Wx, W2, Wout};
        __half* dsts[4] = {oa, ox, o2, oo};
        src = srcs[s]; dst = dsts[s];
    } else if (i < T5) { src = Wg;  dst = og;  off = i - T4; }
    else if (i < T6)   { src = Wu;  dst = ou;  off = i - T5; }
    else if (i < T7)   { src = Wo;  dst = owo; off = i - T6; }
    else return;
    float4 v = *(const float4*)(src + off * 4);
    uint2 hv; hv.x = pack2h(v.x, v.y); hv.y = pack2h(v.z, v.w);
    *(uint2*)(dst + off * 4) = hv;
}

__global__ void rmsnorm_half_k(const float* __restrict__ x, const float* __restrict__ w,
                               __half* __restrict__ out) {
    const long row = blockIdx.x;
    const float* xr = x + row * (long)Dn;
    const int t4 = threadIdx.x * 4;
    float4 v = *(const float4*)(xr + t4);
    float ss = v.x*v.x + v.y*v.y + v.z*v.z + v.w*v.w;
    #pragma unroll
    for (int o = 16; o > 0; o >>= 1) ss += __shfl_xor_sync(0xffffffffu, ss, o);
    __shared__ float warps[8];
    if ((threadIdx.x & 31) == 0) warps[threadIdx.x >> 5] = ss;
    __syncthreads();
    float tot = 0.f;
    #pragma unroll
    for (int i = 0; i < 8; i++) tot += warps[i];
    const float inv = rsqrtf(tot * (1.0f / Dn) + 1.1920929e-07f);
    float4 wv = *(const float4*)(w + t4);
    uint2 hv;
    hv.x = pack2h(v.x*inv*wv.x, v.y*inv*wv.y);
    hv.y = pack2h(v.z*inv*wv.z, v.w*inv*wv.w);
    *(uint2*)(out + row * (long)Dn + t4) = hv;
}

// row-per-block conv; rows t>=Tn-3 also emit the fp32 new_conv_buf slice
__global__ void __launch_bounds__(256)
conv_row_k(const __half* __restrict__ b1h, const float* __restrict__ cbuf,
           const float* __restrict__ cw, const float* __restrict__ cb,
           __half* __restrict__ oh, float* __restrict__ out_cb) {
    const int row = blockIdx.x;              // 0..BT-1
    const int t = row & (Tn - 1);
    const int b = row >> 10;
    const int d4 = threadIdx.x * 4;
    const float4 w0 = *(const float4*)(cw + (d4 + 0) * CONVK);
    const float4 w1 = *(const float4*)(cw + (d4 + 1) * CONVK);
    const float4 w2 = *(const float4*)(cw + (d4 + 2) * CONVK);
    const float4 w3 = *(const float4*)(cw + (d4 + 3) * CONVK);
    const float4 bias = *(const float4*)(cb + d4);
    float acc0 = bias.x, acc1 = bias.y, acc2 = bias.z, acc3 = bias.w;
    float l0 = 0.f, l1 = 0.f, l2 = 0.f, l3 = 0.f;   // tap k=3 values (== b1[t])
    #pragma unroll
    for (int k = 0; k < CONVK; k++) {
        const int tt = t + k - (CONVK - 1);
        float s0, s1, s2, s3;
        if (tt >= 0) {
            const uint2 hv = *(const uint2*)(b1h + ((long)b * Tn + tt) * Dn + d4);
            const __half2 h0 = *(const __half2*)&hv.x;
            const __half2 h1 = *(const __half2*)&hv.y;
            s0 = __half2float(h0.x); s1 = __half2float(h0.y);
            s2 = __half2float(h1.x); s3 = __half2float(h1.y);
        } else {
            const float4 f = *(const float4*)(cbuf + ((long)b * (CONVK - 1) + (t + k)) * Dn + d4);
            s0 = f.x; s1 = f.y; s2 = f.z; s3 = f.w;
        }
        if (k == CONVK - 1) { l0 = s0; l1 = s1; l2 = s2; l3 = s3; }
        const float wk0 = (&w0.x)[k], wk1 = (&w1.x)[k], wk2 = (&w2.x)[k], wk3 = (&w3.x)[k];
        acc0 = fmaf(s0, wk0, acc0);
        acc1 = fmaf(s1, wk1, acc1);
        acc2 = fmaf(s2, wk2, acc2);
        acc3 = fmaf(s3, wk3, acc3);
    }
    uint2 hv; hv.x = pack2h(acc0, acc1); hv.y = pack2h(acc2, acc3);
    *(uint2*)(oh + (long)row * Dn + d4) = hv;
    if (t >= Tn - (CONVK - 1)) {
        float4 f; f.x = l0; f.y = l1; f.z = l2; f.w = l3;
        *(float4*)(out_cb + ((long)b * (CONVK - 1) + (t - (Tn - (CONVK - 1)))) * Dn + d4) = f;
    }
}

// scan pass 1: chunk-local scan (h_start=0) + cumulative a-product
__global__ void scan_p1_k(const float* __restrict__ r, const __half* __restrict__ ih,
                          const __half* __restrict__ convh, const float* __restrict__ ls8,
                          __half* __restrict__ outh, __half* __restrict__ pah,
                          float* __restrict__ sE, float* __restrict__ sP) {
    const int idx = blockIdx.x * 128 + threadIdx.x;   // 0..Bsz*NCH*Dn-1
    const int d = idx & (Dn - 1);
    const int c = (idx >> 10) & (NCH - 1);
    const int b = idx >> 12;
    const float l8 = ls8[d];
    const long base = ((long)b * Tn + c * CHL) * Dn + d;
    float h = 0.f, p = 1.f;
    float cr[4], ci[4], cc[4];
    #pragma unroll
    for (int j = 0; j < 4; j++) {
        const long o = base + (long)j * Dn;
        cr[j] = r[o]; ci[j] = __half2float(ih[o]); cc[j] = __half2float(convh[o]);
    }
    for (int t0 = 0; t0 < CHL; t0 += 4) {
        float nr[4], ni[4], nc[4];
        if (t0 + 4 < CHL) {
            #pragma unroll
            for (int j = 0; j < 4; j++) {
                const long o = base + (long)(t0 + 4 + j) * Dn;
                nr[j] = r[o]; ni[j] = __half2float(ih[o]); nc[j] = __half2float(convh[o]);
            }
        }
        #pragma unroll
        for (int j = 0; j < 4; j++) {
            const float a = expf(cr[j] * l8);
            const float gate = sqrtf(fmaxf((1.f - a) * (1.f + a), 1e-6f));
            h = fmaf(a, h, gate * ci[j] * cc[j]);
            p *= a;
            const long o = base + (long)(t0 + j) * Dn;
            outh[o] = __float2half_rn(h);
            pah[o] = __float2half_rn(p);
        }
        #pragma unroll
        for (int j = 0; j < 4; j++) { cr[j] = nr[j]; ci[j] = ni[j]; cc[j] = nc[j]; }
    }
    sE[idx] = h;
    sP[idx] = p;
}

// scan pass 2: combine chunk summaries -> h_start per chunk + final h
__global__ void scan_p2_k(const float* __restrict__ sE, const float* __restrict__ sP,
                          const float* __restrict__ h0, float* __restrict__ hs,
                          float* __restrict__ newh) {
    const int idx = blockIdx.x * 256 + threadIdx.x;   // 0..Bsz*Dn-1
    const int d = idx & (Dn - 1);
    const int b = idx >> 10;
    float h = h0[idx];
    #pragma unroll
    for (int c = 0; c < NCH; c++) {
        const long o = (long)(b * NCH + c) * Dn + d;
        hs[o] = h;
        h = sE[o] + sP[o] * h;
    }
    newh[idx] = h;
}

// ================= host side =================
extern "C" void kernel_launch(void* const* d_in, const int* in_sizes, int n_in,
                              void* d_out, int out_size) {
    const float* x_seq   = (const float*)d_in[0];
    const float* h0      = (const float*)d_in[1];
    const float* convbuf = (const float*)d_in[2];
    const float* norm1_w = (const float*)d_in[3];
    const float* W1      = (const float*)d_in[4];
    const float* conv_w  = (const float*)d_in[5];
    const float* conv_b  = (const float*)d_in[6];
    const float* Wa      = (const float*)d_in[7];
    const float* ba      = (const float*)d_in[8];
    const float* Wx      = (const float*)d_in[9];
    const float* bx      = (const float*)d_in[10];
    const float* log_lam = (const float*)d_in[11];
    const float* W2      = (const float*)d_in[12];
    const float* Wout    = (const float*)d_in[13];
    const float* norm2_w = (const float*)d_in[14];
    const float* Wg      = (const float*)d_in[15];
    const float* Wu      = (const float*)d_in[16];
    const float* Wo      = (const float*)d_in[17];

    float* out_x2 = (float*)d_out;
    float* out_h  = out_x2 + (long)BTD;
    float* out_cb = out_h + (long)Bsz * Dn;

    float *p_r, *p_x1, *p_ls8, *p_sE, *p_sP, *p_hs;
    cudaGetSymbolAddress((void**)&p_r, g_r);
    cudaGetSymbolAddress((void**)&p_x1, g_x1);
    cudaGetSymbolAddress((void**)&p_ls8, g_ls8);
    cudaGetSymbolAddress((void**)&p_sE, g_sE);
    cudaGetSymbolAddress((void**)&p_sP, g_sP);
    cudaGetSymbolAddress((void**)&p_hs, g_hs);

    __half *b1h, *ihh, *nh, *ch, *sch, *pah, *ph, *n2h, *acth;
    cudaGetSymbolAddress((void**)&b1h, g_b1_h);
    cudaGetSymbolAddress((void**)&ihh, g_i_h);
    cudaGetSymbolAddress((void**)&nh, g_norm_h);
    cudaGetSymbolAddress((void**)&ch, g_conv_h);
    cudaGetSymbolAddress((void**)&sch, g_scan_h);
    cudaGetSymbolAddress((void**)&pah, g_pa_h);
    cudaGetSymbolAddress((void**)&ph, g_prod_h);
    cudaGetSymbolAddress((void**)&n2h, g_n2_h);
    cudaGetSymbolAddress((void**)&acth, g_act_h);

    __half *w1h, *wah, *wxh, *w2h, *woh, *wgh, *wuh, *wo2h;
    cudaGetSymbolAddress((void**)&w1h, g_w1_h);
    cudaGetSymbolAddress((void**)&wah, g_wa_h);
    cudaGetSymbolAddress((void**)&wxh, g_wx_h);
    cudaGetSymbolAddress((void**)&w2h, g_w2_h);
    cudaGetSymbolAddress((void**)&woh, g_wo_h);
    cudaGetSymbolAddress((void**)&wgh, g_wg_h);
    cudaGetSymbolAddress((void**)&wuh, g_wu_h);
    cudaGetSymbolAddress((void**)&wo2h, g_wout2_h);

    cudaFuncSetAttribute(gemm_mma<0,1>, cudaFuncAttributeMaxDynamicSharedMemorySize, S_SMEM);
    cudaFuncSetAttribute(gemm_mma<1,0>, cudaFuncAttributeMaxDynamicSharedMemorySize, S_SMEM);
    cudaFuncSetAttribute(gemm_mma<1,1>, cudaFuncAttributeMaxDynamicSharedMemorySize, S_SMEM);
    cudaFuncSetAttribute(gemm_mma<3,0>, cudaFuncAttributeMaxDynamicSharedMemorySize, S_SMEM);
    cudaFuncSetAttribute(gemm_mma<6,1>, cudaFuncAttributeMaxDynamicSharedMemorySize, S_SMEM);
    cudaFuncSetAttribute(gemm_dual,     cudaFuncAttributeMaxDynamicSharedMemorySize, D_SMEM);

    const dim3 gD(Dn / 128, BT / 256);     // (8, 64)   single 256x128
    const dim3 gH(Hn / 128, BT / 128);     // (32, 128) dual mlp

    // 1. W1 + ls8 conversion (small — keeps gemm_b1 at launch #4)
    wconv_w1_k<<<(W1M + Dn/4 + 255)/256, 256>>>(W1, log_lam, w1h, p_ls8);
    // 2. remaining weights
    const long WR = 4L*W1M + 3L*WHM;
    wconv_rest_k<<<(int)((WR + 255)/256), 256>>>(Wa, Wx, W2, Wout, Wg, Wu, Wo,
                                                 wah, wxh, w2h, woh, wgh, wuh, wo2h);
    // 3. rmsnorm1 -> fp16
    rmsnorm_half_k<<<BT, 256>>>(x_seq, norm1_w, nh);
    // 4. b1 = normed @ W1^T -> fp16   (ncu slot #4)
    gemm_mma<0,1><<<gD, 256, S_SMEM>>>(nh, w1h, nullptr, b1h, nullptr, nullptr,
                                       nullptr, nullptr, nullptr, Dn, Dn);
    // 5. conv -> fp16 (+ new_conv_buf fused)
    conv_row_k<<<BT, 256>>>(b1h, convbuf, conv_w, conv_b, ch, out_cb);
    // 6/7. r (fp32), i (fp16) = sigmoid(conv @ {Wa,Wx}^T + bias)
    gemm_mma<1,0><<<gD, 256, S_SMEM>>>(ch, wah, p_r, nullptr, nullptr, nullptr,
                                       nullptr, nullptr, ba, Dn, Dn);
    gemm_mma<1,1><<<gD, 256, S_SMEM>>>(ch, wxh, nullptr, ihh, nullptr, nullptr,
                                       nullptr, nullptr, bx, Dn, Dn);
    // 8. scan pass 1 (chunk-local, 4x parallel)
    scan_p1_k<<<(Bsz * NCH * Dn) / 128, 128>>>(p_r, ihh, ch, p_ls8, sch, pah, p_sE, p_sP);
    // 9. scan pass 2 (combine summaries, h_start + new_h)
    scan_p2_k<<<(Bsz * Dn) / 256, 256>>>(p_sE, p_sP, h0, p_hs, out_h);
    // 10. prod = gelu(normed @ W2^T) * (scan_local + pa*hs) -> fp16  (fixup fused)
    gemm_mma<6,1><<<gD, 256, S_SMEM>>>(nh, w2h, nullptr, ph, nullptr, sch,
                                       pah, p_hs, nullptr, Dn, Dn);
    // 11. x1 = x_seq + prod @ Wout^T
    gemm_mma<3,0><<<gD, 256, S_SMEM>>>(ph, woh, p_x1, nullptr, x_seq, nullptr,
                                       nullptr, nullptr, nullptr, Dn, Dn);
    // 12. n2 = rmsnorm(x1) -> fp16
    rmsnorm_half_k<<<BT, 256>>>(p_x1, norm2_w, n2h);
    // 13. act = gelu(n2@Wg^T) * (n2@Wu^T) -> fp16
    gemm_dual<<<gH, 256, D_SMEM>>>(n2h, wgh, wuh, acth, Hn, Dn);
    // 14. x2 = x1 + act @ Wo^T
    gemm_mma<3,0><<<gD, 256, S_SMEM>>>(acth, wo2h, out_x2, nullptr, p_x1, nullptr,
                                       nullptr, nullptr, nullptr, Dn, Hn);
}

// round 13
// speedup vs baseline: 1.1017x; 1.0185x over previous
#include <cuda_runtime.h>
#include <cuda_fp16.h>
#include <math.h>
#include <stdint.h>

// ---------------- problem dims ----------------
#define Bsz 16
#define Tn  1024
#define Dn  1024
#define Hn  4096
#define BT  (Bsz*Tn)              // 16384
#define BTD (Bsz*Tn*Dn)           // 16777216
#define BTH (Bsz*Tn*Hn)           // 67108864
#define CONVK 4
#define NCH 4                     // scan chunks
#define CHL (Tn/NCH)              // 256

// ---------------- GEMM tile config ----------------
#define STAGES 4
#define S_A_BYTES 20480           // 256 rows x 80B
#define S_STAGE   30720
#define S_SMEM    (STAGES*S_STAGE)    // 122880
#define D_STAGE   30720               // dual: A,Bg,Bu 128x32 each
#define D_SMEM    (STAGES*D_STAGE)    // 122880

// ---------------- scratch (device globals) ----------------
__device__ __align__(128) float g_r[BTD];
__device__ __align__(128) float g_x1[BTD];
__device__ __align__(128) float g_ls8[Dn];          // 8*log_sigmoid(lambda)
__device__ __align__(128) float g_sE[Bsz*NCH*Dn];   // chunk-end local h
__device__ __align__(128) float g_sP[Bsz*NCH*Dn];   // chunk a-product
__device__ __align__(128) float g_hs[Bsz*NCH*Dn];   // chunk start h

__device__ __align__(128) __half g_b1_h[BTD];
__device__ __align__(128) __half g_i_h[BTD];
__device__ __align__(128) __half g_norm_h[BTD];
__device__ __align__(128) __half g_conv_h[BTD];
__device__ __align__(128) __half g_scan_h[BTD];     // chunk-local scan
__device__ __align__(128) __half g_pa_h[BTD];       // per-element a-product
__device__ __align__(128) __half g_prod_h[BTD];
__device__ __align__(128) __half g_n2_h[BTD];
__device__ __align__(128) __half g_act_h[BTH];

__device__ __align__(128) __half g_w1_h[Dn*Dn];
__device__ __align__(128) __half g_wa_h[Dn*Dn];
__device__ __align__(128) __half g_wx_h[Dn*Dn];
__device__ __align__(128) __half g_w2_h[Dn*Dn];
__device__ __align__(128) __half g_wo_h[Dn*Dn];              // Wout
__device__ __align__(128) __half g_wg_h[(long)Hn*Dn];
__device__ __align__(128) __half g_wu_h[(long)Hn*Dn];
__device__ __align__(128) __half g_wout2_h[(long)Dn*Hn];     // Wo

// ---------------- helpers ----------------
__device__ __forceinline__ uint32_t smem_u32(const void* p) {
    uint32_t a;
    asm("{ .reg .u64 t; cvta.to.shared.u64 t, %1; cvt.u32.u64 %0, t; }"
        : "=r"(a) : "l"(p));
    return a;
}
__device__ __forceinline__ float gelu_f(float x) {
    return 0.5f * x * (1.0f + erff(x * 0.70710678118654752440f));
}
__device__ __forceinline__ float sigm_f(float x) {
    return 1.0f / (1.0f + expf(-x));
}
__device__ __forceinline__ uint32_t pack2h(float a, float b) {
    __half2 t = __floats2half2_rn(a, b);
    return *reinterpret_cast<uint32_t*>(&t);
}
__device__ __forceinline__ void ldsm4(uint32_t addr, uint32_t r[4]) {
    asm volatile("ldmatrix.sync.aligned.m8n8.x4.shared.b16 {%0,%1,%2,%3}, [%4];"
                 : "=r"(r[0]), "=r"(r[1]), "=r"(r[2]), "=r"(r[3]) : "r"(addr));
}
__device__ __forceinline__ void mma16816(float c[4], const uint32_t a[4], const uint32_t b[2]) {
    asm volatile("mma.sync.aligned.m16n8k16.row.col.f32.f16.f16.f32 "
                 "{%0,%1,%2,%3}, {%4,%5,%6,%7}, {%8,%9}, {%0,%1,%2,%3};"
                 : "+f"(c[0]), "+f"(c[1]), "+f"(c[2]), "+f"(c[3])
                 : "r"(a[0]), "r"(a[1]), "r"(a[2]), "r"(a[3]), "r"(b[0]), "r"(b[1]));
}
__device__ __forceinline__ void cp16(uint32_t dst, const void* src) {
    asm volatile("cp.async.cg.shared.global [%0], [%1], 16;" :: "r"(dst), "l"(src));
}
#define CP_COMMIT() asm volatile("cp.async.commit_group;" ::: "memory")
#define CP_WAIT2()  asm volatile("cp.async.wait_group 2;" ::: "memory")

// register fragment load for the 256x128 kernels (A: wm*64 rows, B: wn*64 cols)
__device__ __forceinline__ void ld_ab_s(uint32_t base, int kk, int wm, int wn, int lane,
                                        uint32_t ah[4][4], uint32_t bh[8][2]) {
    const uint32_t koff = (kk * 16 + (lane >> 4) * 8) * 2;
    #pragma unroll
    for (int i = 0; i < 4; i++) {
        const uint32_t off = (uint32_t)(wm * 64 + i * 16 + (lane & 15)) * 80 + koff;
        ldsm4(base + off, ah[i]);
    }
    #pragma unroll
    for (int j = 0; j < 4; j++) {
        const uint32_t off = (uint32_t)(wn * 64 + j * 16 + (lane & 15)) * 80 + koff;
        uint32_t t[4];
        ldsm4(base + S_A_BYTES + off, t);
        bh[2*j][0] = t[0]; bh[2*j][1] = t[2];
        bh[2*j+1][0] = t[1]; bh[2*j+1][1] = t[3];
    }
}

// ================= GEMM 256x128: C[M,N] = A[M,K] @ B[N,K]^T =================
// EPI: 0=none 3=v+auxf 6=gelu(v)*(scan_local + pa*hs)
// HOUT: 1 -> fp16 out
template<int EPI, int HOUT>
__global__ void __launch_bounds__(256, 1)
gemm_mma(const __half* __restrict__ A, const __half* __restrict__ B,
         float* __restrict__ C, __half* __restrict__ Ch,
         const float* __restrict__ auxf, const __half* __restrict__ auxh,
         const __half* __restrict__ pa, const float* __restrict__ hs,
         int N, int K)
{
    extern __shared__ __align__(128) char smem[];
    const uint32_t sb = smem_u32(smem);
    const int tid = threadIdx.x;
    const int lane = tid & 31, wid = tid >> 5;
    const int wm = wid & 3;            // 4 warps along M (64 rows each)
    const int wn = wid >> 2;           // 2 warps along N (64 cols each)
    const long rowA = (long)blockIdx.y * 256;
    const long rowB = (long)blockIdx.x * 128;
    const int nk = K >> 5;             // BK = 32

    float acc[4][8][4];
    #pragma unroll
    for (int i = 0; i < 4; i++)
        #pragma unroll
        for (int n = 0; n < 8; n++)
            #pragma unroll
            for (int q = 0; q < 4; q++) acc[i][n][q] = 0.f;

    auto load_stage = [&](int s, int kt) {
        const uint32_t base = sb + s * S_STAGE;
        const int k0 = kt << 5;
        #pragma unroll
        for (int t = 0; t < 4; t++) {
            const int idx = tid + t * 256;
            const int r = idx >> 2, c = idx & 3;
            cp16(base + r * 80 + c * 16, A + (rowA + r) * (long)K + k0 + c * 8);
        }
        #pragma unroll
        for (int t = 0; t < 2; t++) {
            const int idx = tid + t * 256;
            const int r = idx >> 2, c = idx & 3;
            cp16(base + S_A_BYTES + r * 80 + c * 16, B + (rowB + r) * (long)K + k0 + c * 8);
        }
    };

    load_stage(0, 0); CP_COMMIT();
    load_stage(1, 1); CP_COMMIT();
    load_stage(2, 2); CP_COMMIT();

    for (int kt = 0; kt < nk; kt++) {
        CP_WAIT2();
        __syncthreads();
        if (kt + 3 < nk) load_stage((kt + 3) & 3, kt + 3);
        CP_COMMIT();

        const uint32_t base = sb + (kt & 3) * S_STAGE;
        uint32_t ah[2][4][4], bh[2][8][2];
        ld_ab_s(base, 0, wm, wn, lane, ah[0], bh[0]);
        #pragma unroll
        for (int kk = 0; kk < 2; kk++) {
            if (kk == 0) ld_ab_s(base, 1, wm, wn, lane, ah[1], bh[1]);
            #pragma unroll
            for (int i = 0; i < 4; i++)
                #pragma unroll
                for (int n = 0; n < 8; n++)
                    mma16816(acc[i][n], ah[kk][i], bh[kk][n]);
        }
    }

    const long r0 = rowA + wm * 64 + (lane >> 2);
    const long c0 = rowB + wn * 64 + (lane & 3) * 2;
    #pragma unroll
    for (int i = 0; i < 4; i++) {
        #pragma unroll
        for (int n = 0; n < 8; n++) {
            #pragma unroll
            for (int h = 0; h < 2; h++) {
                const long row = r0 + i * 16 + h * 8;
                const long col = c0 + n * 8;
                float v0 = acc[i][n][2*h + 0];
                float v1 = acc[i][n][2*h + 1];
                if (EPI == 3) {
                    const float2 a2 = *(const float2*)(auxf + row * (long)N + col);
                    v0 += a2.x; v1 += a2.y;
                } else if (EPI == 6) {
                    const __half2 hl2 = *(const __half2*)(auxh + row * (long)N + col);
                    const __half2 pa2 = *(const __half2*)(pa + row * (long)N + col);
                    const int b = (int)(row >> 10);
                    const int t = (int)(row & (Tn - 1));
                    const int cch = t >> 8;              // t / CHL
                    const float2 hs2 = *(const float2*)(hs + ((long)(b * NCH + cch)) * Dn + col);
                    const float s0 = __half2float(hl2.x) + __half2float(pa2.x) * hs2.x;
                    const float s1 = __half2float(hl2.y) + __half2float(pa2.y) * hs2.y;
                    v0 = gelu_f(v0) * s0;
                    v1 = gelu_f(v1) * s1;
                }
                if (HOUT) {
                    *(uint32_t*)(Ch + row * (long)N + col) = pack2h(v0, v1);
                } else {
                    float2 o; o.x = v0; o.y = v1;
                    *(float2*)(C + row * (long)N + col) = o;
                }
            }
        }
    }
}

// ================= merged r/i GEMM (blockIdx.z selects Wa->r / Wx->i) =======
__global__ void __launch_bounds__(256, 1)
gemm_ri(const __half* __restrict__ A, const __half* __restrict__ Wa,
        const __half* __restrict__ Wx, float* __restrict__ Rout,
        __half* __restrict__ Iout, const float* __restrict__ ba,
        const float* __restrict__ bx, int N, int K)
{
    extern __shared__ __align__(128) char smem[];
    const uint32_t sb = smem_u32(smem);
    const int tid = threadIdx.x;
    const int lane = tid & 31, wid = tid >> 5;
    const int wm = wid & 3;
    const int wn = wid >> 2;
    const long rowA = (long)blockIdx.y * 256;
    const long rowB = (long)blockIdx.x * 128;
    const int z = blockIdx.z;
    const __half* B = z ? Wx : Wa;
    const float* bias = z ? bx : ba;
    const int nk = K >> 5;

    float acc[4][8][4];
    #pragma unroll
    for (int i = 0; i < 4; i++)
        #pragma unroll
        for (int n = 0; n < 8; n++)
            #pragma unroll
            for (int q = 0; q < 4; q++) acc[i][n][q] = 0.f;

    auto load_stage = [&](int s, int kt) {
        const uint32_t base = sb + s * S_STAGE;
        const int k0 = kt << 5;
        #pragma unroll
        for (int t = 0; t < 4; t++) {
            const int idx = tid + t * 256;
            const int r = idx >> 2, c = idx & 3;
            cp16(base + r * 80 + c * 16, A + (rowA + r) * (long)K + k0 + c * 8);
        }
        #pragma unroll
        for (int t = 0; t < 2; t++) {
            const int idx = tid + t * 256;
            const int r = idx >> 2, c = idx & 3;
            cp16(base + S_A_BYTES + r * 80 + c * 16, B + (rowB + r) * (long)K + k0 + c * 8);
        }
    };

    load_stage(0, 0); CP_COMMIT();
    load_stage(1, 1); CP_COMMIT();
    load_stage(2, 2); CP_COMMIT();

    for (int kt = 0; kt < nk; kt++) {
        CP_WAIT2();
        __syncthreads();
        if (kt + 3 < nk) load_stage((kt + 3) & 3, kt + 3);
        CP_COMMIT();

        const uint32_t base = sb + (kt & 3) * S_STAGE;
        uint32_t ah[2][4][4], bh[2][8][2];
        ld_ab_s(base, 0, wm, wn, lane, ah[0], bh[0]);
        #pragma unroll
        for (int kk = 0; kk < 2; kk++) {
            if (kk == 0) ld_ab_s(base, 1, wm, wn, lane, ah[1], bh[1]);
            #pragma unroll
            for (int i = 0; i < 4; i++)
                #pragma unroll
                for (int n = 0; n < 8; n++)
                    mma16816(acc[i][n], ah[kk][i], bh[kk][n]);
        }
    }

    const long r0 = rowA + wm * 64 + (lane >> 2);
    const long c0 = rowB + wn * 64 + (lane & 3) * 2;
    #pragma unroll
    for (int i = 0; i < 4; i++) {
        #pragma unroll
        for (int n = 0; n < 8; n++) {
            #pragma unroll
            for (int h = 0; h < 2; h++) {
                const long row = r0 + i * 16 + h * 8;
                const long col = c0 + n * 8;
                const float v0 = sigm_f(acc[i][n][2*h + 0] + bias[col]);
                const float v1 = sigm_f(acc[i][n][2*h + 1] + bias[col + 1]);
                if (z) {
                    *(uint32_t*)(Iout + row * (long)N + col) = pack2h(v0, v1);
                } else {
                    float2 o; o.x = v0; o.y = v1;
                    *(float2*)(Rout + row * (long)N + col) = o;
                }
            }
        }
    }
}

// ================= Dual MLP GEMM 128x128: Ch = gelu(A@Bg^T)*(A@Bu^T) ========
__global__ void __launch_bounds__(256, 1)
gemm_dual(const __half* __restrict__ A, const __half* __restrict__ Bg,
          const __half* __restrict__ Bu, __half* __restrict__ Ch,
          int N, int K)
{
    extern __shared__ __align__(128) char smem[];
    const uint32_t sb = smem_u32(smem);
    const int tid = threadIdx.x;
    const int lane = tid & 31, wid = tid >> 5;
    const int wm = wid & 1;
    const int wn = wid >> 1;
    const long rowA = (long)blockIdx.y * 128;
    const long rowB = (long)blockIdx.x * 128;
    const int nk = K >> 5;

    float accg[4][4][4], accu[4][4][4];
    #pragma unroll
    for (int i = 0; i < 4; i++)
        #pragma unroll
        for (int n = 0; n < 4; n++)
            #pragma unroll
            for (int q = 0; q < 4; q++) { accg[i][n][q] = 0.f; accu[i][n][q] = 0.f; }

    auto load_stage = [&](int s, int kt) {
        const uint32_t base = sb + s * D_STAGE;
        const int k0 = kt << 5;
        #pragma unroll
        for (int t = 0; t < 2; t++) {
            const int idx = tid + t * 256;
            const int r = idx >> 2, c = idx & 3;
            cp16(base + r * 80 + c * 16, A + (rowA + r) * (long)K + k0 + c * 8);
            cp16(base + 10240 + r * 80 + c * 16, Bg + (rowB + r) * (long)K + k0 + c * 8);
            cp16(base + 20480 + r * 80 + c * 16, Bu + (rowB + r) * (long)K + k0 + c * 8);
        }
    };

    auto ld_frag = [&](uint32_t base, int kk, uint32_t ah[4][4],
                       uint32_t bg[4][2], uint32_t bu[4][2]) {
        const uint32_t koff = (kk * 16 + (lane >> 4) * 8) * 2;
        #pragma unroll
        for (int i = 0; i < 4; i++) {
            const uint32_t off = (uint32_t)(wm * 64 + i * 16 + (lane & 15)) * 80 + koff;
            ldsm4(base + off, ah[i]);
        }
        #pragma unroll
        for (int j = 0; j < 2; j++) {
            const uint32_t off = (uint32_t)(wn * 32 + j * 16 + (lane & 15)) * 80 + koff;
            uint32_t t[4], u[4];
            ldsm4(base + 10240 + off, t);
            ldsm4(base + 20480 + off, u);
            bg[2*j][0] = t[0]; bg[2*j][1] = t[2];
            bg[2*j+1][0] = t[1]; bg[2*j+1][1] = t[3];
            bu[2*j][0] = u[0]; bu[2*j][1] = u[2];
            bu[2*j+1][0] = u[1]; bu[2*j+1][1] = u[3];
        }
    };

    load_stage(0, 0); CP_COMMIT();
    load_stage(1, 1); CP_COMMIT();
    load_stage(2, 2); CP_COMMIT();

    for (int kt = 0; kt < nk; kt++) {
        CP_WAIT2();
        __syncthreads();
        if (kt + 3 < nk) load_stage((kt + 3) & 3, kt + 3);
        CP_COMMIT();

        const uint32_t base = sb + (kt & 3) * D_STAGE;
        uint32_t ah[2][4][4], bg[2][4][2], bu[2][4][2];
        ld_frag(base, 0, ah[0], bg[0], bu[0]);
        #pragma unroll
        for (int kk = 0; kk < 2; kk++) {
            if (kk == 0) ld_frag(base, 1, ah[1], bg[1], bu[1]);
            #pragma unroll
            for (int i = 0; i < 4; i++)
                #pragma unroll
                for (int n = 0; n < 4; n++) {
                    mma16816(accg[i][n], ah[kk][i], bg[kk][n]);
                    mma16816(accu[i][n], ah[kk][i], bu[kk][n]);
                }
        }
    }

    const long r0 = rowA + wm * 64 + (lane >> 2);
    const long c0 = rowB + wn * 32 + (lane & 3) * 2;
    #pragma unroll
    for (int i = 0; i < 4; i++) {
        #pragma unroll
        for (int n = 0; n < 4; n++) {
            #pragma unroll
            for (int h = 0; h < 2; h++) {
                const long row = r0 + i * 16 + h * 8;
                const long col = c0 + n * 8;
                const float v0 = gelu_f(accg[i][n][2*h + 0]) * accu[i][n][2*h + 0];
                const float v1 = gelu_f(accg[i][n][2*h + 1]) * accu[i][n][2*h + 1];
                *(uint32_t*)(Ch + row * (long)N + col) = pack2h(v0, v1);
            }
        }
    }
}

// ================= elementwise kernels =================
#define W1M (Dn*Dn/4)
#define WHM ((long)Hn*Dn/4)

// convert W1 + ls8 table (small, fast — keeps gemm_b1 at launch #4)
__global__ void wconv_w1_k(const float* __restrict__ W1, const float* __restrict__ ll,
                           __half* __restrict__ o1, float* __restrict__ ls8) {
    const long i = (long)blockIdx.x * 256 + threadIdx.x;
    if (i < W1M) {
        float4 v = *(const float4*)(W1 + i * 4);
        uint2 hv; hv.x = pack2h(v.x, v.y); hv.y = pack2h(v.z, v.w);
        *(uint2*)(o1 + i * 4) = hv;
    } else if (i < W1M + Dn / 4) {
        const long d = (i - W1M) * 4;
        #pragma unroll
        for (int j = 0; j < 4; j++)
            ls8[d + j] = -8.0f * log1pf(expf(-ll[d + j]));
    }
}

// convert remaining 7 weight matrices
__global__ void wconv_rest_k(const float* __restrict__ Wa, const float* __restrict__ Wx,
                             const float* __restrict__ W2, const float* __restrict__ Wout,
                             const float* __restrict__ Wg, const float* __restrict__ Wu,
                             const float* __restrict__ Wo,
                             __half* __restrict__ oa, __half* __restrict__ ox,
                             __half* __restrict__ o2, __half* __restrict__ oo,
                             __half* __restrict__ og, __half* __restrict__ ou,
                             __half* __restrict__ owo)
{
    const long i = (long)blockIdx.x * 256 + threadIdx.x;
    const long T4 = 4L * W1M, T5 = T4 + WHM, T6 = T5 + WHM, T7 = T6 + WHM;
    const float* src; __half* dst; long off;
    if (i < T4) {
        const long s = i / W1M; off = i - s * W1M;
        const float* srcs[4] = {Wa, Wx, W2, Wout};
        __half* dsts[4] = {oa, ox, o2, oo};
        src = srcs[s]; dst = dsts[s];
    } else if (i < T5) { src = Wg;  dst = og;  off = i - T4; }
    else if (i < T6)   { src = Wu;  dst = ou;  off = i - T5; }
    else if (i < T7)   { src = Wo;  dst = owo; off = i - T6; }
    else return;
    float4 v = *(const float4*)(src + off * 4);
    uint2 hv; hv.x = pack2h(v.x, v.y); hv.y = pack2h(v.z, v.w);
    *(uint2*)(dst + off * 4) = hv;
}

__global__ void rmsnorm_half_k(const float* __restrict__ x, const float* __restrict__ w,
                               __half* __restrict__ out) {
    const long row = blockIdx.x;
    const float* xr = x + row * (long)Dn;
    const int t4 = threadIdx.x * 4;
    float4 v = *(const float4*)(xr + t4);
    float ss = v.x*v.x + v.y*v.y + v.z*v.z + v.w*v.w;
    #pragma unroll
    for (int o = 16; o > 0; o >>= 1) ss += __shfl_xor_sync(0xffffffffu, ss, o);
    __shared__ float warps[8];
    if ((threadIdx.x & 31) == 0) warps[threadIdx.x >> 5] = ss;
    __syncthreads();
    float tot = 0.f;
    #pragma unroll
    for (int i = 0; i < 8; i++) tot += warps[i];
    const float inv = rsqrtf(tot * (1.0f / Dn) + 1.1920929e-07f);
    float4 wv = *(const float4*)(w + t4);
    uint2 hv;
    hv.x = pack2h(v.x*inv*wv.x, v.y*inv*wv.y);
    hv.y = pack2h(v.z*inv*wv.z, v.w*inv*wv.w);
    *(uint2*)(out + row * (long)Dn + t4) = hv;
}

// row-per-block conv; rows t>=Tn-3 also emit the fp32 new_conv_buf slice
__global__ void __launch_bounds__(256)
conv_row_k(const __half* __restrict__ b1h, const float* __restrict__ cbuf,
           const float* __restrict__ cw, const float* __restrict__ cb,
           __half* __restrict__ oh, float* __restrict__ out_cb) {
    const int row = blockIdx.x;              // 0..BT-1
    const int t = row & (Tn - 1);
    const int b = row >> 10;
    const int d4 = threadIdx.x * 4;
    const float4 w0 = *(const float4*)(cw + (d4 + 0) * CONVK);
    const float4 w1 = *(const float4*)(cw + (d4 + 1) * CONVK);
    const float4 w2 = *(const float4*)(cw + (d4 + 2) * CONVK);
    const float4 w3 = *(const float4*)(cw + (d4 + 3) * CONVK);
    const float4 bias = *(const float4*)(cb + d4);
    float acc0 = bias.x, acc1 = bias.y, acc2 = bias.z, acc3 = bias.w;
    float l0 = 0.f, l1 = 0.f, l2 = 0.f, l3 = 0.f;
    #pragma unroll
    for (int k = 0; k < CONVK; k++) {
        const int tt = t + k - (CONVK - 1);
        float s0, s1, s2, s3;
        if (tt >= 0) {
            const uint2 hv = *(const uint2*)(b1h + ((long)b * Tn + tt) * Dn + d4);
            const __half2 h0 = *(const __half2*)&hv.x;
            const __half2 h1 = *(const __half2*)&hv.y;
            s0 = __half2float(h0.x); s1 = __half2float(h0.y);
            s2 = __half2float(h1.x); s3 = __half2float(h1.y);
        } else {
            const float4 f = *(const float4*)(cbuf + ((long)b * (CONVK - 1) + (t + k)) * Dn + d4);
            s0 = f.x; s1 = f.y; s2 = f.z; s3 = f.w;
        }
        if (k == CONVK - 1) { l0 = s0; l1 = s1; l2 = s2; l3 = s3; }
        const float wk0 = (&w0.x)[k], wk1 = (&w1.x)[k], wk2 = (&w2.x)[k], wk3 = (&w3.x)[k];
        acc0 = fmaf(s0, wk0, acc0);
        acc1 = fmaf(s1, wk1, acc1);
        acc2 = fmaf(s2, wk2, acc2);
        acc3 = fmaf(s3, wk3, acc3);
    }
    uint2 hv; hv.x = pack2h(acc0, acc1); hv.y = pack2h(acc2, acc3);
    *(uint2*)(oh + (long)row * Dn + d4) = hv;
    if (t >= Tn - (CONVK - 1)) {
        float4 f; f.x = l0; f.y = l1; f.z = l2; f.w = l3;
        *(float4*)(out_cb + ((long)b * (CONVK - 1) + (t - (Tn - (CONVK - 1)))) * Dn + d4) = f;
    }
}

// scan pass 1: chunk-local scan (h_start=0) + cumulative a-product
__global__ void scan_p1_k(const float* __restrict__ r, const __half* __restrict__ ih,
                          const __half* __restrict__ convh, const float* __restrict__ ls8,
                          __half* __restrict__ outh, __half* __restrict__ pah,
                          float* __restrict__ sE, float* __restrict__ sP) {
    const int idx = blockIdx.x * 128 + threadIdx.x;   // 0..Bsz*NCH*Dn-1
    const int d = idx & (Dn - 1);
    const int c = (idx >> 10) & (NCH - 1);
    const int b = idx >> 12;
    const float l8 = ls8[d];
    const long base = ((long)b * Tn + c * CHL) * Dn + d;
    float h = 0.f, p = 1.f;
    float cr[4], ci[4], cc[4];
    #pragma unroll
    for (int j = 0; j < 4; j++) {
        const long o = base + (long)j * Dn;
        cr[j] = r[o]; ci[j] = __half2float(ih[o]); cc[j] = __half2float(convh[o]);
    }
    for (int t0 = 0; t0 < CHL; t0 += 4) {
        float nr[4], ni[4], nc[4];
        if (t0 + 4 < CHL) {
            #pragma unroll
            for (int j = 0; j < 4; j++) {
                const long o = base + (long)(t0 + 4 + j) * Dn;
                nr[j] = r[o]; ni[j] = __half2float(ih[o]); nc[j] = __half2float(convh[o]);
            }
        }
        #pragma unroll
        for (int j = 0; j < 4; j++) {
            const float a = expf(cr[j] * l8);
            const float gate = sqrtf(fmaxf((1.f - a) * (1.f + a), 1e-6f));
            h = fmaf(a, h, gate * ci[j] * cc[j]);
            p *= a;
            const long o = base + (long)(t0 + j) * Dn;
            outh[o] = __float2half_rn(h);
            pah[o] = __float2half_rn(p);
        }
        #pragma unroll
        for (int j = 0; j < 4; j++) { cr[j] = nr[j]; ci[j] = ni[j]; cc[j] = nc[j]; }
    }
    sE[idx] = h;
    sP[idx] = p;
}

// scan pass 2: combine chunk summaries -> h_start per chunk + final h
__global__ void scan_p2_k(const float* __restrict__ sE, const float* __restrict__ sP,
                          const float* __restrict__ h0, float* __restrict__ hs,
                          float* __restrict__ newh) {
    const int idx = blockIdx.x * 256 + threadIdx.x;   // 0..Bsz*Dn-1
    const int d = idx & (Dn - 1);
    const int b = idx >> 10;
    float h = h0[idx];
    #pragma unroll
    for (int c = 0; c < NCH; c++) {
        const long o = (long)(b * NCH + c) * Dn + d;
        hs[o] = h;
        h = sE[o] + sP[o] * h;
    }
    newh[idx] = h;
}

// ================= host side =================
extern "C" void kernel_launch(void* const* d_in, const int* in_sizes, int n_in,
                              void* d_out, int out_size) {
    const float* x_seq   = (const float*)d_in[0];
    const float* h0      = (const float*)d_in[1];
    const float* convbuf = (const float*)d_in[2];
    const float* norm1_w = (const float*)d_in[3];
    const float* W1      = (const float*)d_in[4];
    const float* conv_w  = (const float*)d_in[5];
    const float* conv_b  = (const float*)d_in[6];
    const float* Wa      = (const float*)d_in[7];
    const float* ba      = (const float*)d_in[8];
    const float* Wx      = (const float*)d_in[9];
    const float* bx      = (const float*)d_in[10];
    const float* log_lam = (const float*)d_in[11];
    const float* W2      = (const float*)d_in[12];
    const float* Wout    = (const float*)d_in[13];
    const float* norm2_w = (const float*)d_in[14];
    const float* Wg      = (const float*)d_in[15];
    const float* Wu      = (const float*)d_in[16];
    const float* Wo      = (const float*)d_in[17];

    float* out_x2 = (float*)d_out;
    float* out_h  = out_x2 + (long)BTD;
    float* out_cb = out_h + (long)Bsz * Dn;

    float *p_r, *p_x1, *p_ls8, *p_sE, *p_sP, *p_hs;
    cudaGetSymbolAddress((void**)&p_r, g_r);
    cudaGetSymbolAddress((void**)&p_x1, g_x1);
    cudaGetSymbolAddress((void**)&p_ls8, g_ls8);
    cudaGetSymbolAddress((void**)&p_sE, g_sE);
    cudaGetSymbolAddress((void**)&p_sP, g_sP);
    cudaGetSymbolAddress((void**)&p_hs, g_hs);

    __half *b1h, *ihh, *nh, *ch, *sch, *pah, *ph, *n2h, *acth;
    cudaGetSymbolAddress((void**)&b1h, g_b1_h);
    cudaGetSymbolAddress((void**)&ihh, g_i_h);
    cudaGetSymbolAddress((void**)&nh, g_norm_h);
    cudaGetSymbolAddress((void**)&ch, g_conv_h);
    cudaGetSymbolAddress((void**)&sch, g_scan_h);
    cudaGetSymbolAddress((void**)&pah, g_pa_h);
    cudaGetSymbolAddress((void**)&ph, g_prod_h);
    cudaGetSymbolAddress((void**)&n2h, g_n2_h);
    cudaGetSymbolAddress((void**)&acth, g_act_h);

    __half *w1h, *wah, *wxh, *w2h, *woh, *wgh, *wuh, *wo2h;
    cudaGetSymbolAddress((void**)&w1h, g_w1_h);
    cudaGetSymbolAddress((void**)&wah, g_wa_h);
    cudaGetSymbolAddress((void**)&wxh, g_wx_h);
    cudaGetSymbolAddress((void**)&w2h, g_w2_h);
    cudaGetSymbolAddress((void**)&woh, g_wo_h);
    cudaGetSymbolAddress((void**)&wgh, g_wg_h);
    cudaGetSymbolAddress((void**)&wuh, g_wu_h);
    cudaGetSymbolAddress((void**)&wo2h, g_wout2_h);

    cudaFuncSetAttribute(gemm_mma<0,1>, cudaFuncAttributeMaxDynamicSharedMemorySize, S_SMEM);
    cudaFuncSetAttribute(gemm_mma<3,0>, cudaFuncAttributeMaxDynamicSharedMemorySize, S_SMEM);
    cudaFuncSetAttribute(gemm_mma<6,1>, cudaFuncAttributeMaxDynamicSharedMemorySize, S_SMEM);
    cudaFuncSetAttribute(gemm_ri,       cudaFuncAttributeMaxDynamicSharedMemorySize, S_SMEM);
    cudaFuncSetAttribute(gemm_dual,     cudaFuncAttributeMaxDynamicSharedMemorySize, D_SMEM);

    const dim3 gD(Dn / 128, BT / 256);        // (8, 64)
    const dim3 gRI(Dn / 128, BT / 256, 2);    // (8, 64, 2) merged r/i
    const dim3 gH(Hn / 128, BT / 128);        // (32, 128) dual mlp

    // 1. W1 + ls8 conversion (small — keeps gemm_b1 at launch #4)
    wconv_w1_k<<<(W1M + Dn/4 + 255)/256, 256>>>(W1, log_lam, w1h, p_ls8);
    // 2. remaining weights
    const long WR = 4L*W1M + 3L*WHM;
    wconv_rest_k<<<(int)((WR + 255)/256), 256>>>(Wa, Wx, W2, Wout, Wg, Wu, Wo,
                                                 wah, wxh, w2h, woh, wgh, wuh, wo2h);
    // 3. rmsnorm1 -> fp16
    rmsnorm_half_k<<<BT, 256>>>(x_seq, norm1_w, nh);
    // 4. b1 = normed @ W1^T -> fp16   (ncu slot #4)
    gemm_mma<0,1><<<gD, 256, S_SMEM>>>(nh, w1h, nullptr, b1h, nullptr, nullptr,
                                       nullptr, nullptr, Dn, Dn);
    // 5. conv -> fp16 (+ new_conv_buf fused)
    conv_row_k<<<BT, 256>>>(b1h, convbuf, conv_w, conv_b, ch, out_cb);
    // 6. merged r (fp32) + i (fp16) GEMM
    gemm_ri<<<gRI, 256, S_SMEM>>>(ch, wah, wxh, p_r, ihh, ba, bx, Dn, Dn);
    // 7. scan pass 1 (chunk-local, 4x parallel)
    scan_p1_k<<<(Bsz * NCH * Dn) / 128, 128>>>(p_r, ihh, ch, p_ls8, sch, pah, p_sE, p_sP);
    // 8. scan pass 2 (combine summaries)
    scan_p2_k<<<(Bsz * Dn) / 256, 256>>>(p_sE, p_sP, h0, p_hs, out_h);
    // 9. prod = gelu(normed @ W2^T) * (scan_local + pa*hs) -> fp16
    gemm_mma<6,1><<<gD, 256, S_SMEM>>>(nh, w2h, nullptr, ph, nullptr, sch,
                                       pah, p_hs, Dn, Dn);
    // 10. x1 = x_seq + prod @ Wout^T
    gemm_mma<3,0><<<gD, 256, S_SMEM>>>(ph, woh, p_x1, nullptr, x_seq, nullptr,
                                       nullptr, nullptr, Dn, Dn);
    // 11. n2 = rmsnorm(x1) -> fp16
    rmsnorm_half_k<<<BT, 256>>>(p_x1, norm2_w, n2h);
    // 12. act = gelu(n2@Wg^T) * (n2@Wu^T) -> fp16
    gemm_dual<<<gH, 256, D_SMEM>>>(n2h, wgh, wuh, acth, Hn, Dn);
    // 13. x2 = x1 + act @ Wo^T
    gemm_mma<3,0><<<gD, 256, S_SMEM>>>(acth, wo2h, out_x2, nullptr, p_x1, nullptr,
                                       nullptr, nullptr, Dn, Hn);
}

// round 14
// speedup vs baseline: 1.1598x; 1.0528x over previous
#include <cuda_runtime.h>
#include <cuda_fp16.h>
#include <math.h>
#include <stdint.h>

// ---------------- problem dims ----------------
#define Bsz 16
#define Tn  1024
#define Dn  1024
#define Hn  4096
#define BT  (Bsz*Tn)              // 16384
#define BTD (Bsz*Tn*Dn)           // 16777216
#define BTH (Bsz*Tn*Hn)           // 67108864
#define CONVK 4
#define NCH 4                     // scan chunks
#define CHL (Tn/NCH)              // 256

// ---------------- GEMM tile config ----------------
#define STAGES 4
#define S_A_BYTES 20480           // 256 rows x 80B
#define S_STAGE   30720
#define S_SMEM    (STAGES*S_STAGE)    // 122880
#define D_STAGE   30720               // dual: A,Bg,Bu 128x32 each
#define D_SMEM    (STAGES*D_STAGE)    // 122880

// ---------------- scratch (device globals) ----------------
__device__ __align__(128) float g_r[BTD];
__device__ __align__(128) float g_x1[BTD];
__device__ __align__(128) float g_ls8[Dn];          // 8*log_sigmoid(lambda)
__device__ __align__(128) float g_sE[Bsz*NCH*Dn];   // chunk-end local h
__device__ __align__(128) float g_sP[Bsz*NCH*Dn];   // chunk a-product
__device__ __align__(128) float g_hs[Bsz*NCH*Dn];   // chunk start h

__device__ __align__(128) __half g_b1_h[BTD];
__device__ __align__(128) __half g_i_h[BTD];
__device__ __align__(128) __half g_norm_h[BTD];
__device__ __align__(128) __half g_conv_h[BTD];
__device__ __align__(128) __half g_scan_h[BTD];     // chunk-local scan
__device__ __align__(128) __half g_pa_h[BTD];       // per-element a-product
__device__ __align__(128) __half g_prod_h[BTD];
__device__ __align__(128) __half g_n2_h[BTD];
__device__ __align__(128) __half g_act_h[BTH];

__device__ __align__(128) __half g_w1_h[Dn*Dn];
__device__ __align__(128) __half g_wa_h[Dn*Dn];
__device__ __align__(128) __half g_wx_h[Dn*Dn];
__device__ __align__(128) __half g_w2_h[Dn*Dn];
__device__ __align__(128) __half g_wo_h[Dn*Dn];              // Wout
__device__ __align__(128) __half g_wg_h[(long)Hn*Dn];
__device__ __align__(128) __half g_wu_h[(long)Hn*Dn];
__device__ __align__(128) __half g_wout2_h[(long)Dn*Hn];     // Wo

// ---------------- helpers ----------------
__device__ __forceinline__ uint32_t smem_u32(const void* p) {
    uint32_t a;
    asm("{ .reg .u64 t; cvta.to.shared.u64 t, %1; cvt.u32.u64 %0, t; }"
        : "=r"(a) : "l"(p));
    return a;
}
__device__ __forceinline__ float gelu_f(float x) {
    return 0.5f * x * (1.0f + erff(x * 0.70710678118654752440f));
}
__device__ __forceinline__ float sigm_f(float x) {
    return 1.0f / (1.0f + expf(-x));
}
__device__ __forceinline__ uint32_t pack2h(float a, float b) {
    __half2 t = __floats2half2_rn(a, b);
    return *reinterpret_cast<uint32_t*>(&t);
}
__device__ __forceinline__ void ldsm4(uint32_t addr, uint32_t r[4]) {
    asm volatile("ldmatrix.sync.aligned.m8n8.x4.shared.b16 {%0,%1,%2,%3}, [%4];"
                 : "=r"(r[0]), "=r"(r[1]), "=r"(r[2]), "=r"(r[3]) : "r"(addr));
}
__device__ __forceinline__ void mma16816(float c[4], const uint32_t a[4], const uint32_t b[2]) {
    asm volatile("mma.sync.aligned.m16n8k16.row.col.f32.f16.f16.f32 "
                 "{%0,%1,%2,%3}, {%4,%5,%6,%7}, {%8,%9}, {%0,%1,%2,%3};"
                 : "+f"(c[0]), "+f"(c[1]), "+f"(c[2]), "+f"(c[3])
                 : "r"(a[0]), "r"(a[1]), "r"(a[2]), "r"(a[3]), "r"(b[0]), "r"(b[1]));
}
__device__ __forceinline__ void cp16(uint32_t dst, const void* src) {
    asm volatile("cp.async.cg.shared.global [%0], [%1], 16;" :: "r"(dst), "l"(src));
}
#define CP_COMMIT() asm volatile("cp.async.commit_group;" ::: "memory")
#define CP_WAIT2()  asm volatile("cp.async.wait_group 2;" ::: "memory")

// fragment load: A warp tile 64 rows, B warp tile 32 cols
__device__ __forceinline__ void ld_ab_s(uint32_t base, int kk, int wm, int wn, int lane,
                                        uint32_t ah[4][4], uint32_t bh[4][2]) {
    const uint32_t koff = (kk * 16 + (lane >> 4) * 8) * 2;
    #pragma unroll
    for (int i = 0; i < 4; i++) {
        const uint32_t off = (uint32_t)(wm * 64 + i * 16 + (lane & 15)) * 80 + koff;
        ldsm4(base + off, ah[i]);
    }
    #pragma unroll
    for (int j = 0; j < 2; j++) {
        const uint32_t off = (uint32_t)(wn * 32 + j * 16 + (lane & 15)) * 80 + koff;
        uint32_t t[4];
        ldsm4(base + S_A_BYTES + off, t);
        bh[2*j][0] = t[0]; bh[2*j][1] = t[2];
        bh[2*j+1][0] = t[1]; bh[2*j+1][1] = t[3];
    }
}

// ================= GEMM 256x128, 512 threads (16 warps, 64x32 warp tile) ====
// EPI: 0=none 3=v+auxf 6=gelu(v)*(scan_local + pa*hs) ; HOUT: 1 -> fp16 out
template<int EPI, int HOUT>
__global__ void __launch_bounds__(512, 1)
gemm_mma(const __half* __restrict__ A, const __half* __restrict__ B,
         float* __restrict__ C, __half* __restrict__ Ch,
         const float* __restrict__ auxf, const __half* __restrict__ auxh,
         const __half* __restrict__ pa, const float* __restrict__ hs,
         int N, int K)
{
    extern __shared__ __align__(128) char smem[];
    const uint32_t sb = smem_u32(smem);
    const int tid = threadIdx.x;
    const int lane = tid & 31, wid = tid >> 5;
    const int wm = wid & 3;            // 4 warps along M (64 rows each)
    const int wn = wid >> 2;           // 4 warps along N (32 cols each)
    const long rowA = (long)blockIdx.y * 256;
    const long rowB = (long)blockIdx.x * 128;
    const int nk = K >> 5;             // BK = 32

    float acc[4][4][4];
    #pragma unroll
    for (int i = 0; i < 4; i++)
        #pragma unroll
        for (int n = 0; n < 4; n++)
            #pragma unroll
            for (int q = 0; q < 4; q++) acc[i][n][q] = 0.f;

    auto load_stage = [&](int s, int kt) {
        const uint32_t base = sb + s * S_STAGE;
        const int k0 = kt << 5;
        #pragma unroll
        for (int t = 0; t < 2; t++) {
            const int idx = tid + t * 512;
            const int r = idx >> 2, c = idx & 3;
            cp16(base + r * 80 + c * 16, A + (rowA + r) * (long)K + k0 + c * 8);
        }
        {
            const int r = tid >> 2, c = tid & 3;
            cp16(base + S_A_BYTES + r * 80 + c * 16, B + (rowB + r) * (long)K + k0 + c * 8);
        }
    };

    load_stage(0, 0); CP_COMMIT();
    load_stage(1, 1); CP_COMMIT();
    load_stage(2, 2); CP_COMMIT();

    for (int kt = 0; kt < nk; kt++) {
        CP_WAIT2();
        __syncthreads();
        if (kt + 3 < nk) load_stage((kt + 3) & 3, kt + 3);
        CP_COMMIT();

        const uint32_t base = sb + (kt & 3) * S_STAGE;
        #pragma unroll
        for (int kk = 0; kk < 2; kk++) {
            uint32_t ah[4][4], bh[4][2];
            ld_ab_s(base, kk, wm, wn, lane, ah, bh);
            #pragma unroll
            for (int i = 0; i < 4; i++)
                #pragma unroll
                for (int n = 0; n < 4; n++)
                    mma16816(acc[i][n], ah[i], bh[n]);
        }
    }

    const long r0 = rowA + wm * 64 + (lane >> 2);
    const long c0 = rowB + wn * 32 + (lane & 3) * 2;
    #pragma unroll
    for (int i = 0; i < 4; i++) {
        #pragma unroll
        for (int n = 0; n < 4; n++) {
            #pragma unroll
            for (int h = 0; h < 2; h++) {
                const long row = r0 + i * 16 + h * 8;
                const long col = c0 + n * 8;
                float v0 = acc[i][n][2*h + 0];
                float v1 = acc[i][n][2*h + 1];
                if (EPI == 3) {
                    const float2 a2 = *(const float2*)(auxf + row * (long)N + col);
                    v0 += a2.x; v1 += a2.y;
                } else if (EPI == 6) {
                    const __half2 hl2 = *(const __half2*)(auxh + row * (long)N + col);
                    const __half2 pa2 = *(const __half2*)(pa + row * (long)N + col);
                    const int b = (int)(row >> 10);
                    const int t = (int)(row & (Tn - 1));
                    const int cch = t >> 8;
                    const float2 hs2 = *(const float2*)(hs + ((long)(b * NCH + cch)) * Dn + col);
                    const float s0 = __half2float(hl2.x) + __half2float(pa2.x) * hs2.x;
                    const float s1 = __half2float(hl2.y) + __half2float(pa2.y) * hs2.y;
                    v0 = gelu_f(v0) * s0;
                    v1 = gelu_f(v1) * s1;
                }
                if (HOUT) {
                    *(uint32_t*)(Ch + row * (long)N + col) = pack2h(v0, v1);
                } else {
                    float2 o; o.x = v0; o.y = v1;
                    *(float2*)(C + row * (long)N + col) = o;
                }
            }
        }
    }
}

// ================= merged r/i GEMM (blockIdx.z selects Wa->r / Wx->i) =======
__global__ void __launch_bounds__(512, 1)
gemm_ri(const __half* __restrict__ A, const __half* __restrict__ Wa,
        const __half* __restrict__ Wx, float* __restrict__ Rout,
        __half* __restrict__ Iout, const float* __restrict__ ba,
        const float* __restrict__ bx, int N, int K)
{
    extern __shared__ __align__(128) char smem[];
    const uint32_t sb = smem_u32(smem);
    const int tid = threadIdx.x;
    const int lane = tid & 31, wid = tid >> 5;
    const int wm = wid & 3;
    const int wn = wid >> 2;
    const long rowA = (long)blockIdx.y * 256;
    const long rowB = (long)blockIdx.x * 128;
    const int z = blockIdx.z;
    const __half* B = z ? Wx : Wa;
    const float* bias = z ? bx : ba;
    const int nk = K >> 5;

    float acc[4][4][4];
    #pragma unroll
    for (int i = 0; i < 4; i++)
        #pragma unroll
        for (int n = 0; n < 4; n++)
            #pragma unroll
            for (int q = 0; q < 4; q++) acc[i][n][q] = 0.f;

    auto load_stage = [&](int s, int kt) {
        const uint32_t base = sb + s * S_STAGE;
        const int k0 = kt << 5;
        #pragma unroll
        for (int t = 0; t < 2; t++) {
            const int idx = tid + t * 512;
            const int r = idx >> 2, c = idx & 3;
            cp16(base + r * 80 + c * 16, A + (rowA + r) * (long)K + k0 + c * 8);
        }
        {
            const int r = tid >> 2, c = tid & 3;
            cp16(base + S_A_BYTES + r * 80 + c * 16, B + (rowB + r) * (long)K + k0 + c * 8);
        }
    };

    load_stage(0, 0); CP_COMMIT();
    load_stage(1, 1); CP_COMMIT();
    load_stage(2, 2); CP_COMMIT();

    for (int kt = 0; kt < nk; kt++) {
        CP_WAIT2();
        __syncthreads();
        if (kt + 3 < nk) load_stage((kt + 3) & 3, kt + 3);
        CP_COMMIT();

        const uint32_t base = sb + (kt & 3) * S_STAGE;
        #pragma unroll
        for (int kk = 0; kk < 2; kk++) {
            uint32_t ah[4][4], bh[4][2];
            ld_ab_s(base, kk, wm, wn, lane, ah, bh);
            #pragma unroll
            for (int i = 0; i < 4; i++)
                #pragma unroll
                for (int n = 0; n < 4; n++)
                    mma16816(acc[i][n], ah[i], bh[n]);
        }
    }

    const long r0 = rowA + wm * 64 + (lane >> 2);
    const long c0 = rowB + wn * 32 + (lane & 3) * 2;
    #pragma unroll
    for (int i = 0; i < 4; i++) {
        #pragma unroll
        for (int n = 0; n < 4; n++) {
            #pragma unroll
            for (int h = 0; h < 2; h++) {
                const long row = r0 + i * 16 + h * 8;
                const long col = c0 + n * 8;
                const float v0 = sigm_f(acc[i][n][2*h + 0] + bias[col]);
                const float v1 = sigm_f(acc[i][n][2*h + 1] + bias[col + 1]);
                if (z) {
                    *(uint32_t*)(Iout + row * (long)N + col) = pack2h(v0, v1);
                } else {
                    float2 o; o.x = v0; o.y = v1;
                    *(float2*)(Rout + row * (long)N + col) = o;
                }
            }
        }
    }
}

// ============ Dual MLP GEMM 128x128, 512 threads (32x32 warp tile) ==========
__global__ void __launch_bounds__(512, 1)
gemm_dual(const __half* __restrict__ A, const __half* __restrict__ Bg,
          const __half* __restrict__ Bu, __half* __restrict__ Ch,
          int N, int K)
{
    extern __shared__ __align__(128) char smem[];
    const uint32_t sb = smem_u32(smem);
    const int tid = threadIdx.x;
    const int lane = tid & 31, wid = tid >> 5;
    const int wm = wid & 3;            // 4 warps along M (32 rows each)
    const int wn = wid >> 2;           // 4 warps along N (32 cols each)
    const long rowA = (long)blockIdx.y * 128;
    const long rowB = (long)blockIdx.x * 128;
    const int nk = K >> 5;

    float accg[2][4][4], accu[2][4][4];
    #pragma unroll
    for (int i = 0; i < 2; i++)
        #pragma unroll
        for (int n = 0; n < 4; n++)
            #pragma unroll
            for (int q = 0; q < 4; q++) { accg[i][n][q] = 0.f; accu[i][n][q] = 0.f; }

    auto load_stage = [&](int s, int kt) {
        const uint32_t base = sb + s * D_STAGE;
        const int k0 = kt << 5;
        const int r = tid >> 2, c = tid & 3;
        cp16(base + r * 80 + c * 16, A + (rowA + r) * (long)K + k0 + c * 8);
        cp16(base + 10240 + r * 80 + c * 16, Bg + (rowB + r) * (long)K + k0 + c * 8);
        cp16(base + 20480 + r * 80 + c * 16, Bu + (rowB + r) * (long)K + k0 + c * 8);
    };

    load_stage(0, 0); CP_COMMIT();
    load_stage(1, 1); CP_COMMIT();
    load_stage(2, 2); CP_COMMIT();

    for (int kt = 0; kt < nk; kt++) {
        CP_WAIT2();
        __syncthreads();
        if (kt + 3 < nk) load_stage((kt + 3) & 3, kt + 3);
        CP_COMMIT();

        const uint32_t base = sb + (kt & 3) * D_STAGE;
        #pragma unroll
        for (int kk = 0; kk < 2; kk++) {
            const uint32_t koff = (kk * 16 + (lane >> 4) * 8) * 2;
            uint32_t ah[2][4];
            #pragma unroll
            for (int i = 0; i < 2; i++) {
                const uint32_t off = (uint32_t)(wm * 32 + i * 16 + (lane & 15)) * 80 + koff;
                ldsm4(base + off, ah[i]);
            }
            uint32_t bg[4][2], bu[4][2];
            #pragma unroll
            for (int j = 0; j < 2; j++) {
                const uint32_t off = (uint32_t)(wn * 32 + j * 16 + (lane & 15)) * 80 + koff;
                uint32_t t[4], u[4];
                ldsm4(base + 10240 + off, t);
                ldsm4(base + 20480 + off, u);
                bg[2*j][0] = t[0]; bg[2*j][1] = t[2];
                bg[2*j+1][0] = t[1]; bg[2*j+1][1] = t[3];
                bu[2*j][0] = u[0]; bu[2*j][1] = u[2];
                bu[2*j+1][0] = u[1]; bu[2*j+1][1] = u[3];
            }
            #pragma unroll
            for (int i = 0; i < 2; i++)
                #pragma unroll
                for (int n = 0; n < 4; n++) {
                    mma16816(accg[i][n], ah[i], bg[n]);
                    mma16816(accu[i][n], ah[i], bu[n]);
                }
        }
    }

    const long r0 = rowA + wm * 32 + (lane >> 2);
    const long c0 = rowB + wn * 32 + (lane & 3) * 2;
    #pragma unroll
    for (int i = 0; i < 2; i++) {
        #pragma unroll
        for (int n = 0; n < 4; n++) {
            #pragma unroll
            for (int h = 0; h < 2; h++) {
                const long row = r0 + i * 16 + h * 8;
                const long col = c0 + n * 8;
                const float v0 = gelu_f(accg[i][n][2*h + 0]) * accu[i][n][2*h + 0];
                const float v1 = gelu_f(accg[i][n][2*h + 1]) * accu[i][n][2*h + 1];
                *(uint32_t*)(Ch + row * (long)N + col) = pack2h(v0, v1);
            }
        }
    }
}

// ================= elementwise kernels =================
#define W1M (Dn*Dn/4)
#define WHM ((long)Hn*Dn/4)

__global__ void wconv_w1_k(const float* __restrict__ W1, const float* __restrict__ ll,
                           __half* __restrict__ o1, float* __restrict__ ls8) {
    const long i = (long)blockIdx.x * 256 + threadIdx.x;
    if (i < W1M) {
        float4 v = *(const float4*)(W1 + i * 4);
        uint2 hv; hv.x = pack2h(v.x, v.y); hv.y = pack2h(v.z, v.w);
        *(uint2*)(o1 + i * 4) = hv;
    } else if (i < W1M + Dn / 4) {
        const long d = (i - W1M) * 4;
        #pragma unroll
        for (int j = 0; j < 4; j++)
            ls8[d + j] = -8.0f * log1pf(expf(-ll[d + j]));
    }
}

__global__ void wconv_rest_k(const float* __restrict__ Wa, const float* __restrict__ Wx,
                             const float* __restrict__ W2, const float* __restrict__ Wout,
                             const float* __restrict__ Wg, const float* __restrict__ Wu,
                             const float* __restrict__ Wo,
                             __half* __restrict__ oa, __half* __restrict__ ox,
                             __half* __restrict__ o2, __half* __restrict__ oo,
                             __half* __restrict__ og, __half* __restrict__ ou,
                             __half* __restrict__ owo)
{
    const long i = (long)blockIdx.x * 256 + threadIdx.x;
    const long T4 = 4L * W1M, T5 = T4 + WHM, T6 = T5 + WHM, T7 = T6 + WHM;
    const float* src; __half* dst; long off;
    if (i < T4) {
        const long s = i / W1M; off = i - s * W1M;
        const float* srcs[4] = {Wa, Wx, W2, Wout};
        __half* dsts[4] = {oa, ox, o2, oo};
        src = srcs[s]; dst = dsts[s];
    } else if (i < T5) { src = Wg;  dst = og;  off = i - T4; }
    else if (i < T6)   { src = Wu;  dst = ou;  off = i - T5; }
    else if (i < T7)   { src = Wo;  dst = owo; off = i - T6; }
    else return;
    float4 v = *(const float4*)(src + off * 4);
    uint2 hv; hv.x = pack2h(v.x, v.y); hv.y = pack2h(v.z, v.w);
    *(uint2*)(dst + off * 4) = hv;
}

__global__ void rmsnorm_half_k(const float* __restrict__ x, const float* __restrict__ w,
                               __half* __restrict__ out) {
    const long row = blockIdx.x;
    const float* xr = x + row * (long)Dn;
    const int t4 = threadIdx.x * 4;
    float4 v = *(const float4*)(xr + t4);
    float ss = v.x*v.x + v.y*v.y + v.z*v.z + v.w*v.w;
    #pragma unroll
    for (int o = 16; o > 0; o >>= 1) ss += __shfl_xor_sync(0xffffffffu, ss, o);
    __shared__ float warps[8];
    if ((threadIdx.x & 31) == 0) warps[threadIdx.x >> 5] = ss;
    __syncthreads();
    float tot = 0.f;
    #pragma unroll
    for (int i = 0; i < 8; i++) tot += warps[i];
    const float inv = rsqrtf(tot * (1.0f / Dn) + 1.1920929e-07f);
    float4 wv = *(const float4*)(w + t4);
    uint2 hv;
    hv.x = pack2h(v.x*inv*wv.x, v.y*inv*wv.y);
    hv.y = pack2h(v.z*inv*wv.z, v.w*inv*wv.w);
    *(uint2*)(out + row * (long)Dn + t4) = hv;
}

__global__ void __launch_bounds__(256)
conv_row_k(const __half* __restrict__ b1h, const float* __restrict__ cbuf,
           const float* __restrict__ cw, const float* __restrict__ cb,
           __half* __restrict__ oh, float* __restrict__ out_cb) {
    const int row = blockIdx.x;              // 0..BT-1
    const int t = row & (Tn - 1);
    const int b = row >> 10;
    const int d4 = threadIdx.x * 4;
    const float4 w0 = *(const float4*)(cw + (d4 + 0) * CONVK);
    const float4 w1 = *(const float4*)(cw + (d4 + 1) * CONVK);
    const float4 w2 = *(const float4*)(cw + (d4 + 2) * CONVK);
    const float4 w3 = *(const float4*)(cw + (d4 + 3) * CONVK);
    const float4 bias = *(const float4*)(cb + d4);
    float acc0 = bias.x, acc1 = bias.y, acc2 = bias.z, acc3 = bias.w;
    float l0 = 0.f, l1 = 0.f, l2 = 0.f, l3 = 0.f;
    #pragma unroll
    for (int k = 0; k < CONVK; k++) {
        const int tt = t + k - (CONVK - 1);
        float s0, s1, s2, s3;
        if (tt >= 0) {
            const uint2 hv = *(const uint2*)(b1h + ((long)b * Tn + tt) * Dn + d4);
            const __half2 h0 = *(const __half2*)&hv.x;
            const __half2 h1 = *(const __half2*)&hv.y;
            s0 = __half2float(h0.x); s1 = __half2float(h0.y);
            s2 = __half2float(h1.x); s3 = __half2float(h1.y);
        } else {
            const float4 f = *(const float4*)(cbuf + ((long)b * (CONVK - 1) + (t + k)) * Dn + d4);
            s0 = f.x; s1 = f.y; s2 = f.z; s3 = f.w;
        }
        if (k == CONVK - 1) { l0 = s0; l1 = s1; l2 = s2; l3 = s3; }
        const float wk0 = (&w0.x)[k], wk1 = (&w1.x)[k], wk2 = (&w2.x)[k], wk3 = (&w3.x)[k];
        acc0 = fmaf(s0, wk0, acc0);
        acc1 = fmaf(s1, wk1, acc1);
        acc2 = fmaf(s2, wk2, acc2);
        acc3 = fmaf(s3, wk3, acc3);
    }
    uint2 hv; hv.x = pack2h(acc0, acc1); hv.y = pack2h(acc2, acc3);
    *(uint2*)(oh + (long)row * Dn + d4) = hv;
    if (t >= Tn - (CONVK - 1)) {
        float4 f; f.x = l0; f.y = l1; f.z = l2; f.w = l3;
        *(float4*)(out_cb + ((long)b * (CONVK - 1) + (t - (Tn - (CONVK - 1)))) * Dn + d4) = f;
    }
}

__global__ void scan_p1_k(const float* __restrict__ r, const __half* __restrict__ ih,
                          const __half* __restrict__ convh, const float* __restrict__ ls8,
                          __half* __restrict__ outh, __half* __restrict__ pah,
                          float* __restrict__ sE, float* __restrict__ sP) {
    const int idx = blockIdx.x * 128 + threadIdx.x;   // 0..Bsz*NCH*Dn-1
    const int d = idx & (Dn - 1);
    const int c = (idx >> 10) & (NCH - 1);
    const int b = idx >> 12;
    const float l8 = ls8[d];
    const long base = ((long)b * Tn + c * CHL) * Dn + d;
    float h = 0.f, p = 1.f;
    float cr[4], ci[4], cc[4];
    #pragma unroll
    for (int j = 0; j < 4; j++) {
        const long o = base + (long)j * Dn;
        cr[j] = r[o]; ci[j] = __half2float(ih[o]); cc[j] = __half2float(convh[o]);
    }
    for (int t0 = 0; t0 < CHL; t0 += 4) {
        float nr[4], ni[4], nc[4];
        if (t0 + 4 < CHL) {
            #pragma unroll
            for (int j = 0; j < 4; j++) {
                const long o = base + (long)(t0 + 4 + j) * Dn;
                nr[j] = r[o]; ni[j] = __half2float(ih[o]); nc[j] = __half2float(convh[o]);
            }
        }
        #pragma unroll
        for (int j = 0; j < 4; j++) {
            const float a = expf(cr[j] * l8);
            const float gate = sqrtf(fmaxf((1.f - a) * (1.f + a), 1e-6f));
            h = fmaf(a, h, gate * ci[j] * cc[j]);
            p *= a;
            const long o = base + (long)(t0 + j) * Dn;
            outh[o] = __float2half_rn(h);
            pah[o] = __float2half_rn(p);
        }
        #pragma unroll
        for (int j = 0; j < 4; j++) { cr[j] = nr[j]; ci[j] = ni[j]; cc[j] = nc[j]; }
    }
    sE[idx] = h;
    sP[idx] = p;
}

__global__ void scan_p2_k(const float* __restrict__ sE, const float* __restrict__ sP,
                          const float* __restrict__ h0, float* __restrict__ hs,
                          float* __restrict__ newh) {
    const int idx = blockIdx.x * 256 + threadIdx.x;   // 0..Bsz*Dn-1
    const int d = idx & (Dn - 1);
    const int b = idx >> 10;
    float h = h0[idx];
    #pragma unroll
    for (int c = 0; c < NCH; c++) {
        const long o = (long)(b * NCH + c) * Dn + d;
        hs[o] = h;
        h = sE[o] + sP[o] * h;
    }
    newh[idx] = h;
}

// ================= host side =================
extern "C" void kernel_launch(void* const* d_in, const int* in_sizes, int n_in,
                              void* d_out, int out_size) {
    const float* x_seq   = (const float*)d_in[0];
    const float* h0      = (const float*)d_in[1];
    const float* convbuf = (const float*)d_in[2];
    const float* norm1_w = (const float*)d_in[3];
    const float* W1      = (const float*)d_in[4];
    const float* conv_w  = (const float*)d_in[5];
    const float* conv_b  = (const float*)d_in[6];
    const float* Wa      = (const float*)d_in[7];
    const float* ba      = (const float*)d_in[8];
    const float* Wx      = (const float*)d_in[9];
    const float* bx      = (const float*)d_in[10];
    const float* log_lam = (const float*)d_in[11];
    const float* W2      = (const float*)d_in[12];
    const float* Wout    = (const float*)d_in[13];
    const float* norm2_w = (const float*)d_in[14];
    const float* Wg      = (const float*)d_in[15];
    const float* Wu      = (const float*)d_in[16];
    const float* Wo      = (const float*)d_in[17];

    float* out_x2 = (float*)d_out;
    float* out_h  = out_x2 + (long)BTD;
    float* out_cb = out_h + (long)Bsz * Dn;

    float *p_r, *p_x1, *p_ls8, *p_sE, *p_sP, *p_hs;
    cudaGetSymbolAddress((void**)&p_r, g_r);
    cudaGetSymbolAddress((void**)&p_x1, g_x1);
    cudaGetSymbolAddress((void**)&p_ls8, g_ls8);
    cudaGetSymbolAddress((void**)&p_sE, g_sE);
    cudaGetSymbolAddress((void**)&p_sP, g_sP);
    cudaGetSymbolAddress((void**)&p_hs, g_hs);

    __half *b1h, *ihh, *nh, *ch, *sch, *pah, *ph, *n2h, *acth;
    cudaGetSymbolAddress((void**)&b1h, g_b1_h);
    cudaGetSymbolAddress((void**)&ihh, g_i_h);
    cudaGetSymbolAddress((void**)&nh, g_norm_h);
    cudaGetSymbolAddress((void**)&ch, g_conv_h);
    cudaGetSymbolAddress((void**)&sch, g_scan_h);
    cudaGetSymbolAddress((void**)&pah, g_pa_h);
    cudaGetSymbolAddress((void**)&ph, g_prod_h);
    cudaGetSymbolAddress((void**)&n2h, g_n2_h);
    cudaGetSymbolAddress((void**)&acth, g_act_h);

    __half *w1h, *wah, *wxh, *w2h, *woh, *wgh, *wuh, *wo2h;
    cudaGetSymbolAddress((void**)&w1h, g_w1_h);
    cudaGetSymbolAddress((void**)&wah, g_wa_h);
    cudaGetSymbolAddress((void**)&wxh, g_wx_h);
    cudaGetSymbolAddress((void**)&w2h, g_w2_h);
    cudaGetSymbolAddress((void**)&woh, g_wo_h);
    cudaGetSymbolAddress((void**)&wgh, g_wg_h);
    cudaGetSymbolAddress((void**)&wuh, g_wu_h);
    cudaGetSymbolAddress((void**)&wo2h, g_wout2_h);

    cudaFuncSetAttribute(gemm_mma<0,1>, cudaFuncAttributeMaxDynamicSharedMemorySize, S_SMEM);
    cudaFuncSetAttribute(gemm_mma<3,0>, cudaFuncAttributeMaxDynamicSharedMemorySize, S_SMEM);
    cudaFuncSetAttribute(gemm_mma<6,1>, cudaFuncAttributeMaxDynamicSharedMemorySize, S_SMEM);
    cudaFuncSetAttribute(gemm_ri,       cudaFuncAttributeMaxDynamicSharedMemorySize, S_SMEM);
    cudaFuncSetAttribute(gemm_dual,     cudaFuncAttributeMaxDynamicSharedMemorySize, D_SMEM);

    const dim3 gD(Dn / 128, BT / 256);        // (8, 64)
    const dim3 gRI(Dn / 128, BT / 256, 2);    // (8, 64, 2)
    const dim3 gH(Hn / 128, BT / 128);        // (32, 128)

    // 1. W1 + ls8 conversion
    wconv_w1_k<<<(W1M + Dn/4 + 255)/256, 256>>>(W1, log_lam, w1h, p_ls8);
    // 2. remaining weights
    const long WR = 4L*W1M + 3L*WHM;
    wconv_rest_k<<<(int)((WR + 255)/256), 256>>>(Wa, Wx, W2, Wout, Wg, Wu, Wo,
                                                 wah, wxh, w2h, woh, wgh, wuh, wo2h);
    // 3. rmsnorm1 -> fp16
    rmsnorm_half_k<<<BT, 256>>>(x_seq, norm1_w, nh);
    // 4. b1 = normed @ W1^T -> fp16   (ncu slot #4)
    gemm_mma<0,1><<<gD, 512, S_SMEM>>>(nh, w1h, nullptr, b1h, nullptr, nullptr,
                                       nullptr, nullptr, Dn, Dn);
    // 5. conv -> fp16 (+ new_conv_buf fused)
    conv_row_k<<<BT, 256>>>(b1h, convbuf, conv_w, conv_b, ch, out_cb);
    // 6. merged r (fp32) + i (fp16) GEMM
    gemm_ri<<<gRI, 512, S_SMEM>>>(ch, wah, wxh, p_r, ihh, ba, bx, Dn, Dn);
    // 7. scan pass 1 (chunk-local, 4x parallel)
    scan_p1_k<<<(Bsz * NCH * Dn) / 128, 128>>>(p_r, ihh, ch, p_ls8, sch, pah, p_sE, p_sP);
    // 8. scan pass 2
    scan_p2_k<<<(Bsz * Dn) / 256, 256>>>(p_sE, p_sP, h0, p_hs, out_h);
    // 9. prod = gelu(normed @ W2^T) * (scan_local + pa*hs) -> fp16
    gemm_mma<6,1><<<gD, 512, S_SMEM>>>(nh, w2h, nullptr, ph, nullptr, sch,
                                       pah, p_hs, Dn, Dn);
    // 10. x1 = x_seq + prod @ Wout^T
    gemm_mma<3,0><<<gD, 512, S_SMEM>>>(ph, woh, p_x1, nullptr, x_seq, nullptr,
                                       nullptr, nullptr, Dn, Dn);
    // 11. n2 = rmsnorm(x1) -> fp16
    rmsnorm_half_k<<<BT, 256>>>(p_x1, norm2_w, n2h);
    // 12. act = gelu(n2@Wg^T) * (n2@Wu^T) -> fp16
    gemm_dual<<<gH, 512, D_SMEM>>>(n2h, wgh, wuh, acth, Hn, Dn);
    // 13. x2 = x1 + act @ Wo^T
    gemm_mma<3,0><<<gD, 512, S_SMEM>>>(acth, wo2h, out_x2, nullptr, p_x1, nullptr,
                                       nullptr, nullptr, Dn, Hn);
}

// round 15
// speedup vs baseline: 1.1776x; 1.0153x over previous
#include <cuda_runtime.h>
#include <cuda_fp16.h>
#include <math.h>
#include <stdint.h>

// ---------------- problem dims ----------------
#define Bsz 16
#define Tn  1024
#define Dn  1024
#define Hn  4096
#define BT  (Bsz*Tn)              // 16384
#define BTD (Bsz*Tn*Dn)           // 16777216
#define BTH (Bsz*Tn*Hn)           // 67108864
#define CONVK 4
#define NCH 4                     // scan chunks
#define CHL (Tn/NCH)              // 256

// ---------------- GEMM tile config ----------------
#define STAGES 4
#define S_A_BYTES 20480           // 256 rows x 80B
#define S_STAGE   30720
#define S_SMEM    (STAGES*S_STAGE)    // 122880
#define D_STAGE   30720
#define D_SMEM    (STAGES*D_STAGE)    // 122880

// ---------------- scratch (device globals) ----------------
__device__ __align__(128) float g_r[BTD];
__device__ __align__(128) float g_x1[BTD];
__device__ __align__(128) float g_ls8[Dn];
__device__ __align__(128) float g_sE[Bsz*NCH*Dn];
__device__ __align__(128) float g_sP[Bsz*NCH*Dn];
__device__ __align__(128) float g_hs[Bsz*NCH*Dn];

__device__ __align__(128) __half g_b1_h[BTD];
__device__ __align__(128) __half g_i_h[BTD];
__device__ __align__(128) __half g_norm_h[BTD];
__device__ __align__(128) __half g_conv_h[BTD];
__device__ __align__(128) __half g_scan_h[BTD];
__device__ __align__(128) __half g_pa_h[BTD];
__device__ __align__(128) __half g_b2_h[BTD];       // gelu(normed@W2^T)
__device__ __align__(128) __half g_prod_h[BTD];
__device__ __align__(128) __half g_n2_h[BTD];
__device__ __align__(128) __half g_act_h[BTH];

__device__ __align__(128) __half g_w1_h[Dn*Dn];
__device__ __align__(128) __half g_wa_h[Dn*Dn];
__device__ __align__(128) __half g_wx_h[Dn*Dn];
__device__ __align__(128) __half g_w2_h[Dn*Dn];
__device__ __align__(128) __half g_wo_h[Dn*Dn];
__device__ __align__(128) __half g_wg_h[(long)Hn*Dn];
__device__ __align__(128) __half g_wu_h[(long)Hn*Dn];
__device__ __align__(128) __half g_wout2_h[(long)Dn*Hn];

// ---------------- helpers ----------------
__device__ __forceinline__ uint32_t smem_u32(const void* p) {
    uint32_t a;
    asm("{ .reg .u64 t; cvta.to.shared.u64 t, %1; cvt.u32.u64 %0, t; }"
        : "=r"(a) : "l"(p));
    return a;
}
__device__ __forceinline__ float gelu_f(float x) {
    return 0.5f * x * (1.0f + erff(x * 0.70710678118654752440f));
}
__device__ __forceinline__ float sigm_f(float x) {
    return 1.0f / (1.0f + expf(-x));
}
__device__ __forceinline__ uint32_t pack2h(float a, float b) {
    __half2 t = __floats2half2_rn(a, b);
    return *reinterpret_cast<uint32_t*>(&t);
}
__device__ __forceinline__ void ldsm4(uint32_t addr, uint32_t r[4]) {
    asm volatile("ldmatrix.sync.aligned.m8n8.x4.shared.b16 {%0,%1,%2,%3}, [%4];"
                 : "=r"(r[0]), "=r"(r[1]), "=r"(r[2]), "=r"(r[3]) : "r"(addr));
}
__device__ __forceinline__ void mma16816(float c[4], const uint32_t a[4], const uint32_t b[2]) {
    asm volatile("mma.sync.aligned.m16n8k16.row.col.f32.f16.f16.f32 "
                 "{%0,%1,%2,%3}, {%4,%5,%6,%7}, {%8,%9}, {%0,%1,%2,%3};"
                 : "+f"(c[0]), "+f"(c[1]), "+f"(c[2]), "+f"(c[3])
                 : "r"(a[0]), "r"(a[1]), "r"(a[2]), "r"(a[3]), "r"(b[0]), "r"(b[1]));
}
__device__ __forceinline__ void cp16(uint32_t dst, const void* src) {
    asm volatile("cp.async.cg.shared.global [%0], [%1], 16;" :: "r"(dst), "l"(src));
}
#define CP_COMMIT() asm volatile("cp.async.commit_group;" ::: "memory")
#define CP_WAIT2()  asm volatile("cp.async.wait_group 2;" ::: "memory")

__device__ __forceinline__ void ld_ab_s(uint32_t base, int kk, int wm, int wn, int lane,
                                        uint32_t ah[4][4], uint32_t bh[4][2]) {
    const uint32_t koff = (kk * 16 + (lane >> 4) * 8) * 2;
    #pragma unroll
    for (int i = 0; i < 4; i++) {
        const uint32_t off = (uint32_t)(wm * 64 + i * 16 + (lane & 15)) * 80 + koff;
        ldsm4(base + off, ah[i]);
    }
    #pragma unroll
    for (int j = 0; j < 2; j++) {
        const uint32_t off = (uint32_t)(wn * 32 + j * 16 + (lane & 15)) * 80 + koff;
        uint32_t t[4];
        ldsm4(base + S_A_BYTES + off, t);
        bh[2*j][0] = t[0]; bh[2*j][1] = t[2];
        bh[2*j+1][0] = t[1]; bh[2*j+1][1] = t[3];
    }
}

// ================= GEMM 256x128, 512 threads =================
// EPI: 0=none 2=gelu 3=v+auxf ; HOUT: 1 -> fp16 out
template<int EPI, int HOUT>
__global__ void __launch_bounds__(512, 1)
gemm_mma(const __half* __restrict__ A, const __half* __restrict__ B,
         float* __restrict__ C, __half* __restrict__ Ch,
         const float* __restrict__ auxf, int N, int K)
{
    extern __shared__ __align__(128) char smem[];
    const uint32_t sb = smem_u32(smem);
    const int tid = threadIdx.x;
    const int lane = tid & 31, wid = tid >> 5;
    const int wm = wid & 3;
    const int wn = wid >> 2;
    const long rowA = (long)blockIdx.y * 256;
    const long rowB = (long)blockIdx.x * 128;
    const int nk = K >> 5;

    float acc[4][4][4];
    #pragma unroll
    for (int i = 0; i < 4; i++)
        #pragma unroll
        for (int n = 0; n < 4; n++)
            #pragma unroll
            for (int q = 0; q < 4; q++) acc[i][n][q] = 0.f;

    auto load_stage = [&](int s, int kt) {
        const uint32_t base = sb + s * S_STAGE;
        const int k0 = kt << 5;
        #pragma unroll
        for (int t = 0; t < 2; t++) {
            const int idx = tid + t * 512;
            const int r = idx >> 2, c = idx & 3;
            cp16(base + r * 80 + c * 16, A + (rowA + r) * (long)K + k0 + c * 8);
        }
        {
            const int r = tid >> 2, c = tid & 3;
            cp16(base + S_A_BYTES + r * 80 + c * 16, B + (rowB + r) * (long)K + k0 + c * 8);
        }
    };

    load_stage(0, 0); CP_COMMIT();
    load_stage(1, 1); CP_COMMIT();
    load_stage(2, 2); CP_COMMIT();

    for (int kt = 0; kt < nk; kt++) {
        CP_WAIT2();
        __syncthreads();
        if (kt + 3 < nk) load_stage((kt + 3) & 3, kt + 3);
        CP_COMMIT();

        const uint32_t base = sb + (kt & 3) * S_STAGE;
        #pragma unroll
        for (int kk = 0; kk < 2; kk++) {
            uint32_t ah[4][4], bh[4][2];
            ld_ab_s(base, kk, wm, wn, lane, ah, bh);
            #pragma unroll
            for (int i = 0; i < 4; i++)
                #pragma unroll
                for (int n = 0; n < 4; n++)
                    mma16816(acc[i][n], ah[i], bh[n]);
        }
    }

    const long r0 = rowA + wm * 64 + (lane >> 2);
    const long c0 = rowB + wn * 32 + (lane & 3) * 2;
    #pragma unroll
    for (int i = 0; i < 4; i++) {
        #pragma unroll
        for (int n = 0; n < 4; n++) {
            #pragma unroll
            for (int h = 0; h < 2; h++) {
                const long row = r0 + i * 16 + h * 8;
                const long col = c0 + n * 8;
                float v0 = acc[i][n][2*h + 0];
                float v1 = acc[i][n][2*h + 1];
                if (EPI == 2) {
                    v0 = gelu_f(v0); v1 = gelu_f(v1);
                } else if (EPI == 3) {
                    const float2 a2 = *(const float2*)(auxf + row * (long)N + col);
                    v0 += a2.x; v1 += a2.y;
                }
                if (HOUT) {
                    *(uint32_t*)(Ch + row * (long)N + col) = pack2h(v0, v1);
                } else {
                    float2 o; o.x = v0; o.y = v1;
                    *(float2*)(C + row * (long)N + col) = o;
                }
            }
        }
    }
}

// ================= merged r/i GEMM =================
__global__ void __launch_bounds__(512, 1)
gemm_ri(const __half* __restrict__ A, const __half* __restrict__ Wa,
        const __half* __restrict__ Wx, float* __restrict__ Rout,
        __half* __restrict__ Iout, const float* __restrict__ ba,
        const float* __restrict__ bx, int N, int K)
{
    extern __shared__ __align__(128) char smem[];
    const uint32_t sb = smem_u32(smem);
    const int tid = threadIdx.x;
    const int lane = tid & 31, wid = tid >> 5;
    const int wm = wid & 3;
    const int wn = wid >> 2;
    const long rowA = (long)blockIdx.y * 256;
    const long rowB = (long)blockIdx.x * 128;
    const int z = blockIdx.z;
    const __half* B = z ? Wx : Wa;
    const float* bias = z ? bx : ba;
    const int nk = K >> 5;

    float acc[4][4][4];
    #pragma unroll
    for (int i = 0; i < 4; i++)
        #pragma unroll
        for (int n = 0; n < 4; n++)
            #pragma unroll
            for (int q = 0; q < 4; q++) acc[i][n][q] = 0.f;

    auto load_stage = [&](int s, int kt) {
        const uint32_t base = sb + s * S_STAGE;
        const int k0 = kt << 5;
        #pragma unroll
        for (int t = 0; t < 2; t++) {
            const int idx = tid + t * 512;
            const int r = idx >> 2, c = idx & 3;
            cp16(base + r * 80 + c * 16, A + (rowA + r) * (long)K + k0 + c * 8);
        }
        {
            const int r = tid >> 2, c = tid & 3;
            cp16(base + S_A_BYTES + r * 80 + c * 16, B + (rowB + r) * (long)K + k0 + c * 8);
        }
    };

    load_stage(0, 0); CP_COMMIT();
    load_stage(1, 1); CP_COMMIT();
    load_stage(2, 2); CP_COMMIT();

    for (int kt = 0; kt < nk; kt++) {
        CP_WAIT2();
        __syncthreads();
        if (kt + 3 < nk) load_stage((kt + 3) & 3, kt + 3);
        CP_COMMIT();

        const uint32_t base = sb + (kt & 3) * S_STAGE;
        #pragma unroll
        for (int kk = 0; kk < 2; kk++) {
            uint32_t ah[4][4], bh[4][2];
            ld_ab_s(base, kk, wm, wn, lane, ah, bh);
            #pragma unroll
            for (int i = 0; i < 4; i++)
                #pragma unroll
                for (int n = 0; n < 4; n++)
                    mma16816(acc[i][n], ah[i], bh[n]);
        }
    }

    const long r0 = rowA + wm * 64 + (lane >> 2);
    const long c0 = rowB + wn * 32 + (lane & 3) * 2;
    #pragma unroll
    for (int i = 0; i < 4; i++) {
        #pragma unroll
        for (int n = 0; n < 4; n++) {
            #pragma unroll
            for (int h = 0; h < 2; h++) {
                const long row = r0 + i * 16 + h * 8;
                const long col = c0 + n * 8;
                const float v0 = sigm_f(acc[i][n][2*h + 0] + bias[col]);
                const float v1 = sigm_f(acc[i][n][2*h + 1] + bias[col + 1]);
                if (z) {
                    *(uint32_t*)(Iout + row * (long)N + col) = pack2h(v0, v1);
                } else {
                    float2 o; o.x = v0; o.y = v1;
                    *(float2*)(Rout + row * (long)N + col) = o;
                }
            }
        }
    }
}

// ============ Dual MLP GEMM 128x128, 512 threads ==========
__global__ void __launch_bounds__(512, 1)
gemm_dual(const __half* __restrict__ A, const __half* __restrict__ Bg,
          const __half* __restrict__ Bu, __half* __restrict__ Ch,
          int N, int K)
{
    extern __shared__ __align__(128) char smem[];
    const uint32_t sb = smem_u32(smem);
    const int tid = threadIdx.x;
    const int lane = tid & 31, wid = tid >> 5;
    const int wm = wid & 3;
    const int wn = wid >> 2;
    const long rowA = (long)blockIdx.y * 128;
    const long rowB = (long)blockIdx.x * 128;
    const int nk = K >> 5;

    float accg[2][4][4], accu[2][4][4];
    #pragma unroll
    for (int i = 0; i < 2; i++)
        #pragma unroll
        for (int n = 0; n < 4; n++)
            #pragma unroll
            for (int q = 0; q < 4; q++) { accg[i][n][q] = 0.f; accu[i][n][q] = 0.f; }

    auto load_stage = [&](int s, int kt) {
        const uint32_t base = sb + s * D_STAGE;
        const int k0 = kt << 5;
        const int r = tid >> 2, c = tid & 3;
        cp16(base + r * 80 + c * 16, A + (rowA + r) * (long)K + k0 + c * 8);
        cp16(base + 10240 + r * 80 + c * 16, Bg + (rowB + r) * (long)K + k0 + c * 8);
        cp16(base + 20480 + r * 80 + c * 16, Bu + (rowB + r) * (long)K + k0 + c * 8);
    };

    load_stage(0, 0); CP_COMMIT();
    load_stage(1, 1); CP_COMMIT();
    load_stage(2, 2); CP_COMMIT();

    for (int kt = 0; kt < nk; kt++) {
        CP_WAIT2();
        __syncthreads();
        if (kt + 3 < nk) load_stage((kt + 3) & 3, kt + 3);
        CP_COMMIT();

        const uint32_t base = sb + (kt & 3) * D_STAGE;
        #pragma unroll
        for (int kk = 0; kk < 2; kk++) {
            const uint32_t koff = (kk * 16 + (lane >> 4) * 8) * 2;
            uint32_t ah[2][4];
            #pragma unroll
            for (int i = 0; i < 2; i++) {
                const uint32_t off = (uint32_t)(wm * 32 + i * 16 + (lane & 15)) * 80 + koff;
                ldsm4(base + off, ah[i]);
            }
            uint32_t bg[4][2], bu[4][2];
            #pragma unroll
            for (int j = 0; j < 2; j++) {
                const uint32_t off = (uint32_t)(wn * 32 + j * 16 + (lane & 15)) * 80 + koff;
                uint32_t t[4], u[4];
                ldsm4(base + 10240 + off, t);
                ldsm4(base + 20480 + off, u);
                bg[2*j][0] = t[0]; bg[2*j][1] = t[2];
                bg[2*j+1][0] = t[1]; bg[2*j+1][1] = t[3];
                bu[2*j][0] = u[0]; bu[2*j][1] = u[2];
                bu[2*j+1][0] = u[1]; bu[2*j+1][1] = u[3];
            }
            #pragma unroll
            for (int i = 0; i < 2; i++)
                #pragma unroll
                for (int n = 0; n < 4; n++) {
                    mma16816(accg[i][n], ah[i], bg[n]);
                    mma16816(accu[i][n], ah[i], bu[n]);
                }
        }
    }

    const long r0 = rowA + wm * 32 + (lane >> 2);
    const long c0 = rowB + wn * 32 + (lane & 3) * 2;
    #pragma unroll
    for (int i = 0; i < 2; i++) {
        #pragma unroll
        for (int n = 0; n < 4; n++) {
            #pragma unroll
            for (int h = 0; h < 2; h++) {
                const long row = r0 + i * 16 + h * 8;
                const long col = c0 + n * 8;
                const float v0 = gelu_f(accg[i][n][2*h + 0]) * accu[i][n][2*h + 0];
                const float v1 = gelu_f(accg[i][n][2*h + 1]) * accu[i][n][2*h + 1];
                *(uint32_t*)(Ch + row * (long)N + col) = pack2h(v0, v1);
            }
        }
    }
}

// ================= elementwise kernels =================
#define W1M (Dn*Dn/4)
#define WHM ((long)Hn*Dn/4)

__global__ void wconv_w1_k(const float* __restrict__ W1, const float* __restrict__ ll,
                           __half* __restrict__ o1, float* __restrict__ ls8) {
    const long i = (long)blockIdx.x * 256 + threadIdx.x;
    if (i < W1M) {
        float4 v = *(const float4*)(W1 + i * 4);
        uint2 hv; hv.x = pack2h(v.x, v.y); hv.y = pack2h(v.z, v.w);
        *(uint2*)(o1 + i * 4) = hv;
    } else if (i < W1M + Dn / 4) {
        const long d = (i - W1M) * 4;
        #pragma unroll
        for (int j = 0; j < 4; j++)
            ls8[d + j] = -8.0f * log1pf(expf(-ll[d + j]));
    }
}

__global__ void wconv_rest_k(const float* __restrict__ Wa, const float* __restrict__ Wx,
                             const float* __restrict__ W2, const float* __restrict__ Wout,
                             const float* __restrict__ Wg, const float* __restrict__ Wu,
                             const float* __restrict__ Wo,
                             __half* __restrict__ oa, __half* __restrict__ ox,
                             __half* __restrict__ o2, __half* __restrict__ oo,
                             __half* __restrict__ og, __half* __restrict__ ou,
                             __half* __restrict__ owo)
{
    const long i = (long)blockIdx.x * 256 + threadIdx.x;
    const long T4 = 4L * W1M, T5 = T4 + WHM, T6 = T5 + WHM, T7 = T6 + WHM;
    const float* src; __half* dst; long off;
    if (i < T4) {
        const long s = i / W1M; off = i - s * W1M;
        const float* srcs[4] = {Wa, Wx, W2, Wout};
        __half* dsts[4] = {oa, ox, o2, oo};
        src = srcs[s]; dst = dsts[s];
    } else if (i < T5) { src = Wg;  dst = og;  off = i - T4; }
    else if (i < T6)   { src = Wu;  dst = ou;  off = i - T5; }
    else if (i < T7)   { src = Wo;  dst = owo; off = i - T6; }
    else return;
    float4 v = *(const float4*)(src + off * 4);
    uint2 hv; hv.x = pack2h(v.x, v.y); hv.y = pack2h(v.z, v.w);
    *(uint2*)(dst + off * 4) = hv;
}

__global__ void rmsnorm_half_k(const float* __restrict__ x, const float* __restrict__ w,
                               __half* __restrict__ out) {
    const long row = blockIdx.x;
    const float* xr = x + row * (long)Dn;
    const int t4 = threadIdx.x * 4;
    float4 v = *(const float4*)(xr + t4);
    float ss = v.x*v.x + v.y*v.y + v.z*v.z + v.w*v.w;
    #pragma unroll
    for (int o = 16; o > 0; o >>= 1) ss += __shfl_xor_sync(0xffffffffu, ss, o);
    __shared__ float warps[8];
    if ((threadIdx.x & 31) == 0) warps[threadIdx.x >> 5] = ss;
    __syncthreads();
    float tot = 0.f;
    #pragma unroll
    for (int i = 0; i < 8; i++) tot += warps[i];
    const float inv = rsqrtf(tot * (1.0f / Dn) + 1.1920929e-07f);
    float4 wv = *(const float4*)(w + t4);
    uint2 hv;
    hv.x = pack2h(v.x*inv*wv.x, v.y*inv*wv.y);
    hv.y = pack2h(v.z*inv*wv.z, v.w*inv*wv.w);
    *(uint2*)(out + row * (long)Dn + t4) = hv;
}

__global__ void __launch_bounds__(256)
conv_row_k(const __half* __restrict__ b1h, const float* __restrict__ cbuf,
           const float* __restrict__ cw, const float* __restrict__ cb,
           __half* __restrict__ oh, float* __restrict__ out_cb) {
    const int row = blockIdx.x;
    const int t = row & (Tn - 1);
    const int b = row >> 10;
    const int d4 = threadIdx.x * 4;
    const float4 w0 = *(const float4*)(cw + (d4 + 0) * CONVK);
    const float4 w1 = *(const float4*)(cw + (d4 + 1) * CONVK);
    const float4 w2 = *(const float4*)(cw + (d4 + 2) * CONVK);
    const float4 w3 = *(const float4*)(cw + (d4 + 3) * CONVK);
    const float4 bias = *(const float4*)(cb + d4);
    float acc0 = bias.x, acc1 = bias.y, acc2 = bias.z, acc3 = bias.w;
    float l0 = 0.f, l1 = 0.f, l2 = 0.f, l3 = 0.f;
    #pragma unroll
    for (int k = 0; k < CONVK; k++) {
        const int tt = t + k - (CONVK - 1);
        float s0, s1, s2, s3;
        if (tt >= 0) {
            const uint2 hv = *(const uint2*)(b1h + ((long)b * Tn + tt) * Dn + d4);
            const __half2 h0 = *(const __half2*)&hv.x;
            const __half2 h1 = *(const __half2*)&hv.y;
            s0 = __half2float(h0.x); s1 = __half2float(h0.y);
            s2 = __half2float(h1.x); s3 = __half2float(h1.y);
        } else {
            const float4 f = *(const float4*)(cbuf + ((long)b * (CONVK - 1) + (t + k)) * Dn + d4);
            s0 = f.x; s1 = f.y; s2 = f.z; s3 = f.w;
        }
        if (k == CONVK - 1) { l0 = s0; l1 = s1; l2 = s2; l3 = s3; }
        const float wk0 = (&w0.x)[k], wk1 = (&w1.x)[k], wk2 = (&w2.x)[k], wk3 = (&w3.x)[k];
        acc0 = fmaf(s0, wk0, acc0);
        acc1 = fmaf(s1, wk1, acc1);
        acc2 = fmaf(s2, wk2, acc2);
        acc3 = fmaf(s3, wk3, acc3);
    }
    uint2 hv; hv.x = pack2h(acc0, acc1); hv.y = pack2h(acc2, acc3);
    *(uint2*)(oh + (long)row * Dn + d4) = hv;
    if (t >= Tn - (CONVK - 1)) {
        float4 f; f.x = l0; f.y = l1; f.z = l2; f.w = l3;
        *(float4*)(out_cb + ((long)b * (CONVK - 1) + (t - (Tn - (CONVK - 1)))) * Dn + d4) = f;
    }
}

__global__ void scan_p1_k(const float* __restrict__ r, const __half* __restrict__ ih,
                          const __half* __restrict__ convh, const float* __restrict__ ls8,
                          __half* __restrict__ outh, __half* __restrict__ pah,
                          float* __restrict__ sE, float* __restrict__ sP) {
    const int idx = blockIdx.x * 128 + threadIdx.x;
    const int d = idx & (Dn - 1);
    const int c = (idx >> 10) & (NCH - 1);
    const int b = idx >> 12;
    const float l8 = ls8[d];
    const long base = ((long)b * Tn + c * CHL) * Dn + d;
    float h = 0.f, p = 1.f;
    float cr[4], ci[4], cc[4];
    #pragma unroll
    for (int j = 0; j < 4; j++) {
        const long o = base + (long)j * Dn;
        cr[j] = r[o]; ci[j] = __half2float(ih[o]); cc[j] = __half2float(convh[o]);
    }
    for (int t0 = 0; t0 < CHL; t0 += 4) {
        float nr[4], ni[4], nc[4];
        if (t0 + 4 < CHL) {
            #pragma unroll
            for (int j = 0; j < 4; j++) {
                const long o = base + (long)(t0 + 4 + j) * Dn;
                nr[j] = r[o]; ni[j] = __half2float(ih[o]); nc[j] = __half2float(convh[o]);
            }
        }
        #pragma unroll
        for (int j = 0; j < 4; j++) {
            const float a = expf(cr[j] * l8);
            const float gate = sqrtf(fmaxf((1.f - a) * (1.f + a), 1e-6f));
            h = fmaf(a, h, gate * ci[j] * cc[j]);
            p *= a;
            const long o = base + (long)(t0 + j) * Dn;
            outh[o] = __float2half_rn(h);
            pah[o] = __float2half_rn(p);
        }
        #pragma unroll
        for (int j = 0; j < 4; j++) { cr[j] = nr[j]; ci[j] = ni[j]; cc[j] = nc[j]; }
    }
    sE[idx] = h;
    sP[idx] = p;
}

__global__ void scan_p2_k(const float* __restrict__ sE, const float* __restrict__ sP,
                          const float* __restrict__ h0, float* __restrict__ hs,
                          float* __restrict__ newh) {
    const int idx = blockIdx.x * 256 + threadIdx.x;
    const int d = idx & (Dn - 1);
    const int b = idx >> 10;
    float h = h0[idx];
    #pragma unroll
    for (int c = 0; c < NCH; c++) {
        const long o = (long)(b * NCH + c) * Dn + d;
        hs[o] = h;
        h = sE[o] + sP[o] * h;
    }
    newh[idx] = h;
}

// prod = b2 * (scan_local + pa*hs)   (fp16 in/out, fp32 math)
__global__ void prod_k(const __half* __restrict__ b2, const __half* __restrict__ sc,
                       const __half* __restrict__ pa, const float* __restrict__ hs,
                       __half* __restrict__ out) {
    const long i = (long)blockIdx.x * 256 + threadIdx.x;
    if (i >= BTD / 4) return;
    const long e = i * 4;
    const int row = (int)(e >> 10);
    const int d0 = (int)(e & (Dn - 1));
    const int b = row >> 10, t = row & (Tn - 1), cch = t >> 8;
    const float4 h4 = *(const float4*)(hs + ((long)(b * NCH + cch)) * Dn + d0);
    const uint2 b2v = *(const uint2*)(b2 + e);
    const uint2 scv = *(const uint2*)(sc + e);
    const uint2 pav = *(const uint2*)(pa + e);
    const __half2 b2a = *(const __half2*)&b2v.x, b2b = *(const __half2*)&b2v.y;
    const __half2 sca = *(const __half2*)&scv.x, scb = *(const __half2*)&scv.y;
    const __half2 paa = *(const __half2*)&pav.x, pab = *(const __half2*)&pav.y;
    const float v0 = __half2float(b2a.x) * (__half2float(sca.x) + __half2float(paa.x) * h4.x);
    const float v1 = __half2float(b2a.y) * (__half2float(sca.y) + __half2float(paa.y) * h4.y);
    const float v2 = __half2float(b2b.x) * (__half2float(scb.x) + __half2float(pab.x) * h4.z);
    const float v3 = __half2float(b2b.y) * (__half2float(scb.y) + __half2float(pab.y) * h4.w);
    uint2 o; o.x = pack2h(v0, v1); o.y = pack2h(v2, v3);
    *(uint2*)(out + e) = o;
}

// ================= host side =================
extern "C" void kernel_launch(void* const* d_in, const int* in_sizes, int n_in,
                              void* d_out, int out_size) {
    const float* x_seq   = (const float*)d_in[0];
    const float* h0      = (const float*)d_in[1];
    const float* convbuf = (const float*)d_in[2];
    const float* norm1_w = (const float*)d_in[3];
    const float* W1      = (const float*)d_in[4];
    const float* conv_w  = (const float*)d_in[5];
    const float* conv_b  = (const float*)d_in[6];
    const float* Wa      = (const float*)d_in[7];
    const float* ba      = (const float*)d_in[8];
    const float* Wx      = (const float*)d_in[9];
    const float* bx      = (const float*)d_in[10];
    const float* log_lam = (const float*)d_in[11];
    const float* W2      = (const float*)d_in[12];
    const float* Wout    = (const float*)d_in[13];
    const float* norm2_w = (const float*)d_in[14];
    const float* Wg      = (const float*)d_in[15];
    const float* Wu      = (const float*)d_in[16];
    const float* Wo      = (const float*)d_in[17];

    float* out_x2 = (float*)d_out;
    float* out_h  = out_x2 + (long)BTD;
    float* out_cb = out_h + (long)Bsz * Dn;

    float *p_r, *p_x1, *p_ls8, *p_sE, *p_sP, *p_hs;
    cudaGetSymbolAddress((void**)&p_r, g_r);
    cudaGetSymbolAddress((void**)&p_x1, g_x1);
    cudaGetSymbolAddress((void**)&p_ls8, g_ls8);
    cudaGetSymbolAddress((void**)&p_sE, g_sE);
    cudaGetSymbolAddress((void**)&p_sP, g_sP);
    cudaGetSymbolAddress((void**)&p_hs, g_hs);

    __half *b1h, *ihh, *nh, *ch, *sch, *pah, *b2h, *ph, *n2h, *acth;
    cudaGetSymbolAddress((void**)&b1h, g_b1_h);
    cudaGetSymbolAddress((void**)&ihh, g_i_h);
    cudaGetSymbolAddress((void**)&nh, g_norm_h);
    cudaGetSymbolAddress((void**)&ch, g_conv_h);
    cudaGetSymbolAddress((void**)&sch, g_scan_h);
    cudaGetSymbolAddress((void**)&pah, g_pa_h);
    cudaGetSymbolAddress((void**)&b2h, g_b2_h);
    cudaGetSymbolAddress((void**)&ph, g_prod_h);
    cudaGetSymbolAddress((void**)&n2h, g_n2_h);
    cudaGetSymbolAddress((void**)&acth, g_act_h);

    __half *w1h, *wah, *wxh, *w2h, *woh, *wgh, *wuh, *wo2h;
    cudaGetSymbolAddress((void**)&w1h, g_w1_h);
    cudaGetSymbolAddress((void**)&wah, g_wa_h);
    cudaGetSymbolAddress((void**)&wxh, g_wx_h);
    cudaGetSymbolAddress((void**)&w2h, g_w2_h);
    cudaGetSymbolAddress((void**)&woh, g_wo_h);
    cudaGetSymbolAddress((void**)&wgh, g_wg_h);
    cudaGetSymbolAddress((void**)&wuh, g_wu_h);
    cudaGetSymbolAddress((void**)&wo2h, g_wout2_h);

    cudaFuncSetAttribute(gemm_mma<0,1>, cudaFuncAttributeMaxDynamicSharedMemorySize, S_SMEM);
    cudaFuncSetAttribute(gemm_mma<2,1>, cudaFuncAttributeMaxDynamicSharedMemorySize, S_SMEM);
    cudaFuncSetAttribute(gemm_mma<3,0>, cudaFuncAttributeMaxDynamicSharedMemorySize, S_SMEM);
    cudaFuncSetAttribute(gemm_ri,       cudaFuncAttributeMaxDynamicSharedMemorySize, S_SMEM);
    cudaFuncSetAttribute(gemm_dual,     cudaFuncAttributeMaxDynamicSharedMemorySize, D_SMEM);

    // static side stream + events (created once, on the uncaptured correctness call)
    static cudaStream_t s_side = nullptr;
    static cudaEvent_t ev_root, ev_nh, ev_wc, ev_b2;
    if (!s_side) {
        cudaStreamCreateWithFlags(&s_side, cudaStreamNonBlocking);
        cudaEventCreateWithFlags(&ev_root, cudaEventDisableTiming);
        cudaEventCreateWithFlags(&ev_nh,   cudaEventDisableTiming);
        cudaEventCreateWithFlags(&ev_wc,   cudaEventDisableTiming);
        cudaEventCreateWithFlags(&ev_b2,   cudaEventDisableTiming);
    }

    const dim3 gD(Dn / 128, BT / 256);        // (8, 64)
    const dim3 gRI(Dn / 128, BT / 256, 2);
    const dim3 gH(Hn / 128, BT / 128);

    // ---- main: W1 conversion + rmsnorm1 ----
    wconv_w1_k<<<(W1M + Dn/4 + 255)/256, 256>>>(W1, log_lam, w1h, p_ls8);
    cudaEventRecord(ev_root, 0);              // fork point for side stream
    rmsnorm_half_k<<<BT, 256>>>(x_seq, norm1_w, nh);
    cudaEventRecord(ev_nh, 0);

    // ---- side: remaining weight conversions, then W2 GEMM -> b2h ----
    cudaStreamWaitEvent(s_side, ev_root, 0);
    const long WR = 4L*W1M + 3L*WHM;
    wconv_rest_k<<<(int)((WR + 255)/256), 256, 0, s_side>>>(
        Wa, Wx, W2, Wout, Wg, Wu, Wo, wah, wxh, w2h, woh, wgh, wuh, wo2h);
    cudaEventRecord(ev_wc, s_side);
    cudaStreamWaitEvent(s_side, ev_nh, 0);
    gemm_mma<2,1><<<gD, 512, S_SMEM, s_side>>>(nh, w2h, nullptr, b2h, nullptr, Dn, Dn);
    cudaEventRecord(ev_b2, s_side);

    // ---- main chain ----
    gemm_mma<0,1><<<gD, 512, S_SMEM>>>(nh, w1h, nullptr, b1h, nullptr, Dn, Dn);
    conv_row_k<<<BT, 256>>>(b1h, convbuf, conv_w, conv_b, ch, out_cb);
    cudaStreamWaitEvent(0, ev_wc, 0);         // need wah/wxh
    gemm_ri<<<gRI, 512, S_SMEM>>>(ch, wah, wxh, p_r, ihh, ba, bx, Dn, Dn);
    scan_p1_k<<<(Bsz * NCH * Dn) / 128, 128>>>(p_r, ihh, ch, p_ls8, sch, pah, p_sE, p_sP);
    scan_p2_k<<<(Bsz * Dn) / 256, 256>>>(p_sE, p_sP, h0, p_hs, out_h);
    cudaStreamWaitEvent(0, ev_b2, 0);         // join side (b2h ready)
    prod_k<<<(BTD/4 + 255)/256, 256>>>(b2h, sch, pah, p_hs, ph);
    gemm_mma<3,0><<<gD, 512, S_SMEM>>>(ph, woh, p_x1, nullptr, x_seq, Dn, Dn);
    rmsnorm_half_k<<<BT, 256>>>(p_x1, norm2_w, n2h);
    gemm_dual<<<gH, 512, D_SMEM>>>(n2h, wgh, wuh, acth, Hn, Dn);
    gemm_mma<3,0><<<gD, 512, S_SMEM>>>(acth, wo2h, out_x2, nullptr, p_x1, Dn, Hn);
}

// round 16
// speedup vs baseline: 1.2069x; 1.0249x over previous
#include <cuda_runtime.h>
#include <cuda_fp16.h>
#include <math.h>
#include <stdint.h>

// ---------------- problem dims ----------------
#define Bsz 16
#define Tn  1024
#define Dn  1024
#define Hn  4096
#define BT  (Bsz*Tn)              // 16384
#define HALF_M (BT/2)             // 8192
#define BTD (Bsz*Tn*Dn)           // 16777216
#define BTH (Bsz*Tn*Hn)           // 67108864
#define CONVK 4
#define NCH 4                     // scan chunks
#define CHL (Tn/NCH)              // 256

// ---------------- GEMM tile config ----------------
#define STAGES 4
#define S_A_BYTES 20480           // 256 rows x 80B
#define S_STAGE   30720
#define S_SMEM    (STAGES*S_STAGE)    // 122880
#define D_STAGE   30720
#define D_SMEM    (STAGES*D_STAGE)    // 122880

// ---------------- scratch (device globals) ----------------
__device__ __align__(128) float g_r[BTD];
__device__ __align__(128) float g_x1[BTD];
__device__ __align__(128) float g_ls8[Dn];
__device__ __align__(128) float g_sE[Bsz*NCH*Dn];
__device__ __align__(128) float g_sP[Bsz*NCH*Dn];
__device__ __align__(128) float g_hs[Bsz*NCH*Dn];

__device__ __align__(128) __half g_b1_h[BTD];
__device__ __align__(128) __half g_i_h[BTD];
__device__ __align__(128) __half g_norm_h[BTD];
__device__ __align__(128) __half g_conv_h[BTD];
__device__ __align__(128) __half g_scan_h[BTD];
__device__ __align__(128) __half g_pa_h[BTD];
__device__ __align__(128) __half g_b2_h[BTD];       // gelu(normed@W2^T)
__device__ __align__(128) __half g_prod_h[BTD];
__device__ __align__(128) __half g_n2_h[BTD];
__device__ __align__(128) __half g_act_h[BTH];

__device__ __align__(128) __half g_w1_h[Dn*Dn];
__device__ __align__(128) __half g_wa_h[Dn*Dn];
__device__ __align__(128) __half g_wx_h[Dn*Dn];
__device__ __align__(128) __half g_w2_h[Dn*Dn];
__device__ __align__(128) __half g_wo_h[Dn*Dn];
__device__ __align__(128) __half g_wg_h[(long)Hn*Dn];
__device__ __align__(128) __half g_wu_h[(long)Hn*Dn];
__device__ __align__(128) __half g_wout2_h[(long)Dn*Hn];

// ---------------- helpers ----------------
__device__ __forceinline__ uint32_t smem_u32(const void* p) {
    uint32_t a;
    asm("{ .reg .u64 t; cvta.to.shared.u64 t, %1; cvt.u32.u64 %0, t; }"
        : "=r"(a) : "l"(p));
    return a;
}
__device__ __forceinline__ float gelu_f(float x) {
    return 0.5f * x * (1.0f + erff(x * 0.70710678118654752440f));
}
__device__ __forceinline__ float sigm_f(float x) {
    return 1.0f / (1.0f + expf(-x));
}
__device__ __forceinline__ uint32_t pack2h(float a, float b) {
    __half2 t = __floats2half2_rn(a, b);
    return *reinterpret_cast<uint32_t*>(&t);
}
__device__ __forceinline__ void ldsm4(uint32_t addr, uint32_t r[4]) {
    asm volatile("ldmatrix.sync.aligned.m8n8.x4.shared.b16 {%0,%1,%2,%3}, [%4];"
                 : "=r"(r[0]), "=r"(r[1]), "=r"(r[2]), "=r"(r[3]) : "r"(addr));
}
__device__ __forceinline__ void mma16816(float c[4], const uint32_t a[4], const uint32_t b[2]) {
    asm volatile("mma.sync.aligned.m16n8k16.row.col.f32.f16.f16.f32 "
                 "{%0,%1,%2,%3}, {%4,%5,%6,%7}, {%8,%9}, {%0,%1,%2,%3};"
                 : "+f"(c[0]), "+f"(c[1]), "+f"(c[2]), "+f"(c[3])
                 : "r"(a[0]), "r"(a[1]), "r"(a[2]), "r"(a[3]), "r"(b[0]), "r"(b[1]));
}
__device__ __forceinline__ void cp16(uint32_t dst, const void* src) {
    asm volatile("cp.async.cg.shared.global [%0], [%1], 16;" :: "r"(dst), "l"(src));
}
#define CP_COMMIT() asm volatile("cp.async.commit_group;" ::: "memory")
#define CP_WAIT2()  asm volatile("cp.async.wait_group 2;" ::: "memory")

__device__ __forceinline__ void ld_ab_s(uint32_t base, int kk, int wm, int wn, int lane,
                                        uint32_t ah[4][4], uint32_t bh[4][2]) {
    const uint32_t koff = (kk * 16 + (lane >> 4) * 8) * 2;
    #pragma unroll
    for (int i = 0; i < 4; i++) {
        const uint32_t off = (uint32_t)(wm * 64 + i * 16 + (lane & 15)) * 80 + koff;
        ldsm4(base + off, ah[i]);
    }
    #pragma unroll
    for (int j = 0; j < 2; j++) {
        const uint32_t off = (uint32_t)(wn * 32 + j * 16 + (lane & 15)) * 80 + koff;
        uint32_t t[4];
        ldsm4(base + S_A_BYTES + off, t);
        bh[2*j][0] = t[0]; bh[2*j][1] = t[2];
        bh[2*j+1][0] = t[1]; bh[2*j+1][1] = t[3];
    }
}

// ================= GEMM 256x128, 512 threads =================
// EPI: 0=none 2=gelu 3=v+auxf ; HOUT: 1 -> fp16 out
template<int EPI, int HOUT>
__global__ void __launch_bounds__(512, 1)
gemm_mma(const __half* __restrict__ A, const __half* __restrict__ B,
         float* __restrict__ C, __half* __restrict__ Ch,
         const float* __restrict__ auxf, int rowOff, int N, int K)
{
    extern __shared__ __align__(128) char smem[];
    const uint32_t sb = smem_u32(smem);
    const int tid = threadIdx.x;
    const int lane = tid & 31, wid = tid >> 5;
    const int wm = wid & 3;
    const int wn = wid >> 2;
    const long rowA = (long)rowOff + (long)blockIdx.y * 256;
    const long rowB = (long)blockIdx.x * 128;
    const int nk = K >> 5;

    float acc[4][4][4];
    #pragma unroll
    for (int i = 0; i < 4; i++)
        #pragma unroll
        for (int n = 0; n < 4; n++)
            #pragma unroll
            for (int q = 0; q < 4; q++) acc[i][n][q] = 0.f;

    auto load_stage = [&](int s, int kt) {
        const uint32_t base = sb + s * S_STAGE;
        const int k0 = kt << 5;
        #pragma unroll
        for (int t = 0; t < 2; t++) {
            const int idx = tid + t * 512;
            const int r = idx >> 2, c = idx & 3;
            cp16(base + r * 80 + c * 16, A + (rowA + r) * (long)K + k0 + c * 8);
        }
        {
            const int r = tid >> 2, c = tid & 3;
            cp16(base + S_A_BYTES + r * 80 + c * 16, B + (rowB + r) * (long)K + k0 + c * 8);
        }
    };

    load_stage(0, 0); CP_COMMIT();
    load_stage(1, 1); CP_COMMIT();
    load_stage(2, 2); CP_COMMIT();

    for (int kt = 0; kt < nk; kt++) {
        CP_WAIT2();
        __syncthreads();
        if (kt + 3 < nk) load_stage((kt + 3) & 3, kt + 3);
        CP_COMMIT();

        const uint32_t base = sb + (kt & 3) * S_STAGE;
        #pragma unroll
        for (int kk = 0; kk < 2; kk++) {
            uint32_t ah[4][4], bh[4][2];
            ld_ab_s(base, kk, wm, wn, lane, ah, bh);
            #pragma unroll
            for (int i = 0; i < 4; i++)
                #pragma unroll
                for (int n = 0; n < 4; n++)
                    mma16816(acc[i][n], ah[i], bh[n]);
        }
    }

    const long r0 = rowA + wm * 64 + (lane >> 2);
    const long c0 = rowB + wn * 32 + (lane & 3) * 2;
    #pragma unroll
    for (int i = 0; i < 4; i++) {
        #pragma unroll
        for (int n = 0; n < 4; n++) {
            #pragma unroll
            for (int h = 0; h < 2; h++) {
                const long row = r0 + i * 16 + h * 8;
                const long col = c0 + n * 8;
                float v0 = acc[i][n][2*h + 0];
                float v1 = acc[i][n][2*h + 1];
                if (EPI == 2) {
                    v0 = gelu_f(v0); v1 = gelu_f(v1);
                } else if (EPI == 3) {
                    const float2 a2 = *(const float2*)(auxf + row * (long)N + col);
                    v0 += a2.x; v1 += a2.y;
                }
                if (HOUT) {
                    *(uint32_t*)(Ch + row * (long)N + col) = pack2h(v0, v1);
                } else {
                    float2 o; o.x = v0; o.y = v1;
                    *(float2*)(C + row * (long)N + col) = o;
                }
            }
        }
    }
}

// ================= merged r/i GEMM =================
__global__ void __launch_bounds__(512, 1)
gemm_ri(const __half* __restrict__ A, const __half* __restrict__ Wa,
        const __half* __restrict__ Wx, float* __restrict__ Rout,
        __half* __restrict__ Iout, const float* __restrict__ ba,
        const float* __restrict__ bx, int N, int K)
{
    extern __shared__ __align__(128) char smem[];
    const uint32_t sb = smem_u32(smem);
    const int tid = threadIdx.x;
    const int lane = tid & 31, wid = tid >> 5;
    const int wm = wid & 3;
    const int wn = wid >> 2;
    const long rowA = (long)blockIdx.y * 256;
    const long rowB = (long)blockIdx.x * 128;
    const int z = blockIdx.z;
    const __half* B = z ? Wx : Wa;
    const float* bias = z ? bx : ba;
    const int nk = K >> 5;

    float acc[4][4][4];
    #pragma unroll
    for (int i = 0; i < 4; i++)
        #pragma unroll
        for (int n = 0; n < 4; n++)
            #pragma unroll
            for (int q = 0; q < 4; q++) acc[i][n][q] = 0.f;

    auto load_stage = [&](int s, int kt) {
        const uint32_t base = sb + s * S_STAGE;
        const int k0 = kt << 5;
        #pragma unroll
        for (int t = 0; t < 2; t++) {
            const int idx = tid + t * 512;
            const int r = idx >> 2, c = idx & 3;
            cp16(base + r * 80 + c * 16, A + (rowA + r) * (long)K + k0 + c * 8);
        }
        {
            const int r = tid >> 2, c = tid & 3;
            cp16(base + S_A_BYTES + r * 80 + c * 16, B + (rowB + r) * (long)K + k0 + c * 8);
        }
    };

    load_stage(0, 0); CP_COMMIT();
    load_stage(1, 1); CP_COMMIT();
    load_stage(2, 2); CP_COMMIT();

    for (int kt = 0; kt < nk; kt++) {
        CP_WAIT2();
        __syncthreads();
        if (kt + 3 < nk) load_stage((kt + 3) & 3, kt + 3);
        CP_COMMIT();

        const uint32_t base = sb + (kt & 3) * S_STAGE;
        #pragma unroll
        for (int kk = 0; kk < 2; kk++) {
            uint32_t ah[4][4], bh[4][2];
            ld_ab_s(base, kk, wm, wn, lane, ah, bh);
            #pragma unroll
            for (int i = 0; i < 4; i++)
                #pragma unroll
                for (int n = 0; n < 4; n++)
                    mma16816(acc[i][n], ah[i], bh[n]);
        }
    }

    const long r0 = rowA + wm * 64 + (lane >> 2);
    const long c0 = rowB + wn * 32 + (lane & 3) * 2;
    #pragma unroll
    for (int i = 0; i < 4; i++) {
        #pragma unroll
        for (int n = 0; n < 4; n++) {
            #pragma unroll
            for (int h = 0; h < 2; h++) {
                const long row = r0 + i * 16 + h * 8;
                const long col = c0 + n * 8;
                const float v0 = sigm_f(acc[i][n][2*h + 0] + bias[col]);
                const float v1 = sigm_f(acc[i][n][2*h + 1] + bias[col + 1]);
                if (z) {
                    *(uint32_t*)(Iout + row * (long)N + col) = pack2h(v0, v1);
                } else {
                    float2 o; o.x = v0; o.y = v1;
                    *(float2*)(Rout + row * (long)N + col) = o;
                }
            }
        }
    }
}

// ============ Dual MLP GEMM 128x128, 512 threads ==========
__global__ void __launch_bounds__(512, 1)
gemm_dual(const __half* __restrict__ A, const __half* __restrict__ Bg,
          const __half* __restrict__ Bu, __half* __restrict__ Ch,
          int rowOff, int N, int K)
{
    extern __shared__ __align__(128) char smem[];
    const uint32_t sb = smem_u32(smem);
    const int tid = threadIdx.x;
    const int lane = tid & 31, wid = tid >> 5;
    const int wm = wid & 3;
    const int wn = wid >> 2;
    const long rowA = (long)rowOff + (long)blockIdx.y * 128;
    const long rowB = (long)blockIdx.x * 128;
    const int nk = K >> 5;

    float accg[2][4][4], accu[2][4][4];
    #pragma unroll
    for (int i = 0; i < 2; i++)
        #pragma unroll
        for (int n = 0; n < 4; n++)
            #pragma unroll
            for (int q = 0; q < 4; q++) { accg[i][n][q] = 0.f; accu[i][n][q] = 0.f; }

    auto load_stage = [&](int s, int kt) {
        const uint32_t base = sb + s * D_STAGE;
        const int k0 = kt << 5;
        const int r = tid >> 2, c = tid & 3;
        cp16(base + r * 80 + c * 16, A + (rowA + r) * (long)K + k0 + c * 8);
        cp16(base + 10240 + r * 80 + c * 16, Bg + (rowB + r) * (long)K + k0 + c * 8);
        cp16(base + 20480 + r * 80 + c * 16, Bu + (rowB + r) * (long)K + k0 + c * 8);
    };

    load_stage(0, 0); CP_COMMIT();
    load_stage(1, 1); CP_COMMIT();
    load_stage(2, 2); CP_COMMIT();

    for (int kt = 0; kt < nk; kt++) {
        CP_WAIT2();
        __syncthreads();
        if (kt + 3 < nk) load_stage((kt + 3) & 3, kt + 3);
        CP_COMMIT();

        const uint32_t base = sb + (kt & 3) * D_STAGE;
        #pragma unroll
        for (int kk = 0; kk < 2; kk++) {
            const uint32_t koff = (kk * 16 + (lane >> 4) * 8) * 2;
            uint32_t ah[2][4];
            #pragma unroll
            for (int i = 0; i < 2; i++) {
                const uint32_t off = (uint32_t)(wm * 32 + i * 16 + (lane & 15)) * 80 + koff;
                ldsm4(base + off, ah[i]);
            }
            uint32_t bg[4][2], bu[4][2];
            #pragma unroll
            for (int j = 0; j < 2; j++) {
                const uint32_t off = (uint32_t)(wn * 32 + j * 16 + (lane & 15)) * 80 + koff;
                uint32_t t[4], u[4];
                ldsm4(base + 10240 + off, t);
                ldsm4(base + 20480 + off, u);
                bg[2*j][0] = t[0]; bg[2*j][1] = t[2];
                bg[2*j+1][0] = t[1]; bg[2*j+1][1] = t[3];
                bu[2*j][0] = u[0]; bu[2*j][1] = u[2];
                bu[2*j+1][0] = u[1]; bu[2*j+1][1] = u[3];
            }
            #pragma unroll
            for (int i = 0; i < 2; i++)
                #pragma unroll
                for (int n = 0; n < 4; n++) {
                    mma16816(accg[i][n], ah[i], bg[n]);
                    mma16816(accu[i][n], ah[i], bu[n]);
                }
        }
    }

    const long r0 = rowA + wm * 32 + (lane >> 2);
    const long c0 = rowB + wn * 32 + (lane & 3) * 2;
    #pragma unroll
    for (int i = 0; i < 2; i++) {
        #pragma unroll
        for (int n = 0; n < 4; n++) {
            #pragma unroll
            for (int h = 0; h < 2; h++) {
                const long row = r0 + i * 16 + h * 8;
                const long col = c0 + n * 8;
                const float v0 = gelu_f(accg[i][n][2*h + 0]) * accu[i][n][2*h + 0];
                const float v1 = gelu_f(accg[i][n][2*h + 1]) * accu[i][n][2*h + 1];
                *(uint32_t*)(Ch + row * (long)N + col) = pack2h(v0, v1);
            }
        }
    }
}

// ================= elementwise kernels =================
#define W1M (Dn*Dn/4)
#define WHM ((long)Hn*Dn/4)

__global__ void wconv_w1_k(const float* __restrict__ W1, const float* __restrict__ ll,
                           __half* __restrict__ o1, float* __restrict__ ls8) {
    const long i = (long)blockIdx.x * 256 + threadIdx.x;
    if (i < W1M) {
        float4 v = *(const float4*)(W1 + i * 4);
        uint2 hv; hv.x = pack2h(v.x, v.y); hv.y = pack2h(v.z, v.w);
        *(uint2*)(o1 + i * 4) = hv;
    } else if (i < W1M + Dn / 4) {
        const long d = (i - W1M) * 4;
        #pragma unroll
        for (int j = 0; j < 4; j++)
            ls8[d + j] = -8.0f * log1pf(expf(-ll[d + j]));
    }
}

__global__ void wconv_rest_k(const float* __restrict__ Wa, const float* __restrict__ Wx,
                             const float* __restrict__ W2, const float* __restrict__ Wout,
                             const float* __restrict__ Wg, const float* __restrict__ Wu,
                             const float* __restrict__ Wo,
                             __half* __restrict__ oa, __half* __restrict__ ox,
                             __half* __restrict__ o2, __half* __restrict__ oo,
                             __half* __restrict__ og, __half* __restrict__ ou,
                             __half* __restrict__ owo)
{
    const long i = (long)blockIdx.x * 256 + threadIdx.x;
    const long T4 = 4L * W1M, T5 = T4 + WHM, T6 = T5 + WHM, T7 = T6 + WHM;
    const float* src; __half* dst; long off;
    if (i < T4) {
        const long s = i / W1M; off = i - s * W1M;
        const float* srcs[4] = {Wa, Wx, W2, Wout};
        __half* dsts[4] = {oa, ox, o2, oo};
        src = srcs[s]; dst = dsts[s];
    } else if (i < T5) { src = Wg;  dst = og;  off = i - T4; }
    else if (i < T6)   { src = Wu;  dst = ou;  off = i - T5; }
    else if (i < T7)   { src = Wo;  dst = owo; off = i - T6; }
    else return;
    float4 v = *(const float4*)(src + off * 4);
    uint2 hv; hv.x = pack2h(v.x, v.y); hv.y = pack2h(v.z, v.w);
    *(uint2*)(dst + off * 4) = hv;
}

__global__ void rmsnorm_half_k(const float* __restrict__ x, const float* __restrict__ w,
                               __half* __restrict__ out) {
    const long row = blockIdx.x;
    const float* xr = x + row * (long)Dn;
    const int t4 = threadIdx.x * 4;
    float4 v = *(const float4*)(xr + t4);
    float ss = v.x*v.x + v.y*v.y + v.z*v.z + v.w*v.w;
    #pragma unroll
    for (int o = 16; o > 0; o >>= 1) ss += __shfl_xor_sync(0xffffffffu, ss, o);
    __shared__ float warps[8];
    if ((threadIdx.x & 31) == 0) warps[threadIdx.x >> 5] = ss;
    __syncthreads();
    float tot = 0.f;
    #pragma unroll
    for (int i = 0; i < 8; i++) tot += warps[i];
    const float inv = rsqrtf(tot * (1.0f / Dn) + 1.1920929e-07f);
    float4 wv = *(const float4*)(w + t4);
    uint2 hv;
    hv.x = pack2h(v.x*inv*wv.x, v.y*inv*wv.y);
    hv.y = pack2h(v.z*inv*wv.z, v.w*inv*wv.w);
    *(uint2*)(out + row * (long)Dn + t4) = hv;
}

__global__ void __launch_bounds__(256)
conv_row_k(const __half* __restrict__ b1h, const float* __restrict__ cbuf,
           const float* __restrict__ cw, const float* __restrict__ cb,
           __half* __restrict__ oh, float* __restrict__ out_cb) {
    const int row = blockIdx.x;
    const int t = row & (Tn - 1);
    const int b = row >> 10;
    const int d4 = threadIdx.x * 4;
    const float4 w0 = *(const float4*)(cw + (d4 + 0) * CONVK);
    const float4 w1 = *(const float4*)(cw + (d4 + 1) * CONVK);
    const float4 w2 = *(const float4*)(cw + (d4 + 2) * CONVK);
    const float4 w3 = *(const float4*)(cw + (d4 + 3) * CONVK);
    const float4 bias = *(const float4*)(cb + d4);
    float acc0 = bias.x, acc1 = bias.y, acc2 = bias.z, acc3 = bias.w;
    float l0 = 0.f, l1 = 0.f, l2 = 0.f, l3 = 0.f;
    #pragma unroll
    for (int k = 0; k < CONVK; k++) {
        const int tt = t + k - (CONVK - 1);
        float s0, s1, s2, s3;
        if (tt >= 0) {
            const uint2 hv = *(const uint2*)(b1h + ((long)b * Tn + tt) * Dn + d4);
            const __half2 h0 = *(const __half2*)&hv.x;
            const __half2 h1 = *(const __half2*)&hv.y;
            s0 = __half2float(h0.x); s1 = __half2float(h0.y);
            s2 = __half2float(h1.x); s3 = __half2float(h1.y);
        } else {
            const float4 f = *(const float4*)(cbuf + ((long)b * (CONVK - 1) + (t + k)) * Dn + d4);
            s0 = f.x; s1 = f.y; s2 = f.z; s3 = f.w;
        }
        if (k == CONVK - 1) { l0 = s0; l1 = s1; l2 = s2; l3 = s3; }
        const float wk0 = (&w0.x)[k], wk1 = (&w1.x)[k], wk2 = (&w2.x)[k], wk3 = (&w3.x)[k];
        acc0 = fmaf(s0, wk0, acc0);
        acc1 = fmaf(s1, wk1, acc1);
        acc2 = fmaf(s2, wk2, acc2);
        acc3 = fmaf(s3, wk3, acc3);
    }
    uint2 hv; hv.x = pack2h(acc0, acc1); hv.y = pack2h(acc2, acc3);
    *(uint2*)(oh + (long)row * Dn + d4) = hv;
    if (t >= Tn - (CONVK - 1)) {
        float4 f; f.x = l0; f.y = l1; f.z = l2; f.w = l3;
        *(float4*)(out_cb + ((long)b * (CONVK - 1) + (t - (Tn - (CONVK - 1)))) * Dn + d4) = f;
    }
}

__global__ void scan_p1_k(const float* __restrict__ r, const __half* __restrict__ ih,
                          const __half* __restrict__ convh, const float* __restrict__ ls8,
                          __half* __restrict__ outh, __half* __restrict__ pah,
                          float* __restrict__ sE, float* __restrict__ sP) {
    const int idx = blockIdx.x * 128 + threadIdx.x;
    const int d = idx & (Dn - 1);
    const int c = (idx >> 10) & (NCH - 1);
    const int b = idx >> 12;
    const float l8 = ls8[d];
    const long base = ((long)b * Tn + c * CHL) * Dn + d;
    float h = 0.f, p = 1.f;
    float cr[4], ci[4], cc[4];
    #pragma unroll
    for (int j = 0; j < 4; j++) {
        const long o = base + (long)j * Dn;
        cr[j] = r[o]; ci[j] = __half2float(ih[o]); cc[j] = __half2float(convh[o]);
    }
    for (int t0 = 0; t0 < CHL; t0 += 4) {
        float nr[4], ni[4], nc[4];
        if (t0 + 4 < CHL) {
            #pragma unroll
            for (int j = 0; j < 4; j++) {
                const long o = base + (long)(t0 + 4 + j) * Dn;
                nr[j] = r[o]; ni[j] = __half2float(ih[o]); nc[j] = __half2float(convh[o]);
            }
        }
        #pragma unroll
        for (int j = 0; j < 4; j++) {
            const float a = expf(cr[j] * l8);
            const float gate = sqrtf(fmaxf((1.f - a) * (1.f + a), 1e-6f));
            h = fmaf(a, h, gate * ci[j] * cc[j]);
            p *= a;
            const long o = base + (long)(t0 + j) * Dn;
            outh[o] = __float2half_rn(h);
            pah[o] = __float2half_rn(p);
        }
        #pragma unroll
        for (int j = 0; j < 4; j++) { cr[j] = nr[j]; ci[j] = ni[j]; cc[j] = nc[j]; }
    }
    sE[idx] = h;
    sP[idx] = p;
}

__global__ void scan_p2_k(const float* __restrict__ sE, const float* __restrict__ sP,
                          const float* __restrict__ h0, float* __restrict__ hs,
                          float* __restrict__ newh) {
    const int idx = blockIdx.x * 256 + threadIdx.x;
    const int d = idx & (Dn - 1);
    const int b = idx >> 10;
    float h = h0[idx];
    #pragma unroll
    for (int c = 0; c < NCH; c++) {
        const long o = (long)(b * NCH + c) * Dn + d;
        hs[o] = h;
        h = sE[o] + sP[o] * h;
    }
    newh[idx] = h;
}

// prod = b2 * (scan_local + pa*hs)   (fp16 in/out, fp32 math), element offset e0
__global__ void prod_k(const __half* __restrict__ b2, const __half* __restrict__ sc,
                       const __half* __restrict__ pa, const float* __restrict__ hs,
                       __half* __restrict__ out, long e0, long n4) {
    const long i = (long)blockIdx.x * 256 + threadIdx.x;
    if (i >= n4) return;
    const long e = e0 + i * 4;
    const int row = (int)(e >> 10);
    const int d0 = (int)(e & (Dn - 1));
    const int b = row >> 10, t = row & (Tn - 1), cch = t >> 8;
    const float4 h4 = *(const float4*)(hs + ((long)(b * NCH + cch)) * Dn + d0);
    const uint2 b2v = *(const uint2*)(b2 + e);
    const uint2 scv = *(const uint2*)(sc + e);
    const uint2 pav = *(const uint2*)(pa + e);
    const __half2 b2a = *(const __half2*)&b2v.x, b2b = *(const __half2*)&b2v.y;
    const __half2 sca = *(const __half2*)&scv.x, scb = *(const __half2*)&scv.y;
    const __half2 paa = *(const __half2*)&pav.x, pab = *(const __half2*)&pav.y;
    const float v0 = __half2float(b2a.x) * (__half2float(sca.x) + __half2float(paa.x) * h4.x);
    const float v1 = __half2float(b2a.y) * (__half2float(sca.y) + __half2float(paa.y) * h4.y);
    const float v2 = __half2float(b2b.x) * (__half2float(scb.x) + __half2float(pab.x) * h4.z);
    const float v3 = __half2float(b2b.y) * (__half2float(scb.y) + __half2float(pab.y) * h4.w);
    uint2 o; o.x = pack2h(v0, v1); o.y = pack2h(v2, v3);
    *(uint2*)(out + e) = o;
}

// ================= host side =================
extern "C" void kernel_launch(void* const* d_in, const int* in_sizes, int n_in,
                              void* d_out, int out_size) {
    const float* x_seq   = (const float*)d_in[0];
    const float* h0      = (const float*)d_in[1];
    const float* convbuf = (const float*)d_in[2];
    const float* norm1_w = (const float*)d_in[3];
    const float* W1      = (const float*)d_in[4];
    const float* conv_w  = (const float*)d_in[5];
    const float* conv_b  = (const float*)d_in[6];
    const float* Wa      = (const float*)d_in[7];
    const float* ba      = (const float*)d_in[8];
    const float* Wx      = (const float*)d_in[9];
    const float* bx      = (const float*)d_in[10];
    const float* log_lam = (const float*)d_in[11];
    const float* W2      = (const float*)d_in[12];
    const float* Wout    = (const float*)d_in[13];
    const float* norm2_w = (const float*)d_in[14];
    const float* Wg      = (const float*)d_in[15];
    const float* Wu      = (const float*)d_in[16];
    const float* Wo      = (const float*)d_in[17];

    float* out_x2 = (float*)d_out;
    float* out_h  = out_x2 + (long)BTD;
    float* out_cb = out_h + (long)Bsz * Dn;

    float *p_r, *p_x1, *p_ls8, *p_sE, *p_sP, *p_hs;
    cudaGetSymbolAddress((void**)&p_r, g_r);
    cudaGetSymbolAddress((void**)&p_x1, g_x1);
    cudaGetSymbolAddress((void**)&p_ls8, g_ls8);
    cudaGetSymbolAddress((void**)&p_sE, g_sE);
    cudaGetSymbolAddress((void**)&p_sP, g_sP);
    cudaGetSymbolAddress((void**)&p_hs, g_hs);

    __half *b1h, *ihh, *nh, *ch, *sch, *pah, *b2h, *ph, *n2h, *acth;
    cudaGetSymbolAddress((void**)&b1h, g_b1_h);
    cudaGetSymbolAddress((void**)&ihh, g_i_h);
    cudaGetSymbolAddress((void**)&nh, g_norm_h);
    cudaGetSymbolAddress((void**)&ch, g_conv_h);
    cudaGetSymbolAddress((void**)&sch, g_scan_h);
    cudaGetSymbolAddress((void**)&pah, g_pa_h);
    cudaGetSymbolAddress((void**)&b2h, g_b2_h);
    cudaGetSymbolAddress((void**)&ph, g_prod_h);
    cudaGetSymbolAddress((void**)&n2h, g_n2_h);
    cudaGetSymbolAddress((void**)&acth, g_act_h);

    __half *w1h, *wah, *wxh, *w2h, *woh, *wgh, *wuh, *wo2h;
    cudaGetSymbolAddress((void**)&w1h, g_w1_h);
    cudaGetSymbolAddress((void**)&wah, g_wa_h);
    cudaGetSymbolAddress((void**)&wxh, g_wx_h);
    cudaGetSymbolAddress((void**)&w2h, g_w2_h);
    cudaGetSymbolAddress((void**)&woh, g_wo_h);
    cudaGetSymbolAddress((void**)&wgh, g_wg_h);
    cudaGetSymbolAddress((void**)&wuh, g_wu_h);
    cudaGetSymbolAddress((void**)&wo2h, g_wout2_h);

    cudaFuncSetAttribute(gemm_mma<0,1>, cudaFuncAttributeMaxDynamicSharedMemorySize, S_SMEM);
    cudaFuncSetAttribute(gemm_mma<2,1>, cudaFuncAttributeMaxDynamicSharedMemorySize, S_SMEM);
    cudaFuncSetAttribute(gemm_mma<3,0>, cudaFuncAttributeMaxDynamicSharedMemorySize, S_SMEM);
    cudaFuncSetAttribute(gemm_ri,       cudaFuncAttributeMaxDynamicSharedMemorySize, S_SMEM);
    cudaFuncSetAttribute(gemm_dual,     cudaFuncAttributeMaxDynamicSharedMemorySize, D_SMEM);

    // static side stream + events (created once, on the uncaptured correctness call)
    static cudaStream_t s_side = nullptr;
    static cudaEvent_t ev_root, ev_nh, ev_wc, ev_b2, ev_scan, ev_t1;
    if (!s_side) {
        cudaStreamCreateWithFlags(&s_side, cudaStreamNonBlocking);
        cudaEventCreateWithFlags(&ev_root, cudaEventDisableTiming);
        cudaEventCreateWithFlags(&ev_nh,   cudaEventDisableTiming);
        cudaEventCreateWithFlags(&ev_wc,   cudaEventDisableTiming);
        cudaEventCreateWithFlags(&ev_b2,   cudaEventDisableTiming);
        cudaEventCreateWithFlags(&ev_scan, cudaEventDisableTiming);
        cudaEventCreateWithFlags(&ev_t1,   cudaEventDisableTiming);
    }

    const dim3 gD(Dn / 128, BT / 256);        // full (8, 64)
    const dim3 gDH(Dn / 128, HALF_M / 256);   // half (8, 32)
    const dim3 gRI(Dn / 128, BT / 256, 2);
    const dim3 gHH(Hn / 128, HALF_M / 128);   // dual half (32, 64)

    // ---- main: W1 conversion + rmsnorm1 ----
    wconv_w1_k<<<(W1M + Dn/4 + 255)/256, 256>>>(W1, log_lam, w1h, p_ls8);
    cudaEventRecord(ev_root, 0);
    rmsnorm_half_k<<<BT, 256>>>(x_seq, norm1_w, nh);
    cudaEventRecord(ev_nh, 0);

    // ---- side: remaining weight conversions, then W2 GEMM -> b2h ----
    cudaStreamWaitEvent(s_side, ev_root, 0);
    const long WR = 4L*W1M + 3L*WHM;
    wconv_rest_k<<<(int)((WR + 255)/256), 256, 0, s_side>>>(
        Wa, Wx, W2, Wout, Wg, Wu, Wo, wah, wxh, w2h, woh, wgh, wuh, wo2h);
    cudaEventRecord(ev_wc, s_side);
    cudaStreamWaitEvent(s_side, ev_nh, 0);
    gemm_mma<2,1><<<gD, 512, S_SMEM, s_side>>>(nh, w2h, nullptr, b2h, nullptr, 0, Dn, Dn);
    cudaEventRecord(ev_b2, s_side);

    // ---- main chain up to scan ----
    gemm_mma<0,1><<<gD, 512, S_SMEM>>>(nh, w1h, nullptr, b1h, nullptr, 0, Dn, Dn);
    conv_row_k<<<BT, 256>>>(b1h, convbuf, conv_w, conv_b, ch, out_cb);
    cudaStreamWaitEvent(0, ev_wc, 0);
    gemm_ri<<<gRI, 512, S_SMEM>>>(ch, wah, wxh, p_r, ihh, ba, bx, Dn, Dn);
    scan_p1_k<<<(Bsz * NCH * Dn) / 128, 128>>>(p_r, ihh, ch, p_ls8, sch, pah, p_sE, p_sP);
    scan_p2_k<<<(Bsz * Dn) / 256, 256>>>(p_sE, p_sP, h0, p_hs, out_h);
    cudaEventRecord(ev_scan, 0);

    // ---- tail pipeline, two M-halves on two streams ----
    const long n4h = (long)BTD / 8;             // fp16 quads per half
    const int pgrid = (int)((n4h + 255) / 256);

    // H0 on main (needs b2h from side)
    cudaStreamWaitEvent(0, ev_b2, 0);
    prod_k<<<pgrid, 256>>>(b2h, sch, pah, p_hs, ph, 0L, n4h);
    gemm_mma<3,0><<<gDH, 512, S_SMEM>>>(ph, woh, p_x1, nullptr, x_seq, 0, Dn, Dn);
    rmsnorm_half_k<<<HALF_M, 256>>>(p_x1, norm2_w, n2h);
    gemm_dual<<<gHH, 512, D_SMEM>>>(n2h, wgh, wuh, acth, 0, Hn, Dn);
    gemm_mma<3,0><<<gDH, 512, S_SMEM>>>(acth, wo2h, out_x2, nullptr, p_x1, 0, Dn, Hn);

    // H1 on side (b2h in-order on side; needs scan results from main)
    cudaStreamWaitEvent(s_side, ev_scan, 0);
    prod_k<<<pgrid, 256, 0, s_side>>>(b2h, sch, pah, p_hs, ph, (long)BTD / 2, n4h);
    gemm_mma<3,0><<<gDH, 512, S_SMEM, s_side>>>(ph, woh, p_x1, nullptr, x_seq, HALF_M, Dn, Dn);
    rmsnorm_half_k<<<HALF_M, 256, 0, s_side>>>(p_x1 + (long)HALF_M * Dn, norm2_w,
                                               n2h + (long)HALF_M * Dn);
    gemm_dual<<<gHH, 512, D_SMEM, s_side>>>(n2h, wgh, wuh, acth, HALF_M, Hn, Dn);
    gemm_mma<3,0><<<gDH, 512, S_SMEM, s_side>>>(acth, wo2h, out_x2, nullptr, p_x1,
                                                HALF_M, Dn, Hn);
    cudaEventRecord(ev_t1, s_side);
    cudaStreamWaitEvent(0, ev_t1, 0);   // join side into main before capture ends
}